// round 11
// baseline (speedup 1.0000x reference)
#include <cuda_runtime.h>
#include <cuda_bf16.h>
#include <cstdint>

#define BDIM 4
#define SDIM 2048
#define IDIM 1024
#define DDIM 1024
#define NTOK (BDIM * SDIM)   // 8192

// ---------------------------------------------------------------------------
// Device scratch (allocation-free rule)
// ---------------------------------------------------------------------------
__device__ __align__(128) __nv_bfloat16 g_qh[(size_t)NTOK * IDIM];
__device__ __align__(128) __nv_bfloat16 g_ql[(size_t)NTOK * IDIM];
__device__ __align__(128) __nv_bfloat16 g_kh[(size_t)NTOK * IDIM];
__device__ __align__(128) __nv_bfloat16 g_kl[(size_t)NTOK * IDIM];
__device__ __align__(128) __nv_bfloat16 g_vh[(size_t)NTOK * IDIM];
__device__ __align__(128) __nv_bfloat16 g_vl[(size_t)NTOK * IDIM];
__device__ __align__(128) __nv_bfloat16 g_wqt_h[(size_t)DDIM * IDIM];
__device__ __align__(128) __nv_bfloat16 g_wqt_l[(size_t)DDIM * IDIM];
__device__ __align__(128) __nv_bfloat16 g_wkt_h[(size_t)DDIM * IDIM];
__device__ __align__(128) __nv_bfloat16 g_wkt_l[(size_t)DDIM * IDIM];
__device__ __align__(128) __nv_bfloat16 g_wvt_h[(size_t)DDIM * IDIM];
__device__ __align__(128) __nv_bfloat16 g_wvt_l[(size_t)DDIM * IDIM];
__device__ __align__(128) __nv_bfloat16 g_qph[(size_t)NTOK * DDIM];
__device__ __align__(128) __nv_bfloat16 g_qpl[(size_t)NTOK * DDIM];
__device__ __align__(128) __nv_bfloat16 g_kph[(size_t)NTOK * DDIM];
__device__ __align__(128) __nv_bfloat16 g_kpl[(size_t)NTOK * DDIM];
__device__ __align__(128) __nv_bfloat16 g_vpth[(size_t)DDIM * NTOK];  // [D, tokens]
__device__ __align__(128) __nv_bfloat16 g_vptl[(size_t)DDIM * NTOK];
__device__ __align__(128) float g_logits[(size_t)BDIM * SDIM * SDIM];
__device__ __align__(128) __nv_bfloat16 g_ah[(size_t)BDIM * SDIM * SDIM];
__device__ __align__(128) __nv_bfloat16 g_al[(size_t)BDIM * SDIM * SDIM];

// ---------------------------------------------------------------------------
// PTX helpers
// ---------------------------------------------------------------------------
__device__ __forceinline__ uint32_t smem_u32(const void* p) {
    uint32_t a;
    asm("{ .reg .u64 t; cvta.to.shared.u64 t, %1; cvt.u32.u64 %0, t; }"
        : "=r"(a) : "l"(p));
    return a;
}

__device__ __forceinline__ void cp16(uint32_t d, const void* g) {
    asm volatile("cp.async.cg.shared.global [%0], [%1], 16;" :: "r"(d), "l"(g) : "memory");
}
#define CP_COMMIT() asm volatile("cp.async.commit_group;" ::: "memory")
#define CP_WAIT1()  asm volatile("cp.async.wait_group 1;" ::: "memory")

__device__ __forceinline__ void ldsm4(uint32_t* r, uint32_t addr) {
    asm volatile("ldmatrix.sync.aligned.m8n8.x4.shared.b16 {%0,%1,%2,%3}, [%4];"
        : "=r"(r[0]), "=r"(r[1]), "=r"(r[2]), "=r"(r[3]) : "r"(addr));
}

// mma.sync m16n8k16 bf16 -> fp32 accumulate
__device__ __forceinline__ void mma_bf16(float* d, const uint32_t* a,
                                         uint32_t b0, uint32_t b1) {
    asm volatile(
        "mma.sync.aligned.m16n8k16.row.col.f32.bf16.bf16.f32 "
        "{%0,%1,%2,%3}, {%4,%5,%6,%7}, {%8,%9}, {%0,%1,%2,%3};"
        : "+f"(d[0]), "+f"(d[1]), "+f"(d[2]), "+f"(d[3])
        : "r"(a[0]), "r"(a[1]), "r"(a[2]), "r"(a[3]), "r"(b0), "r"(b1));
}

// CTA tile 64(M) x 128(N), K-tile 32.
// SMEM stage: Ah/Al 64 rows, Bh/Bl 128 rows, 80B pitch.
#define KT 32
#define ROWB 80
#define A_BYTES (64 * ROWB)             // 5120
#define B_BYTES (128 * ROWB)            // 10240
#define OFF_AH 0
#define OFF_AL A_BYTES
#define OFF_BH (2 * A_BYTES)
#define OFF_BL (2 * A_BYTES + B_BYTES)
#define STG_BYTES (2 * A_BYTES + 2 * B_BYTES)   // 30720
#define NSTAGE 2
#define SMEM_TOTAL (NSTAGE * STG_BYTES)         // 61440 -> 2 CTAs/SM (reg-bound)

#define NTHREADS 256

// transpose staging pitch (elements): 64 tokens + 8 pad
#define TPITCH 72

// ROWS rows x 32 cols bf16 loader (ROWS*4 16B chunks, 256 threads)
template <int ROWS>
__device__ __forceinline__ void load_arr(const __nv_bfloat16* __restrict__ G,
                                         int ldg, int kt, uint32_t dst, int tid) {
#pragma unroll
    for (int i = 0; i < ROWS / 64; i++) {
        int idx = tid + i * NTHREADS;
        int row = idx >> 2;
        int c = idx & 3;
        cp16(dst + row * ROWB + c * 16, (const void*)(G + (size_t)row * ldg + kt + c * 8));
    }
}

// ---------------------------------------------------------------------------
// Shared mainloop: D[64,128] += A[64,K] * B[128,K]^T (NT, hi/lo 3-product).
// 8 warps (2 m x 4 n), warp tile 32x32; 2-stage ping-pong, 2 CTAs/SM.
// ---------------------------------------------------------------------------
__device__ __forceinline__ void gemm_mainloop(
    const __nv_bfloat16* __restrict__ Ahb, const __nv_bfloat16* __restrict__ Alb,
    const __nv_bfloat16* __restrict__ Bhb, const __nv_bfloat16* __restrict__ Blb,
    int K, int lda, int ldb,
    uint32_t sbase, int tid, int wm, int wn, int lane,
    float d[2][4][4])
{
    const int w8 = lane & 7, j8 = lane >> 3;
    int aoff[2], boff[2];
#pragma unroll
    for (int mf = 0; mf < 2; mf++)
        aoff[mf] = (wm * 32 + mf * 16 + w8 + 8 * (j8 & 1)) * ROWB + (j8 >> 1) * 16;
#pragma unroll
    for (int g = 0; g < 2; g++)
        boff[g] = (wn * 32 + g * 16 + w8 + 8 * (j8 >> 1)) * ROWB + (j8 & 1) * 16;

    const int T = K / KT;

    // preload stages 0,1
#pragma unroll
    for (int p = 0; p < 2; p++) {
        uint32_t b = sbase + p * STG_BYTES;
        load_arr<64>(Ahb, lda, p * KT, b + OFF_AH, tid);
        load_arr<64>(Alb, lda, p * KT, b + OFF_AL, tid);
        load_arr<128>(Bhb, ldb, p * KT, b + OFF_BH, tid);
        load_arr<128>(Blb, ldb, p * KT, b + OFF_BL, tid);
        CP_COMMIT();
    }

    for (int t = 0; t < T; t++) {
        CP_WAIT1();            // stage t landed
        __syncthreads();

        const uint32_t sb = sbase + (t & 1) * STG_BYTES;
        const uint32_t sAh = sb + OFF_AH;
        const uint32_t sAl = sb + OFF_AL;
        const uint32_t sBh = sb + OFF_BH;
        const uint32_t sBl = sb + OFF_BL;

#pragma unroll
        for (int ks = 0; ks < 2; ks++) {
            const int kb = ks * 32;
            uint32_t ah[2][4], al[2][4];
            ldsm4(ah[0], sAh + aoff[0] + kb);
            ldsm4(ah[1], sAh + aoff[1] + kb);
            ldsm4(al[0], sAl + aoff[0] + kb);
            ldsm4(al[1], sAl + aoff[1] + kb);
#pragma unroll
            for (int g = 0; g < 2; g++) {
                uint32_t bh[4], bl[4];
                ldsm4(bh, sBh + boff[g] + kb);
                ldsm4(bl, sBl + boff[g] + kb);
#pragma unroll
                for (int sub = 0; sub < 2; sub++) {
                    const int nf = g * 2 + sub;
                    const uint32_t bh0 = bh[sub * 2], bh1 = bh[sub * 2 + 1];
                    const uint32_t bl0 = bl[sub * 2], bl1 = bl[sub * 2 + 1];
                    mma_bf16(d[0][nf], ah[0], bh0, bh1);
                    mma_bf16(d[1][nf], ah[1], bh0, bh1);
                    mma_bf16(d[0][nf], ah[0], bl0, bl1);
                    mma_bf16(d[1][nf], ah[1], bl0, bl1);
                    mma_bf16(d[0][nf], al[0], bh0, bh1);
                    mma_bf16(d[1][nf], al[1], bh0, bh1);
                }
            }
        }

        __syncthreads();       // all warps finished reading slot t&1
        if (t + 2 < T) {
            const int kt = (t + 2) * KT;
            load_arr<64>(Ahb, lda, kt, sb + OFF_AH, tid);
            load_arr<64>(Alb, lda, kt, sb + OFF_AL, tid);
            load_arr<128>(Bhb, ldb, kt, sb + OFF_BH, tid);
            load_arr<128>(Blb, ldb, kt, sb + OFF_BL, tid);
        }
        CP_COMMIT();           // always commit to keep group count fixed
    }
}

// ---------------------------------------------------------------------------
// Merged QKV projection GEMM. blockIdx.z in {0,1,2} selects {Q,K,V}.
// z<2: out = bias+hi/lo split, row-major. z=2: transposed [DDIM, NTOK] via
// smem-staged transpose (coalesced stores).
// ---------------------------------------------------------------------------
__global__ void __launch_bounds__(NTHREADS, 2)
proj_gemm(const __nv_bfloat16* __restrict__ qh, const __nv_bfloat16* __restrict__ ql,
          const __nv_bfloat16* __restrict__ kh, const __nv_bfloat16* __restrict__ kl,
          const __nv_bfloat16* __restrict__ vh, const __nv_bfloat16* __restrict__ vl,
          const __nv_bfloat16* __restrict__ wqh, const __nv_bfloat16* __restrict__ wql,
          const __nv_bfloat16* __restrict__ wkh, const __nv_bfloat16* __restrict__ wkl,
          const __nv_bfloat16* __restrict__ wvh, const __nv_bfloat16* __restrict__ wvl,
          const float* __restrict__ bq, const float* __restrict__ bk,
          const float* __restrict__ bv,
          __nv_bfloat16* __restrict__ qph, __nv_bfloat16* __restrict__ qpl,
          __nv_bfloat16* __restrict__ kph, __nv_bfloat16* __restrict__ kpl,
          __nv_bfloat16* __restrict__ vpth, __nv_bfloat16* __restrict__ vptl)
{
    extern __shared__ char smem[];
    const uint32_t sbase = smem_u32(smem);
    const int tid = threadIdx.x;
    const int wid = tid >> 5, lane = tid & 31;
    const int wm = wid & 1, wn = wid >> 1;
    const int mBase = blockIdx.y * 64;
    const int nBase = blockIdx.x * 128;
    const int z = blockIdx.z;

    const __nv_bfloat16* Ah = (z == 0) ? qh : (z == 1) ? kh : vh;
    const __nv_bfloat16* Al = (z == 0) ? ql : (z == 1) ? kl : vl;
    const __nv_bfloat16* Bh = (z == 0) ? wqh : (z == 1) ? wkh : wvh;
    const __nv_bfloat16* Bl = (z == 0) ? wql : (z == 1) ? wkl : wvl;
    const float* bias = (z == 0) ? bq : (z == 1) ? bk : bv;
    __nv_bfloat16* Ch = (z == 0) ? qph : (z == 1) ? kph : vpth;
    __nv_bfloat16* Cl = (z == 0) ? qpl : (z == 1) ? kpl : vptl;

    float d[2][4][4];
#pragma unroll
    for (int i = 0; i < 2; i++)
#pragma unroll
        for (int j = 0; j < 4; j++)
#pragma unroll
            for (int e = 0; e < 4; e++) d[i][j][e] = 0.f;

    gemm_mainloop(Ah + (size_t)mBase * IDIM, Al + (size_t)mBase * IDIM,
                  Bh + (size_t)nBase * IDIM, Bl + (size_t)nBase * IDIM,
                  IDIM, IDIM, IDIM, sbase, tid, wm, wn, lane, d);

    if (z != 2) {
        const int row0 = mBase + wm * 32 + (lane >> 2);
        const int col0 = nBase + wn * 32 + (lane & 3) * 2;
#pragma unroll
        for (int mf = 0; mf < 2; mf++) {
#pragma unroll
            for (int nf = 0; nf < 4; nf++) {
                const int r = row0 + mf * 16;
                const int c = col0 + nf * 8;
                const float* dd = d[mf][nf];
                const float b0v = bias[c], b1v = bias[c + 1];
#pragma unroll
                for (int h = 0; h < 2; h++) {
                    float v0 = dd[h * 2 + 0] + b0v;
                    float v1 = dd[h * 2 + 1] + b1v;
                    __nv_bfloat16 h0 = __float2bfloat16(v0);
                    __nv_bfloat16 h1 = __float2bfloat16(v1);
                    __nv_bfloat16 l0 = __float2bfloat16(v0 - __bfloat162float(h0));
                    __nv_bfloat16 l1 = __float2bfloat16(v1 - __bfloat162float(h1));
                    size_t o = (size_t)(r + h * 8) * DDIM + c;
                    *(__nv_bfloat162*)(Ch + o) = __nv_bfloat162(h0, h1);
                    *(__nv_bfloat162*)(Cl + o) = __nv_bfloat162(l0, l1);
                }
            }
        }
    } else {
        // smem-staged transpose: [col][token] layout, then coalesced writes
        __syncthreads();   // mainloop smem fully consumed
        __nv_bfloat16* sh = (__nv_bfloat16*)smem;
        __nv_bfloat16* sl = sh + 128 * TPITCH;
        const int lr0 = wm * 32 + (lane >> 2);
        const int lc0 = wn * 32 + (lane & 3) * 2;
#pragma unroll
        for (int mf = 0; mf < 2; mf++) {
#pragma unroll
            for (int nf = 0; nf < 4; nf++) {
                const float* dd = d[mf][nf];
                const int c = lc0 + nf * 8;
                const float b0v = bias[nBase + c], b1v = bias[nBase + c + 1];
#pragma unroll
                for (int h = 0; h < 2; h++) {
                    const int r = lr0 + mf * 16 + h * 8;
                    float v0 = dd[h * 2 + 0] + b0v;
                    float v1 = dd[h * 2 + 1] + b1v;
                    __nv_bfloat16 h0 = __float2bfloat16(v0);
                    __nv_bfloat16 h1 = __float2bfloat16(v1);
                    sh[c * TPITCH + r] = h0;
                    sh[(c + 1) * TPITCH + r] = h1;
                    sl[c * TPITCH + r] = __float2bfloat16(v0 - __bfloat162float(h0));
                    sl[(c + 1) * TPITCH + r] = __float2bfloat16(v1 - __bfloat162float(h1));
                }
            }
        }
        __syncthreads();
        // 8 warps x 16 cols: lane covers 2 tokens (4B) -> 128B/warp/col coalesced
#pragma unroll
        for (int i = 0; i < 16; i++) {
            const int c = wid * 16 + i;
            uint32_t vh1 = *(const uint32_t*)(sh + c * TPITCH + lane * 2);
            uint32_t vl1 = *(const uint32_t*)(sl + c * TPITCH + lane * 2);
            size_t o = (size_t)(nBase + c) * NTOK + mBase + lane * 2;
            *(uint32_t*)(vpth + o) = vh1;
            *(uint32_t*)(vptl + o) = vl1;
        }
    }
}

// ---------------------------------------------------------------------------
// Generic NT GEMM with fp32 output (logits & AV), batched via strides.
// ---------------------------------------------------------------------------
__global__ void __launch_bounds__(NTHREADS, 2)
hmma_gemm_f32(const __nv_bfloat16* __restrict__ Ah, const __nv_bfloat16* __restrict__ Al,
              const __nv_bfloat16* __restrict__ Bh, const __nv_bfloat16* __restrict__ Bl,
              float* __restrict__ Cf,
              int K, int lda, int ldb, int ldc,
              size_t sA, size_t sB, size_t sC)
{
    extern __shared__ char smem[];
    const uint32_t sbase = smem_u32(smem);
    const int tid = threadIdx.x;
    const int wid = tid >> 5, lane = tid & 31;
    const int wm = wid & 1, wn = wid >> 1;
    const int mBase = blockIdx.y * 64;
    const int nBase = blockIdx.x * 128;
    const int z = blockIdx.z;

    float d[2][4][4];
#pragma unroll
    for (int i = 0; i < 2; i++)
#pragma unroll
        for (int j = 0; j < 4; j++)
#pragma unroll
            for (int e = 0; e < 4; e++) d[i][j][e] = 0.f;

    gemm_mainloop(Ah + z * sA + (size_t)mBase * lda, Al + z * sA + (size_t)mBase * lda,
                  Bh + z * sB + (size_t)nBase * ldb, Bl + z * sB + (size_t)nBase * ldb,
                  K, lda, ldb, sbase, tid, wm, wn, lane, d);

    const int row0 = mBase + wm * 32 + (lane >> 2);
    const int col0 = nBase + wn * 32 + (lane & 3) * 2;
    float* Cp = Cf + z * sC;

#pragma unroll
    for (int mf = 0; mf < 2; mf++) {
#pragma unroll
        for (int nf = 0; nf < 4; nf++) {
            const int r = row0 + mf * 16;
            const int c = col0 + nf * 8;
            const float* dd = d[mf][nf];
            *(float2*)(Cp + (size_t)r * ldc + c) = make_float2(dd[0], dd[1]);
            *(float2*)(Cp + (size_t)(r + 8) * ldc + c) = make_float2(dd[2], dd[3]);
        }
    }
}

// ---------------------------------------------------------------------------
// fp32 -> (hi, lo) bf16 split; grid.y selects among 3 tensors
// ---------------------------------------------------------------------------
__global__ void __launch_bounds__(256)
split_f32_3(const float4* __restrict__ x0, __nv_bfloat16* __restrict__ h0p, __nv_bfloat16* __restrict__ l0p,
            const float4* __restrict__ x1, __nv_bfloat16* __restrict__ h1p, __nv_bfloat16* __restrict__ l1p,
            const float4* __restrict__ x2, __nv_bfloat16* __restrict__ h2p, __nv_bfloat16* __restrict__ l2p,
            int n4)
{
    int i = blockIdx.x * 256 + threadIdx.x;
    if (i >= n4) return;
    int s = blockIdx.y;
    const float4* x = (s == 0) ? x0 : (s == 1) ? x1 : x2;
    __nv_bfloat16* hi = (s == 0) ? h0p : (s == 1) ? h1p : h2p;
    __nv_bfloat16* lo = (s == 0) ? l0p : (s == 1) ? l1p : l2p;

    float4 v = x[i];
    float vv[4] = {v.x, v.y, v.z, v.w};
    __nv_bfloat162 h2[2], l2[2];
#pragma unroll
    for (int j = 0; j < 4; j++) {
        __nv_bfloat16 h = __float2bfloat16(vv[j]);
        __nv_bfloat16 l = __float2bfloat16(vv[j] - __bfloat162float(h));
        ((__nv_bfloat16*)h2)[j] = h;
        ((__nv_bfloat16*)l2)[j] = l;
    }
    ((__nv_bfloat162*)hi)[i * 2]     = h2[0];
    ((__nv_bfloat162*)hi)[i * 2 + 1] = h2[1];
    ((__nv_bfloat162*)lo)[i * 2]     = l2[0];
    ((__nv_bfloat162*)lo)[i * 2 + 1] = l2[1];
}

// Merged W[K,N] fp32 -> WT hi/lo [N,K] bf16 for all 3 weights (grid.z)
__global__ void __launch_bounds__(256)
transpose_split_3(const float* __restrict__ W0, __nv_bfloat16* __restrict__ T0h, __nv_bfloat16* __restrict__ T0l,
                  const float* __restrict__ W1, __nv_bfloat16* __restrict__ T1h, __nv_bfloat16* __restrict__ T1l,
                  const float* __restrict__ W2, __nv_bfloat16* __restrict__ T2h, __nv_bfloat16* __restrict__ T2l,
                  int rows, int cols)
{
    __shared__ float tile[32][33];
    int s = blockIdx.z;
    const float* W = (s == 0) ? W0 : (s == 1) ? W1 : W2;
    __nv_bfloat16* Th = (s == 0) ? T0h : (s == 1) ? T1h : T2h;
    __nv_bfloat16* Tl = (s == 0) ? T0l : (s == 1) ? T1l : T2l;

    int bx = blockIdx.x * 32;  // n
    int by = blockIdx.y * 32;  // k
    int tx = threadIdx.x & 31;
    int ty = threadIdx.x >> 5; // 0..7
#pragma unroll
    for (int i = ty; i < 32; i += 8)
        tile[i][tx] = W[(size_t)(by + i) * cols + bx + tx];
    __syncthreads();
#pragma unroll
    for (int i = ty; i < 32; i += 8) {
        float v = tile[tx][i];  // = W[by+tx][bx+i]
        __nv_bfloat16 h = __float2bfloat16(v);
        __nv_bfloat16 l = __float2bfloat16(v - __bfloat162float(h));
        size_t o = (size_t)(bx + i) * rows + by + tx;
        Th[o] = h;
        Tl[o] = l;
    }
}

// ---------------------------------------------------------------------------
// scale+mask+softmax, fp32 logits in -> bf16 hi/lo attn out
// ---------------------------------------------------------------------------
__global__ void __launch_bounds__(256)
softmax_split(const float* __restrict__ logits, const float* __restrict__ mask,
              __nv_bfloat16* __restrict__ ah, __nv_bfloat16* __restrict__ al,
              float scale)
{
    __shared__ float red[8];
    __shared__ float bval;

    size_t row = blockIdx.x;
    int q = (int)(row & (SDIM - 1));
    const float* rp = logits + row * (size_t)SDIM;
    const float* mp = mask + (size_t)q * SDIM;
    int t = threadIdx.x;

    float4 a = ((const float4*)rp)[t];
    float4 b = ((const float4*)rp)[t + 256];
    float4 ma = ((const float4*)mp)[t];
    float4 mb = ((const float4*)mp)[t + 256];
    float x[8];
    x[0] = fmaf(a.x, scale, ma.x); x[1] = fmaf(a.y, scale, ma.y);
    x[2] = fmaf(a.z, scale, ma.z); x[3] = fmaf(a.w, scale, ma.w);
    x[4] = fmaf(b.x, scale, mb.x); x[5] = fmaf(b.y, scale, mb.y);
    x[6] = fmaf(b.z, scale, mb.z); x[7] = fmaf(b.w, scale, mb.w);

    float mx = x[0];
#pragma unroll
    for (int i = 1; i < 8; i++) mx = fmaxf(mx, x[i]);
#pragma unroll
    for (int o = 16; o; o >>= 1) mx = fmaxf(mx, __shfl_xor_sync(0xffffffffu, mx, o));
    if ((t & 31) == 0) red[t >> 5] = mx;
    __syncthreads();
    if (t == 0) {
        float m = red[0];
#pragma unroll
        for (int i = 1; i < 8; i++) m = fmaxf(m, red[i]);
        bval = m;
    }
    __syncthreads();
    mx = bval;

    float s = 0.f;
#pragma unroll
    for (int i = 0; i < 8; i++) { x[i] = __expf(x[i] - mx); s += x[i]; }
#pragma unroll
    for (int o = 16; o; o >>= 1) s += __shfl_xor_sync(0xffffffffu, s, o);
    if ((t & 31) == 0) red[t >> 5] = s;
    __syncthreads();
    if (t == 0) {
        float ss = 0.f;
#pragma unroll
        for (int i = 0; i < 8; i++) ss += red[i];
        bval = 1.f / ss;
    }
    __syncthreads();
    float inv = bval;

    __nv_bfloat162* ah2 = (__nv_bfloat162*)(ah + row * (size_t)SDIM);
    __nv_bfloat162* al2 = (__nv_bfloat162*)(al + row * (size_t)SDIM);
#pragma unroll
    for (int half = 0; half < 2; half++) {
#pragma unroll
        for (int p = 0; p < 2; p++) {
            float p0 = x[half * 4 + p * 2 + 0] * inv;
            float p1 = x[half * 4 + p * 2 + 1] * inv;
            __nv_bfloat16 h0 = __float2bfloat16(p0);
            __nv_bfloat16 h1 = __float2bfloat16(p1);
            __nv_bfloat16 l0 = __float2bfloat16(p0 - __bfloat162float(h0));
            __nv_bfloat16 l1 = __float2bfloat16(p1 - __bfloat162float(h1));
            int idx = half * 512 + t * 2 + p;
            ah2[idx] = __nv_bfloat162(h0, h1);
            al2[idx] = __nv_bfloat162(l0, l1);
        }
    }
}

// ---------------------------------------------------------------------------
extern "C" void kernel_launch(void* const* d_in, const int* in_sizes, int n_in,
                              void* d_out, int out_size)
{
    const float* q    = (const float*)d_in[0];
    const float* k    = (const float*)d_in[1];
    const float* v    = (const float*)d_in[2];
    const float* mask = (const float*)d_in[3];
    const float* wq   = (const float*)d_in[4];
    const float* bq   = (const float*)d_in[5];
    const float* wk   = (const float*)d_in[6];
    const float* bk   = (const float*)d_in[7];
    const float* wv   = (const float*)d_in[8];
    const float* bv   = (const float*)d_in[9];
    float* out = (float*)d_out;

#define SYM(p, s) do { void* _t; cudaGetSymbolAddress(&_t, s); p = (decltype(p))_t; } while (0)
    __nv_bfloat16 *qh, *ql, *kh, *kl, *vh, *vl;
    __nv_bfloat16 *wqth, *wqtl, *wkth, *wktl, *wvth, *wvtl;
    __nv_bfloat16 *qph, *qpl, *kph, *kpl, *vpth, *vptl, *ah, *al;
    float* lg;
    SYM(qh, g_qh); SYM(ql, g_ql); SYM(kh, g_kh); SYM(kl, g_kl);
    SYM(vh, g_vh); SYM(vl, g_vl);
    SYM(wqth, g_wqt_h); SYM(wqtl, g_wqt_l);
    SYM(wkth, g_wkt_h); SYM(wktl, g_wkt_l);
    SYM(wvth, g_wvt_h); SYM(wvtl, g_wvt_l);
    SYM(qph, g_qph); SYM(qpl, g_qpl); SYM(kph, g_kph); SYM(kpl, g_kpl);
    SYM(vpth, g_vpth); SYM(vptl, g_vptl);
    SYM(ah, g_ah); SYM(al, g_al);
    SYM(lg, g_logits);
#undef SYM

    cudaFuncSetAttribute(proj_gemm, cudaFuncAttributeMaxDynamicSharedMemorySize, SMEM_TOTAL);
    cudaFuncSetAttribute(hmma_gemm_f32, cudaFuncAttributeMaxDynamicSharedMemorySize, SMEM_TOTAL);

    const int n4 = NTOK * IDIM / 4;

    // 1: merged hi/lo split of q, k, v
    split_f32_3<<<dim3(n4 / 256, 3), 256>>>((const float4*)q, qh, ql,
                                            (const float4*)k, kh, kl,
                                            (const float4*)v, vh, vl, n4);
    // 2: merged weight transpose+split
    transpose_split_3<<<dim3(IDIM / 32, IDIM / 32, 3), 256>>>(
        wq, wqth, wqtl, wk, wkth, wktl, wv, wvth, wvtl, IDIM, DDIM);

    // 3: merged QKV projections (z selects operand set; z=2 writes vp^T)
    dim3 gp(DDIM / 128, NTOK / 64, 3);          // 3072 CTAs
    proj_gemm<<<gp, NTHREADS, SMEM_TOTAL>>>(qh, ql, kh, kl, vh, vl,
                                            wqth, wqtl, wkth, wktl, wvth, wvtl,
                                            bq, bk, bv,
                                            qph, qpl, kph, kpl, vpth, vptl);

    // 4: logits = qp @ kp^T (batched over B)   <- ncu profiles this launch
    dim3 gl(SDIM / 128, SDIM / 64, BDIM);       // 2048 CTAs
    hmma_gemm_f32<<<gl, NTHREADS, SMEM_TOTAL>>>(qph, qpl, kph, kpl, lg,
                                                DDIM, DDIM, DDIM, SDIM,
                                                (size_t)SDIM * DDIM, (size_t)SDIM * DDIM,
                                                (size_t)SDIM * SDIM);

    // 5: softmax -> attn hi/lo
    softmax_split<<<BDIM * SDIM, 256>>>(lg, mask, ah, al, 0.03125f);

    // 6: out = attn @ vp (B operand = vp^T, batch offset = column shift)
    dim3 ga(DDIM / 128, SDIM / 64, BDIM);       // 1024 CTAs
    hmma_gemm_f32<<<ga, NTHREADS, SMEM_TOTAL>>>(ah, al, vpth, vptl, out,
                                                SDIM, SDIM, NTOK, DDIM,
                                                (size_t)SDIM * SDIM, (size_t)SDIM,
                                                (size_t)SDIM * DDIM);
}

// round 12
// speedup vs baseline: 1.0972x; 1.0972x over previous
#include <cuda_runtime.h>
#include <cuda_bf16.h>
#include <cuda_fp16.h>
#include <cstdint>

#define BDIM 4
#define SDIM 2048
#define IDIM 1024
#define DDIM 1024
#define NTOK (BDIM * SDIM)   // 8192

// ---------------------------------------------------------------------------
// Device scratch (allocation-free rule)
// ---------------------------------------------------------------------------
__device__ __align__(128) __nv_bfloat16 g_qh[(size_t)NTOK * IDIM];
__device__ __align__(128) __nv_bfloat16 g_ql[(size_t)NTOK * IDIM];
__device__ __align__(128) __nv_bfloat16 g_kh[(size_t)NTOK * IDIM];
__device__ __align__(128) __nv_bfloat16 g_kl[(size_t)NTOK * IDIM];
__device__ __align__(128) __nv_bfloat16 g_vh[(size_t)NTOK * IDIM];
__device__ __align__(128) __nv_bfloat16 g_vl[(size_t)NTOK * IDIM];
__device__ __align__(128) __nv_bfloat16 g_wqt_h[(size_t)DDIM * IDIM];
__device__ __align__(128) __nv_bfloat16 g_wqt_l[(size_t)DDIM * IDIM];
__device__ __align__(128) __nv_bfloat16 g_wkt_h[(size_t)DDIM * IDIM];
__device__ __align__(128) __nv_bfloat16 g_wkt_l[(size_t)DDIM * IDIM];
__device__ __align__(128) __nv_bfloat16 g_wvt_h[(size_t)DDIM * IDIM];
__device__ __align__(128) __nv_bfloat16 g_wvt_l[(size_t)DDIM * IDIM];
__device__ __align__(128) __nv_bfloat16 g_qph[(size_t)NTOK * DDIM];
__device__ __align__(128) __nv_bfloat16 g_qpl[(size_t)NTOK * DDIM];
__device__ __align__(128) __nv_bfloat16 g_kph[(size_t)NTOK * DDIM];
__device__ __align__(128) __nv_bfloat16 g_kpl[(size_t)NTOK * DDIM];
__device__ __align__(128) __half g_vpth[(size_t)DDIM * NTOK];  // [D, tokens] fp16
__device__ __align__(128) float g_logits[(size_t)BDIM * SDIM * SDIM];
__device__ __align__(128) __half g_ah[(size_t)BDIM * SDIM * SDIM];   // attn hi fp16
__device__ __align__(128) __half g_al[(size_t)BDIM * SDIM * SDIM];   // attn lo fp16

// ---------------------------------------------------------------------------
// PTX helpers
// ---------------------------------------------------------------------------
__device__ __forceinline__ uint32_t smem_u32(const void* p) {
    uint32_t a;
    asm("{ .reg .u64 t; cvta.to.shared.u64 t, %1; cvt.u32.u64 %0, t; }"
        : "=r"(a) : "l"(p));
    return a;
}

__device__ __forceinline__ void cp16(uint32_t d, const void* g) {
    asm volatile("cp.async.cg.shared.global [%0], [%1], 16;" :: "r"(d), "l"(g) : "memory");
}
#define CP_COMMIT() asm volatile("cp.async.commit_group;" ::: "memory")
#define CP_WAIT1()  asm volatile("cp.async.wait_group 1;" ::: "memory")

__device__ __forceinline__ void ldsm4(uint32_t* r, uint32_t addr) {
    asm volatile("ldmatrix.sync.aligned.m8n8.x4.shared.b16 {%0,%1,%2,%3}, [%4];"
        : "=r"(r[0]), "=r"(r[1]), "=r"(r[2]), "=r"(r[3]) : "r"(addr));
}

// mma.sync m16n8k16 bf16 -> fp32 accumulate
__device__ __forceinline__ void mma_bf16(float* d, const uint32_t* a,
                                         uint32_t b0, uint32_t b1) {
    asm volatile(
        "mma.sync.aligned.m16n8k16.row.col.f32.bf16.bf16.f32 "
        "{%0,%1,%2,%3}, {%4,%5,%6,%7}, {%8,%9}, {%0,%1,%2,%3};"
        : "+f"(d[0]), "+f"(d[1]), "+f"(d[2]), "+f"(d[3])
        : "r"(a[0]), "r"(a[1]), "r"(a[2]), "r"(a[3]), "r"(b0), "r"(b1));
}

// mma.sync m16n8k16 fp16 -> fp32 accumulate
__device__ __forceinline__ void mma_fp16(float* d, const uint32_t* a,
                                         uint32_t b0, uint32_t b1) {
    asm volatile(
        "mma.sync.aligned.m16n8k16.row.col.f32.f16.f16.f32 "
        "{%0,%1,%2,%3}, {%4,%5,%6,%7}, {%8,%9}, {%0,%1,%2,%3};"
        : "+f"(d[0]), "+f"(d[1]), "+f"(d[2]), "+f"(d[3])
        : "r"(a[0]), "r"(a[1]), "r"(a[2]), "r"(a[3]), "r"(b0), "r"(b1));
}

// SMEM stage (bf16 3-product GEMMs): 4 arrays of 128 rows x 80B pitch, KT=32
#define KT 32
#define ROWB 80
#define ARR_BYTES (128 * ROWB)          // 10240
#define OFF_AH 0
#define OFF_AL ARR_BYTES
#define OFF_BH (2 * ARR_BYTES)
#define OFF_BL (3 * ARR_BYTES)
#define STG_BYTES (4 * ARR_BYTES)       // 40960
#define NSTAGE 2
#define SMEM_TOTAL (NSTAGE * STG_BYTES) // 81920 -> 2 CTAs/SM

// AV stage (fp16 2-product): 3 arrays
#define AV_OFF_AH 0
#define AV_OFF_AL ARR_BYTES
#define AV_OFF_B  (2 * ARR_BYTES)
#define AV_STG (3 * ARR_BYTES)          // 30720
#define AV_SMEM_TOTAL (NSTAGE * AV_STG) // 61440

#define NTHREADS 256

// transpose staging pitch (elements): 128 tokens + 4 pad
#define TPITCH 132

__device__ __forceinline__ void load_arr(const __nv_bfloat16* __restrict__ G,
                                         int ldg, int kt, uint32_t dst, int tid) {
#pragma unroll
    for (int i = 0; i < 2; i++) {
        int idx = tid + i * NTHREADS;
        int row = idx >> 2;
        int c = idx & 3;
        cp16(dst + row * ROWB + c * 16, (const void*)(G + (size_t)row * ldg + kt + c * 8));
    }
}

// ---------------------------------------------------------------------------
// bf16 3-product mainloop: D[128,128] += A[128,K] * B[128,K]^T (NT).
// 8 warps (4 m x 2 n), warp tile 32x64; 2-stage ping-pong, 2 CTAs/SM.
// ---------------------------------------------------------------------------
__device__ __forceinline__ void gemm_mainloop(
    const __nv_bfloat16* __restrict__ Ahb, const __nv_bfloat16* __restrict__ Alb,
    const __nv_bfloat16* __restrict__ Bhb, const __nv_bfloat16* __restrict__ Blb,
    int K, int lda, int ldb,
    uint32_t sbase, int tid, int wm, int wn, int lane,
    float d[2][8][4])
{
    const int w8 = lane & 7, j8 = lane >> 3;
    int aoff[2], boff[4];
#pragma unroll
    for (int mf = 0; mf < 2; mf++)
        aoff[mf] = (wm * 32 + mf * 16 + w8 + 8 * (j8 & 1)) * ROWB + (j8 >> 1) * 16;
#pragma unroll
    for (int g = 0; g < 4; g++)
        boff[g] = (wn * 64 + g * 16 + w8 + 8 * (j8 >> 1)) * ROWB + (j8 & 1) * 16;

    const int T = K / KT;

#pragma unroll
    for (int p = 0; p < 2; p++) {
        uint32_t b = sbase + p * STG_BYTES;
        load_arr(Ahb, lda, p * KT, b + OFF_AH, tid);
        load_arr(Alb, lda, p * KT, b + OFF_AL, tid);
        load_arr(Bhb, ldb, p * KT, b + OFF_BH, tid);
        load_arr(Blb, ldb, p * KT, b + OFF_BL, tid);
        CP_COMMIT();
    }

    for (int t = 0; t < T; t++) {
        CP_WAIT1();
        __syncthreads();

        const uint32_t sb = sbase + (t & 1) * STG_BYTES;
        const uint32_t sAh = sb + OFF_AH;
        const uint32_t sAl = sb + OFF_AL;
        const uint32_t sBh = sb + OFF_BH;
        const uint32_t sBl = sb + OFF_BL;

#pragma unroll
        for (int ks = 0; ks < 2; ks++) {
            const int kb = ks * 32;
            uint32_t ah[2][4], al[2][4];
            ldsm4(ah[0], sAh + aoff[0] + kb);
            ldsm4(ah[1], sAh + aoff[1] + kb);
            ldsm4(al[0], sAl + aoff[0] + kb);
            ldsm4(al[1], sAl + aoff[1] + kb);
#pragma unroll
            for (int g = 0; g < 4; g++) {
                uint32_t bh[4], bl[4];
                ldsm4(bh, sBh + boff[g] + kb);
                ldsm4(bl, sBl + boff[g] + kb);
#pragma unroll
                for (int sub = 0; sub < 2; sub++) {
                    const int nf = g * 2 + sub;
                    const uint32_t bh0 = bh[sub * 2], bh1 = bh[sub * 2 + 1];
                    const uint32_t bl0 = bl[sub * 2], bl1 = bl[sub * 2 + 1];
                    mma_bf16(d[0][nf], ah[0], bh0, bh1);
                    mma_bf16(d[1][nf], ah[1], bh0, bh1);
                    mma_bf16(d[0][nf], ah[0], bl0, bl1);
                    mma_bf16(d[1][nf], ah[1], bl0, bl1);
                    mma_bf16(d[0][nf], al[0], bh0, bh1);
                    mma_bf16(d[1][nf], al[1], bh0, bh1);
                }
            }
        }

        __syncthreads();
        if (t + 2 < T) {
            const int kt = (t + 2) * KT;
            load_arr(Ahb, lda, kt, sb + OFF_AH, tid);
            load_arr(Alb, lda, kt, sb + OFF_AL, tid);
            load_arr(Bhb, ldb, kt, sb + OFF_BH, tid);
            load_arr(Blb, ldb, kt, sb + OFF_BL, tid);
        }
        CP_COMMIT();
    }
}

// ---------------------------------------------------------------------------
// Merged QKV projection GEMM. blockIdx.z in {0,1,2} selects {Q,K,V}.
// z<2: bias + bf16 hi/lo split, row-major. z=2: bias + fp16 ROUND only,
// transposed [DDIM, NTOK] via smem staging (coalesced stores).
// ---------------------------------------------------------------------------
__global__ void __launch_bounds__(NTHREADS, 2)
proj_gemm(const __nv_bfloat16* __restrict__ qh, const __nv_bfloat16* __restrict__ ql,
          const __nv_bfloat16* __restrict__ kh, const __nv_bfloat16* __restrict__ kl,
          const __nv_bfloat16* __restrict__ vh, const __nv_bfloat16* __restrict__ vl,
          const __nv_bfloat16* __restrict__ wqh, const __nv_bfloat16* __restrict__ wql,
          const __nv_bfloat16* __restrict__ wkh, const __nv_bfloat16* __restrict__ wkl,
          const __nv_bfloat16* __restrict__ wvh, const __nv_bfloat16* __restrict__ wvl,
          const float* __restrict__ bq, const float* __restrict__ bk,
          const float* __restrict__ bv,
          __nv_bfloat16* __restrict__ qph, __nv_bfloat16* __restrict__ qpl,
          __nv_bfloat16* __restrict__ kph, __nv_bfloat16* __restrict__ kpl,
          __half* __restrict__ vpth)
{
    extern __shared__ char smem[];
    const uint32_t sbase = smem_u32(smem);
    const int tid = threadIdx.x;
    const int wid = tid >> 5, lane = tid & 31;
    const int wm = wid & 3, wn = wid >> 2;
    const int mBase = blockIdx.y * 128;
    const int nBase = blockIdx.x * 128;
    const int z = blockIdx.z;

    const __nv_bfloat16* Ah = (z == 0) ? qh : (z == 1) ? kh : vh;
    const __nv_bfloat16* Al = (z == 0) ? ql : (z == 1) ? kl : vl;
    const __nv_bfloat16* Bh = (z == 0) ? wqh : (z == 1) ? wkh : wvh;
    const __nv_bfloat16* Bl = (z == 0) ? wql : (z == 1) ? wkl : wvl;
    const float* bias = (z == 0) ? bq : (z == 1) ? bk : bv;

    float d[2][8][4];
#pragma unroll
    for (int i = 0; i < 2; i++)
#pragma unroll
        for (int j = 0; j < 8; j++)
#pragma unroll
            for (int e = 0; e < 4; e++) d[i][j][e] = 0.f;

    gemm_mainloop(Ah + (size_t)mBase * IDIM, Al + (size_t)mBase * IDIM,
                  Bh + (size_t)nBase * IDIM, Bl + (size_t)nBase * IDIM,
                  IDIM, IDIM, IDIM, sbase, tid, wm, wn, lane, d);

    if (z != 2) {
        __nv_bfloat16* Ch = (z == 0) ? qph : kph;
        __nv_bfloat16* Cl = (z == 0) ? qpl : kpl;
        const int row0 = mBase + wm * 32 + (lane >> 2);
        const int col0 = nBase + wn * 64 + (lane & 3) * 2;
#pragma unroll
        for (int mf = 0; mf < 2; mf++) {
#pragma unroll
            for (int nf = 0; nf < 8; nf++) {
                const int r = row0 + mf * 16;
                const int c = col0 + nf * 8;
                const float* dd = d[mf][nf];
                const float b0v = bias[c], b1v = bias[c + 1];
#pragma unroll
                for (int h = 0; h < 2; h++) {
                    float v0 = dd[h * 2 + 0] + b0v;
                    float v1 = dd[h * 2 + 1] + b1v;
                    __nv_bfloat16 h0 = __float2bfloat16(v0);
                    __nv_bfloat16 h1 = __float2bfloat16(v1);
                    __nv_bfloat16 l0 = __float2bfloat16(v0 - __bfloat162float(h0));
                    __nv_bfloat16 l1 = __float2bfloat16(v1 - __bfloat162float(h1));
                    size_t o = (size_t)(r + h * 8) * DDIM + c;
                    *(__nv_bfloat162*)(Ch + o) = __nv_bfloat162(h0, h1);
                    *(__nv_bfloat162*)(Cl + o) = __nv_bfloat162(l0, l1);
                }
            }
        }
    } else {
        // stage fp16 tile [col][token] in smem, then coalesced writes
        __syncthreads();
        __half* sh = (__half*)smem;
        const int lr0 = wm * 32 + (lane >> 2);
        const int lc0 = wn * 64 + (lane & 3) * 2;
#pragma unroll
        for (int mf = 0; mf < 2; mf++) {
#pragma unroll
            for (int nf = 0; nf < 8; nf++) {
                const float* dd = d[mf][nf];
                const int c = lc0 + nf * 8;
                const float b0v = bias[nBase + c], b1v = bias[nBase + c + 1];
#pragma unroll
                for (int h = 0; h < 2; h++) {
                    const int r = lr0 + mf * 16 + h * 8;
                    sh[c * TPITCH + r] = __float2half_rn(dd[h * 2 + 0] + b0v);
                    sh[(c + 1) * TPITCH + r] = __float2half_rn(dd[h * 2 + 1] + b1v);
                }
            }
        }
        __syncthreads();
        // 8 warps x 16 cols: lane covers 4 tokens (8B) -> 256B/warp/col
#pragma unroll
        for (int i = 0; i < 16; i++) {
            const int c = wid * 16 + i;
            uint2 vh2 = *(const uint2*)(sh + c * TPITCH + lane * 4);
            size_t o = (size_t)(nBase + c) * NTOK + mBase + lane * 4;
            *(uint2*)(vpth + o) = vh2;
        }
    }
}

// ---------------------------------------------------------------------------
// Logits GEMM (bf16 3-product), fp32 out, batched via strides.
// ---------------------------------------------------------------------------
__global__ void __launch_bounds__(NTHREADS, 2)
hmma_gemm_f32(const __nv_bfloat16* __restrict__ Ah, const __nv_bfloat16* __restrict__ Al,
              const __nv_bfloat16* __restrict__ Bh, const __nv_bfloat16* __restrict__ Bl,
              float* __restrict__ Cf,
              int K, int lda, int ldb, int ldc,
              size_t sA, size_t sB, size_t sC)
{
    extern __shared__ char smem[];
    const uint32_t sbase = smem_u32(smem);
    const int tid = threadIdx.x;
    const int wid = tid >> 5, lane = tid & 31;
    const int wm = wid & 3, wn = wid >> 2;
    const int mBase = blockIdx.y * 128;
    const int nBase = blockIdx.x * 128;
    const int z = blockIdx.z;

    float d[2][8][4];
#pragma unroll
    for (int i = 0; i < 2; i++)
#pragma unroll
        for (int j = 0; j < 8; j++)
#pragma unroll
            for (int e = 0; e < 4; e++) d[i][j][e] = 0.f;

    gemm_mainloop(Ah + z * sA + (size_t)mBase * lda, Al + z * sA + (size_t)mBase * lda,
                  Bh + z * sB + (size_t)nBase * ldb, Bl + z * sB + (size_t)nBase * ldb,
                  K, lda, ldb, sbase, tid, wm, wn, lane, d);

    const int row0 = mBase + wm * 32 + (lane >> 2);
    const int col0 = nBase + wn * 64 + (lane & 3) * 2;
    float* Cp = Cf + z * sC;

#pragma unroll
    for (int mf = 0; mf < 2; mf++) {
#pragma unroll
        for (int nf = 0; nf < 8; nf++) {
            const int r = row0 + mf * 16;
            const int c = col0 + nf * 8;
            const float* dd = d[mf][nf];
            *(float2*)(Cp + (size_t)r * ldc + c) = make_float2(dd[0], dd[1]);
            *(float2*)(Cp + (size_t)(r + 8) * ldc + c) = make_float2(dd[2], dd[3]);
        }
    }
}

// ---------------------------------------------------------------------------
// AV GEMM: fp16 2-product. D = (ah + al) @ vph^T(NT form).
// A: attn hi/lo fp16 [row=q, col=k], B: vpth fp16 [row=d, col=token].
// ---------------------------------------------------------------------------
__global__ void __launch_bounds__(NTHREADS, 2)
av_gemm(const __half* __restrict__ Ahg, const __half* __restrict__ Alg,
        const __half* __restrict__ Bg, float* __restrict__ Cf,
        int K, int lda, int ldb, int ldc,
        size_t sA, size_t sB, size_t sC)
{
    extern __shared__ char smem[];
    const uint32_t sbase = smem_u32(smem);
    const int tid = threadIdx.x;
    const int wid = tid >> 5, lane = tid & 31;
    const int wm = wid & 3, wn = wid >> 2;
    const int mBase = blockIdx.y * 128;
    const int nBase = blockIdx.x * 128;
    const int z = blockIdx.z;

    const __nv_bfloat16* Ahb = (const __nv_bfloat16*)(Ahg + z * sA + (size_t)mBase * lda);
    const __nv_bfloat16* Alb = (const __nv_bfloat16*)(Alg + z * sA + (size_t)mBase * lda);
    const __nv_bfloat16* Bb  = (const __nv_bfloat16*)(Bg + z * sB + (size_t)nBase * ldb);

    const int w8 = lane & 7, j8 = lane >> 3;
    int aoff[2], boff[4];
#pragma unroll
    for (int mf = 0; mf < 2; mf++)
        aoff[mf] = (wm * 32 + mf * 16 + w8 + 8 * (j8 & 1)) * ROWB + (j8 >> 1) * 16;
#pragma unroll
    for (int g = 0; g < 4; g++)
        boff[g] = (wn * 64 + g * 16 + w8 + 8 * (j8 >> 1)) * ROWB + (j8 & 1) * 16;

    float d[2][8][4];
#pragma unroll
    for (int i = 0; i < 2; i++)
#pragma unroll
        for (int j = 0; j < 8; j++)
#pragma unroll
            for (int e = 0; e < 4; e++) d[i][j][e] = 0.f;

    const int T = K / KT;

#pragma unroll
    for (int p = 0; p < 2; p++) {
        uint32_t b = sbase + p * AV_STG;
        load_arr(Ahb, lda, p * KT, b + AV_OFF_AH, tid);
        load_arr(Alb, lda, p * KT, b + AV_OFF_AL, tid);
        load_arr(Bb,  ldb, p * KT, b + AV_OFF_B, tid);
        CP_COMMIT();
    }

    for (int t = 0; t < T; t++) {
        CP_WAIT1();
        __syncthreads();

        const uint32_t sb = sbase + (t & 1) * AV_STG;
        const uint32_t sAh = sb + AV_OFF_AH;
        const uint32_t sAl = sb + AV_OFF_AL;
        const uint32_t sB  = sb + AV_OFF_B;

#pragma unroll
        for (int ks = 0; ks < 2; ks++) {
            const int kb = ks * 32;
            uint32_t ah[2][4], al[2][4];
            ldsm4(ah[0], sAh + aoff[0] + kb);
            ldsm4(ah[1], sAh + aoff[1] + kb);
            ldsm4(al[0], sAl + aoff[0] + kb);
            ldsm4(al[1], sAl + aoff[1] + kb);
#pragma unroll
            for (int g = 0; g < 4; g++) {
                uint32_t bh[4];
                ldsm4(bh, sB + boff[g] + kb);
#pragma unroll
                for (int sub = 0; sub < 2; sub++) {
                    const int nf = g * 2 + sub;
                    const uint32_t b0 = bh[sub * 2], b1 = bh[sub * 2 + 1];
                    mma_fp16(d[0][nf], ah[0], b0, b1);
                    mma_fp16(d[1][nf], ah[1], b0, b1);
                    mma_fp16(d[0][nf], al[0], b0, b1);
                    mma_fp16(d[1][nf], al[1], b0, b1);
                }
            }
        }

        __syncthreads();
        if (t + 2 < T) {
            const int kt = (t + 2) * KT;
            load_arr(Ahb, lda, kt, sb + AV_OFF_AH, tid);
            load_arr(Alb, lda, kt, sb + AV_OFF_AL, tid);
            load_arr(Bb,  ldb, kt, sb + AV_OFF_B, tid);
        }
        CP_COMMIT();
    }

    const int row0 = mBase + wm * 32 + (lane >> 2);
    const int col0 = nBase + wn * 64 + (lane & 3) * 2;
    float* Cp = Cf + z * sC;

#pragma unroll
    for (int mf = 0; mf < 2; mf++) {
#pragma unroll
        for (int nf = 0; nf < 8; nf++) {
            const int r = row0 + mf * 16;
            const int c = col0 + nf * 8;
            const float* dd = d[mf][nf];
            *(float2*)(Cp + (size_t)r * ldc + c) = make_float2(dd[0], dd[1]);
            *(float2*)(Cp + (size_t)(r + 8) * ldc + c) = make_float2(dd[2], dd[3]);
        }
    }
}

// ---------------------------------------------------------------------------
// fp32 -> (hi, lo) bf16 split; grid.y selects among 3 tensors
// ---------------------------------------------------------------------------
__global__ void __launch_bounds__(256)
split_f32_3(const float4* __restrict__ x0, __nv_bfloat16* __restrict__ h0p, __nv_bfloat16* __restrict__ l0p,
            const float4* __restrict__ x1, __nv_bfloat16* __restrict__ h1p, __nv_bfloat16* __restrict__ l1p,
            const float4* __restrict__ x2, __nv_bfloat16* __restrict__ h2p, __nv_bfloat16* __restrict__ l2p,
            int n4)
{
    int i = blockIdx.x * 256 + threadIdx.x;
    if (i >= n4) return;
    int s = blockIdx.y;
    const float4* x = (s == 0) ? x0 : (s == 1) ? x1 : x2;
    __nv_bfloat16* hi = (s == 0) ? h0p : (s == 1) ? h1p : h2p;
    __nv_bfloat16* lo = (s == 0) ? l0p : (s == 1) ? l1p : l2p;

    float4 v = x[i];
    float vv[4] = {v.x, v.y, v.z, v.w};
    __nv_bfloat162 h2[2], l2[2];
#pragma unroll
    for (int j = 0; j < 4; j++) {
        __nv_bfloat16 h = __float2bfloat16(vv[j]);
        __nv_bfloat16 l = __float2bfloat16(vv[j] - __bfloat162float(h));
        ((__nv_bfloat16*)h2)[j] = h;
        ((__nv_bfloat16*)l2)[j] = l;
    }
    ((__nv_bfloat162*)hi)[i * 2]     = h2[0];
    ((__nv_bfloat162*)hi)[i * 2 + 1] = h2[1];
    ((__nv_bfloat162*)lo)[i * 2]     = l2[0];
    ((__nv_bfloat162*)lo)[i * 2 + 1] = l2[1];
}

// Merged W[K,N] fp32 -> WT hi/lo [N,K] bf16 for all 3 weights (grid.z)
__global__ void __launch_bounds__(256)
transpose_split_3(const float* __restrict__ W0, __nv_bfloat16* __restrict__ T0h, __nv_bfloat16* __restrict__ T0l,
                  const float* __restrict__ W1, __nv_bfloat16* __restrict__ T1h, __nv_bfloat16* __restrict__ T1l,
                  const float* __restrict__ W2, __nv_bfloat16* __restrict__ T2h, __nv_bfloat16* __restrict__ T2l,
                  int rows, int cols)
{
    __shared__ float tile[32][33];
    int s = blockIdx.z;
    const float* W = (s == 0) ? W0 : (s == 1) ? W1 : W2;
    __nv_bfloat16* Th = (s == 0) ? T0h : (s == 1) ? T1h : T2h;
    __nv_bfloat16* Tl = (s == 0) ? T0l : (s == 1) ? T1l : T2l;

    int bx = blockIdx.x * 32;  // n
    int by = blockIdx.y * 32;  // k
    int tx = threadIdx.x & 31;
    int ty = threadIdx.x >> 5; // 0..7
#pragma unroll
    for (int i = ty; i < 32; i += 8)
        tile[i][tx] = W[(size_t)(by + i) * cols + bx + tx];
    __syncthreads();
#pragma unroll
    for (int i = ty; i < 32; i += 8) {
        float v = tile[tx][i];  // = W[by+tx][bx+i]
        __nv_bfloat16 h = __float2bfloat16(v);
        __nv_bfloat16 l = __float2bfloat16(v - __bfloat162float(h));
        size_t o = (size_t)(bx + i) * rows + by + tx;
        Th[o] = h;
        Tl[o] = l;
    }
}

// ---------------------------------------------------------------------------
// scale+mask+softmax, fp32 logits in -> fp16 hi/lo attn out
// ---------------------------------------------------------------------------
__global__ void __launch_bounds__(256)
softmax_split(const float* __restrict__ logits, const float* __restrict__ mask,
              __half* __restrict__ ah, __half* __restrict__ al,
              float scale)
{
    __shared__ float red[8];
    __shared__ float bval;

    size_t row = blockIdx.x;
    int q = (int)(row & (SDIM - 1));
    const float* rp = logits + row * (size_t)SDIM;
    const float* mp = mask + (size_t)q * SDIM;
    int t = threadIdx.x;

    float4 a = ((const float4*)rp)[t];
    float4 b = ((const float4*)rp)[t + 256];
    float4 ma = ((const float4*)mp)[t];
    float4 mb = ((const float4*)mp)[t + 256];
    float x[8];
    x[0] = fmaf(a.x, scale, ma.x); x[1] = fmaf(a.y, scale, ma.y);
    x[2] = fmaf(a.z, scale, ma.z); x[3] = fmaf(a.w, scale, ma.w);
    x[4] = fmaf(b.x, scale, mb.x); x[5] = fmaf(b.y, scale, mb.y);
    x[6] = fmaf(b.z, scale, mb.z); x[7] = fmaf(b.w, scale, mb.w);

    float mx = x[0];
#pragma unroll
    for (int i = 1; i < 8; i++) mx = fmaxf(mx, x[i]);
#pragma unroll
    for (int o = 16; o; o >>= 1) mx = fmaxf(mx, __shfl_xor_sync(0xffffffffu, mx, o));
    if ((t & 31) == 0) red[t >> 5] = mx;
    __syncthreads();
    if (t == 0) {
        float m = red[0];
#pragma unroll
        for (int i = 1; i < 8; i++) m = fmaxf(m, red[i]);
        bval = m;
    }
    __syncthreads();
    mx = bval;

    float s = 0.f;
#pragma unroll
    for (int i = 0; i < 8; i++) { x[i] = __expf(x[i] - mx); s += x[i]; }
#pragma unroll
    for (int o = 16; o; o >>= 1) s += __shfl_xor_sync(0xffffffffu, s, o);
    if ((t & 31) == 0) red[t >> 5] = s;
    __syncthreads();
    if (t == 0) {
        float ss = 0.f;
#pragma unroll
        for (int i = 0; i < 8; i++) ss += red[i];
        bval = 1.f / ss;
    }
    __syncthreads();
    float inv = bval;

    __half2* ah2 = (__half2*)(ah + row * (size_t)SDIM);
    __half2* al2 = (__half2*)(al + row * (size_t)SDIM);
#pragma unroll
    for (int half = 0; half < 2; half++) {
#pragma unroll
        for (int p = 0; p < 2; p++) {
            float p0 = x[half * 4 + p * 2 + 0] * inv;
            float p1 = x[half * 4 + p * 2 + 1] * inv;
            __half h0 = __float2half_rn(p0);
            __half h1 = __float2half_rn(p1);
            __half l0 = __float2half_rn(p0 - __half2float(h0));
            __half l1 = __float2half_rn(p1 - __half2float(h1));
            int idx = half * 512 + t * 2 + p;
            ah2[idx] = __halves2half2(h0, h1);
            al2[idx] = __halves2half2(l0, l1);
        }
    }
}

// ---------------------------------------------------------------------------
extern "C" void kernel_launch(void* const* d_in, const int* in_sizes, int n_in,
                              void* d_out, int out_size)
{
    const float* q    = (const float*)d_in[0];
    const float* k    = (const float*)d_in[1];
    const float* v    = (const float*)d_in[2];
    const float* mask = (const float*)d_in[3];
    const float* wq   = (const float*)d_in[4];
    const float* bq   = (const float*)d_in[5];
    const float* wk   = (const float*)d_in[6];
    const float* bk   = (const float*)d_in[7];
    const float* wv   = (const float*)d_in[8];
    const float* bv   = (const float*)d_in[9];
    float* out = (float*)d_out;

#define SYM(p, s) do { void* _t; cudaGetSymbolAddress(&_t, s); p = (decltype(p))_t; } while (0)
    __nv_bfloat16 *qh, *ql, *kh, *kl, *vh, *vl;
    __nv_bfloat16 *wqth, *wqtl, *wkth, *wktl, *wvth, *wvtl;
    __nv_bfloat16 *qph, *qpl, *kph, *kpl;
    __half *vpth, *ah, *al;
    float* lg;
    SYM(qh, g_qh); SYM(ql, g_ql); SYM(kh, g_kh); SYM(kl, g_kl);
    SYM(vh, g_vh); SYM(vl, g_vl);
    SYM(wqth, g_wqt_h); SYM(wqtl, g_wqt_l);
    SYM(wkth, g_wkt_h); SYM(wktl, g_wkt_l);
    SYM(wvth, g_wvt_h); SYM(wvtl, g_wvt_l);
    SYM(qph, g_qph); SYM(qpl, g_qpl); SYM(kph, g_kph); SYM(kpl, g_kpl);
    SYM(vpth, g_vpth);
    SYM(ah, g_ah); SYM(al, g_al);
    SYM(lg, g_logits);
#undef SYM

    cudaFuncSetAttribute(proj_gemm, cudaFuncAttributeMaxDynamicSharedMemorySize, SMEM_TOTAL);
    cudaFuncSetAttribute(hmma_gemm_f32, cudaFuncAttributeMaxDynamicSharedMemorySize, SMEM_TOTAL);
    cudaFuncSetAttribute(av_gemm, cudaFuncAttributeMaxDynamicSharedMemorySize, AV_SMEM_TOTAL);

    const int n4 = NTOK * IDIM / 4;

    // 1: merged hi/lo split of q, k, v
    split_f32_3<<<dim3(n4 / 256, 3), 256>>>((const float4*)q, qh, ql,
                                            (const float4*)k, kh, kl,
                                            (const float4*)v, vh, vl, n4);
    // 2: merged weight transpose+split
    transpose_split_3<<<dim3(IDIM / 32, IDIM / 32, 3), 256>>>(
        wq, wqth, wqtl, wk, wkth, wktl, wv, wvth, wvtl, IDIM, DDIM);

    // 3: merged QKV projections (z=2 writes fp16 vp^T)
    dim3 gp(DDIM / 128, NTOK / 128, 3);
    proj_gemm<<<gp, NTHREADS, SMEM_TOTAL>>>(qh, ql, kh, kl, vh, vl,
                                            wqth, wqtl, wkth, wktl, wvth, wvtl,
                                            bq, bk, bv,
                                            qph, qpl, kph, kpl, vpth);

    // 4: logits = qp @ kp^T (batched over B)   <- ncu profiles this launch
    dim3 gl(SDIM / 128, SDIM / 128, BDIM);
    hmma_gemm_f32<<<gl, NTHREADS, SMEM_TOTAL>>>(qph, qpl, kph, kpl, lg,
                                                DDIM, DDIM, DDIM, SDIM,
                                                (size_t)SDIM * DDIM, (size_t)SDIM * DDIM,
                                                (size_t)SDIM * SDIM);

    // 5: softmax -> attn fp16 hi/lo
    softmax_split<<<BDIM * SDIM, 256>>>(lg, mask, ah, al, 0.03125f);

    // 6: out = (ah + al) @ vph  (fp16 2-product)
    dim3 ga(DDIM / 128, SDIM / 128, BDIM);
    av_gemm<<<ga, NTHREADS, AV_SMEM_TOTAL>>>(ah, al, vpth, out,
                                             SDIM, SDIM, NTOK, DDIM,
                                             (size_t)SDIM * SDIM, (size_t)SDIM,
                                             (size_t)SDIM * DDIM);
}

// round 13
// speedup vs baseline: 1.2021x; 1.0956x over previous
#include <cuda_runtime.h>
#include <cuda_bf16.h>
#include <cuda_fp16.h>
#include <cstdint>

#define BDIM 4
#define SDIM 2048
#define IDIM 1024
#define DDIM 1024
#define NTOK (BDIM * SDIM)   // 8192

// ---------------------------------------------------------------------------
// Device scratch (allocation-free rule)
// ---------------------------------------------------------------------------
__device__ __align__(128) __nv_bfloat16 g_qh[(size_t)NTOK * IDIM];
__device__ __align__(128) __nv_bfloat16 g_ql[(size_t)NTOK * IDIM];
__device__ __align__(128) __nv_bfloat16 g_kh[(size_t)NTOK * IDIM];
__device__ __align__(128) __nv_bfloat16 g_kl[(size_t)NTOK * IDIM];
__device__ __align__(128) __nv_bfloat16 g_vh[(size_t)NTOK * IDIM];
__device__ __align__(128) __nv_bfloat16 g_vl[(size_t)NTOK * IDIM];
__device__ __align__(128) __nv_bfloat16 g_wqh[(size_t)IDIM * DDIM];  // natural layout
__device__ __align__(128) __nv_bfloat16 g_wql[(size_t)IDIM * DDIM];
__device__ __align__(128) __nv_bfloat16 g_wkh[(size_t)IDIM * DDIM];
__device__ __align__(128) __nv_bfloat16 g_wkl[(size_t)IDIM * DDIM];
__device__ __align__(128) __nv_bfloat16 g_wvt_h[(size_t)DDIM * IDIM]; // transposed
__device__ __align__(128) __nv_bfloat16 g_wvt_l[(size_t)DDIM * IDIM];
__device__ __align__(128) __nv_bfloat16 g_Mh[(size_t)IDIM * IDIM];   // M = Wq Wk^T
__device__ __align__(128) __nv_bfloat16 g_Ml[(size_t)IDIM * IDIM];
__device__ __align__(128) __nv_bfloat16 g_Ph[(size_t)NTOK * IDIM];   // P = k M^T
__device__ __align__(128) __nv_bfloat16 g_Pl[(size_t)NTOK * IDIM];
__device__ __align__(128) __half g_vpth[(size_t)DDIM * NTOK];        // vp^T fp16
__device__ __align__(128) float g_logits[(size_t)BDIM * SDIM * SDIM];
__device__ __align__(128) __half g_ah[(size_t)BDIM * SDIM * SDIM];
__device__ __align__(128) __half g_al[(size_t)BDIM * SDIM * SDIM];
__device__ float g_w1[IDIM];   // Wq·bk
__device__ float g_w2[IDIM];   // Wk·bq
__device__ float g_c[1];       // bq·bk
__device__ float g_u[NTOK];    // scaled row bias
__device__ float g_v[NTOK];    // scaled col bias

// ---------------------------------------------------------------------------
// PTX helpers
// ---------------------------------------------------------------------------
__device__ __forceinline__ uint32_t smem_u32(const void* p) {
    uint32_t a;
    asm("{ .reg .u64 t; cvta.to.shared.u64 t, %1; cvt.u32.u64 %0, t; }"
        : "=r"(a) : "l"(p));
    return a;
}

__device__ __forceinline__ void cp16(uint32_t d, const void* g) {
    asm volatile("cp.async.cg.shared.global [%0], [%1], 16;" :: "r"(d), "l"(g) : "memory");
}
#define CP_COMMIT() asm volatile("cp.async.commit_group;" ::: "memory")
#define CP_WAIT1()  asm volatile("cp.async.wait_group 1;" ::: "memory")

__device__ __forceinline__ void ldsm4(uint32_t* r, uint32_t addr) {
    asm volatile("ldmatrix.sync.aligned.m8n8.x4.shared.b16 {%0,%1,%2,%3}, [%4];"
        : "=r"(r[0]), "=r"(r[1]), "=r"(r[2]), "=r"(r[3]) : "r"(addr));
}

__device__ __forceinline__ void mma_bf16(float* d, const uint32_t* a,
                                         uint32_t b0, uint32_t b1) {
    asm volatile(
        "mma.sync.aligned.m16n8k16.row.col.f32.bf16.bf16.f32 "
        "{%0,%1,%2,%3}, {%4,%5,%6,%7}, {%8,%9}, {%0,%1,%2,%3};"
        : "+f"(d[0]), "+f"(d[1]), "+f"(d[2]), "+f"(d[3])
        : "r"(a[0]), "r"(a[1]), "r"(a[2]), "r"(a[3]), "r"(b0), "r"(b1));
}

__device__ __forceinline__ void mma_fp16(float* d, const uint32_t* a,
                                         uint32_t b0, uint32_t b1) {
    asm volatile(
        "mma.sync.aligned.m16n8k16.row.col.f32.f16.f16.f32 "
        "{%0,%1,%2,%3}, {%4,%5,%6,%7}, {%8,%9}, {%0,%1,%2,%3};"
        : "+f"(d[0]), "+f"(d[1]), "+f"(d[2]), "+f"(d[3])
        : "r"(a[0]), "r"(a[1]), "r"(a[2]), "r"(a[3]), "r"(b0), "r"(b1));
}

// SMEM stage (bf16 3-product GEMMs): 4 arrays of 128 rows x 80B pitch, KT=32
#define KT 32
#define ROWB 80
#define ARR_BYTES (128 * ROWB)
#define OFF_AH 0
#define OFF_AL ARR_BYTES
#define OFF_BH (2 * ARR_BYTES)
#define OFF_BL (3 * ARR_BYTES)
#define STG_BYTES (4 * ARR_BYTES)
#define NSTAGE 2
#define SMEM_TOTAL (NSTAGE * STG_BYTES)   // 81920 -> 2 CTAs/SM

// AV stage (fp16 2-product): 3 arrays
#define AV_OFF_AH 0
#define AV_OFF_AL ARR_BYTES
#define AV_OFF_B  (2 * ARR_BYTES)
#define AV_STG (3 * ARR_BYTES)
#define AV_SMEM_TOTAL (NSTAGE * AV_STG)

#define NTHREADS 256
#define TPITCH 132

__device__ __forceinline__ void load_arr(const __nv_bfloat16* __restrict__ G,
                                         int ldg, int kt, uint32_t dst, int tid) {
#pragma unroll
    for (int i = 0; i < 2; i++) {
        int idx = tid + i * NTHREADS;
        int row = idx >> 2;
        int c = idx & 3;
        cp16(dst + row * ROWB + c * 16, (const void*)(G + (size_t)row * ldg + kt + c * 8));
    }
}

// ---------------------------------------------------------------------------
// bf16 3-product mainloop: D[128,128] += A[128,K] * B[128,K]^T (NT).
// ---------------------------------------------------------------------------
__device__ __forceinline__ void gemm_mainloop(
    const __nv_bfloat16* __restrict__ Ahb, const __nv_bfloat16* __restrict__ Alb,
    const __nv_bfloat16* __restrict__ Bhb, const __nv_bfloat16* __restrict__ Blb,
    int K, int lda, int ldb,
    uint32_t sbase, int tid, int wm, int wn, int lane,
    float d[2][8][4])
{
    const int w8 = lane & 7, j8 = lane >> 3;
    int aoff[2], boff[4];
#pragma unroll
    for (int mf = 0; mf < 2; mf++)
        aoff[mf] = (wm * 32 + mf * 16 + w8 + 8 * (j8 & 1)) * ROWB + (j8 >> 1) * 16;
#pragma unroll
    for (int g = 0; g < 4; g++)
        boff[g] = (wn * 64 + g * 16 + w8 + 8 * (j8 >> 1)) * ROWB + (j8 & 1) * 16;

    const int T = K / KT;

#pragma unroll
    for (int p = 0; p < 2; p++) {
        uint32_t b = sbase + p * STG_BYTES;
        load_arr(Ahb, lda, p * KT, b + OFF_AH, tid);
        load_arr(Alb, lda, p * KT, b + OFF_AL, tid);
        load_arr(Bhb, ldb, p * KT, b + OFF_BH, tid);
        load_arr(Blb, ldb, p * KT, b + OFF_BL, tid);
        CP_COMMIT();
    }

    for (int t = 0; t < T; t++) {
        CP_WAIT1();
        __syncthreads();

        const uint32_t sb = sbase + (t & 1) * STG_BYTES;
        const uint32_t sAh = sb + OFF_AH;
        const uint32_t sAl = sb + OFF_AL;
        const uint32_t sBh = sb + OFF_BH;
        const uint32_t sBl = sb + OFF_BL;

#pragma unroll
        for (int ks = 0; ks < 2; ks++) {
            const int kb = ks * 32;
            uint32_t ah[2][4], al[2][4];
            ldsm4(ah[0], sAh + aoff[0] + kb);
            ldsm4(ah[1], sAh + aoff[1] + kb);
            ldsm4(al[0], sAl + aoff[0] + kb);
            ldsm4(al[1], sAl + aoff[1] + kb);
#pragma unroll
            for (int g = 0; g < 4; g++) {
                uint32_t bh[4], bl[4];
                ldsm4(bh, sBh + boff[g] + kb);
                ldsm4(bl, sBl + boff[g] + kb);
#pragma unroll
                for (int sub = 0; sub < 2; sub++) {
                    const int nf = g * 2 + sub;
                    const uint32_t bh0 = bh[sub * 2], bh1 = bh[sub * 2 + 1];
                    const uint32_t bl0 = bl[sub * 2], bl1 = bl[sub * 2 + 1];
                    mma_bf16(d[0][nf], ah[0], bh0, bh1);
                    mma_bf16(d[1][nf], ah[1], bh0, bh1);
                    mma_bf16(d[0][nf], ah[0], bl0, bl1);
                    mma_bf16(d[1][nf], ah[1], bl0, bl1);
                    mma_bf16(d[0][nf], al[0], bh0, bh1);
                    mma_bf16(d[1][nf], al[1], bh0, bh1);
                }
            }
        }

        __syncthreads();
        if (t + 2 < T) {
            const int kt = (t + 2) * KT;
            load_arr(Ahb, lda, kt, sb + OFF_AH, tid);
            load_arr(Alb, lda, kt, sb + OFF_AL, tid);
            load_arr(Bhb, ldb, kt, sb + OFF_BH, tid);
            load_arr(Blb, ldb, kt, sb + OFF_BL, tid);
        }
        CP_COMMIT();
    }
}

// Shared epilogue: accum -> bf16 hi/lo split, row-major, optional bias
__device__ __forceinline__ void epi_split(
    float d[2][8][4], __nv_bfloat16* Ch, __nv_bfloat16* Cl,
    const float* bias, int mBase, int nBase, int ldc, int wm, int wn, int lane)
{
    const int row0 = mBase + wm * 32 + (lane >> 2);
    const int col0 = nBase + wn * 64 + (lane & 3) * 2;
#pragma unroll
    for (int mf = 0; mf < 2; mf++) {
#pragma unroll
        for (int nf = 0; nf < 8; nf++) {
            const int r = row0 + mf * 16;
            const int c = col0 + nf * 8;
            const float* dd = d[mf][nf];
            const float b0v = bias ? bias[c] : 0.f;
            const float b1v = bias ? bias[c + 1] : 0.f;
#pragma unroll
            for (int h = 0; h < 2; h++) {
                float v0 = dd[h * 2 + 0] + b0v;
                float v1 = dd[h * 2 + 1] + b1v;
                __nv_bfloat16 h0 = __float2bfloat16(v0);
                __nv_bfloat16 h1 = __float2bfloat16(v1);
                __nv_bfloat16 l0 = __float2bfloat16(v0 - __bfloat162float(h0));
                __nv_bfloat16 l1 = __float2bfloat16(v1 - __bfloat162float(h1));
                size_t o = (size_t)(r + h * 8) * ldc + c;
                *(__nv_bfloat162*)(Ch + o) = __nv_bfloat162(h0, h1);
                *(__nv_bfloat162*)(Cl + o) = __nv_bfloat162(l0, l1);
            }
        }
    }
}

// ---------------------------------------------------------------------------
// M = Wq (Wk)^T with split epilogue. Grid (8, 8).
// ---------------------------------------------------------------------------
__global__ void __launch_bounds__(NTHREADS, 2)
m_gemm(const __nv_bfloat16* __restrict__ Ah, const __nv_bfloat16* __restrict__ Al,
       const __nv_bfloat16* __restrict__ Bh, const __nv_bfloat16* __restrict__ Bl,
       __nv_bfloat16* __restrict__ Ch, __nv_bfloat16* __restrict__ Cl)
{
    extern __shared__ char smem[];
    const uint32_t sbase = smem_u32(smem);
    const int tid = threadIdx.x;
    const int wid = tid >> 5, lane = tid & 31;
    const int wm = wid & 3, wn = wid >> 2;
    const int mBase = blockIdx.y * 128;
    const int nBase = blockIdx.x * 128;

    float d[2][8][4];
#pragma unroll
    for (int i = 0; i < 2; i++)
#pragma unroll
        for (int j = 0; j < 8; j++)
#pragma unroll
            for (int e = 0; e < 4; e++) d[i][j][e] = 0.f;

    gemm_mainloop(Ah + (size_t)mBase * DDIM, Al + (size_t)mBase * DDIM,
                  Bh + (size_t)nBase * DDIM, Bl + (size_t)nBase * DDIM,
                  DDIM, DDIM, DDIM, sbase, tid, wm, wn, lane, d);

    epi_split(d, Ch, Cl, nullptr, mBase, nBase, IDIM, wm, wn, lane);
}

// ---------------------------------------------------------------------------
// Merged P / V GEMM. z=0: P = k M^T -> split. z=1: vp = v Wv + bv -> fp16
// transposed [DDIM, NTOK]. Grid (8, 64, 2).
// ---------------------------------------------------------------------------
__global__ void __launch_bounds__(NTHREADS, 2)
pv_gemm(const __nv_bfloat16* __restrict__ kh, const __nv_bfloat16* __restrict__ kl,
        const __nv_bfloat16* __restrict__ Mh, const __nv_bfloat16* __restrict__ Ml,
        const __nv_bfloat16* __restrict__ vh, const __nv_bfloat16* __restrict__ vl,
        const __nv_bfloat16* __restrict__ wvth, const __nv_bfloat16* __restrict__ wvtl,
        const float* __restrict__ bv,
        __nv_bfloat16* __restrict__ Ph, __nv_bfloat16* __restrict__ Pl,
        __half* __restrict__ vpth)
{
    extern __shared__ char smem[];
    const uint32_t sbase = smem_u32(smem);
    const int tid = threadIdx.x;
    const int wid = tid >> 5, lane = tid & 31;
    const int wm = wid & 3, wn = wid >> 2;
    const int mBase = blockIdx.y * 128;
    const int nBase = blockIdx.x * 128;
    const int z = blockIdx.z;

    const __nv_bfloat16* Ah = z ? vh : kh;
    const __nv_bfloat16* Al = z ? vl : kl;
    const __nv_bfloat16* Bh = z ? wvth : Mh;
    const __nv_bfloat16* Bl = z ? wvtl : Ml;

    float d[2][8][4];
#pragma unroll
    for (int i = 0; i < 2; i++)
#pragma unroll
        for (int j = 0; j < 8; j++)
#pragma unroll
            for (int e = 0; e < 4; e++) d[i][j][e] = 0.f;

    gemm_mainloop(Ah + (size_t)mBase * IDIM, Al + (size_t)mBase * IDIM,
                  Bh + (size_t)nBase * IDIM, Bl + (size_t)nBase * IDIM,
                  IDIM, IDIM, IDIM, sbase, tid, wm, wn, lane, d);

    if (z == 0) {
        epi_split(d, Ph, Pl, nullptr, mBase, nBase, IDIM, wm, wn, lane);
    } else {
        __syncthreads();
        __half* sh = (__half*)smem;
        const int lr0 = wm * 32 + (lane >> 2);
        const int lc0 = wn * 64 + (lane & 3) * 2;
#pragma unroll
        for (int mf = 0; mf < 2; mf++) {
#pragma unroll
            for (int nf = 0; nf < 8; nf++) {
                const float* dd = d[mf][nf];
                const int c = lc0 + nf * 8;
                const float b0v = bv[nBase + c], b1v = bv[nBase + c + 1];
#pragma unroll
                for (int h = 0; h < 2; h++) {
                    const int r = lr0 + mf * 16 + h * 8;
                    sh[c * TPITCH + r] = __float2half_rn(dd[h * 2 + 0] + b0v);
                    sh[(c + 1) * TPITCH + r] = __float2half_rn(dd[h * 2 + 1] + b1v);
                }
            }
        }
        __syncthreads();
#pragma unroll
        for (int i = 0; i < 16; i++) {
            const int c = wid * 16 + i;
            uint2 vh2 = *(const uint2*)(sh + c * TPITCH + lane * 4);
            size_t o = (size_t)(nBase + c) * NTOK + mBase + lane * 4;
            *(uint2*)(vpth + o) = vh2;
        }
    }
}

// ---------------------------------------------------------------------------
// Logits GEMM (bf16 3-product), fp32 out, batched. logits = q P^T.
// ---------------------------------------------------------------------------
__global__ void __launch_bounds__(NTHREADS, 2)
hmma_gemm_f32(const __nv_bfloat16* __restrict__ Ah, const __nv_bfloat16* __restrict__ Al,
              const __nv_bfloat16* __restrict__ Bh, const __nv_bfloat16* __restrict__ Bl,
              float* __restrict__ Cf,
              int K, int lda, int ldb, int ldc,
              size_t sA, size_t sB, size_t sC)
{
    extern __shared__ char smem[];
    const uint32_t sbase = smem_u32(smem);
    const int tid = threadIdx.x;
    const int wid = tid >> 5, lane = tid & 31;
    const int wm = wid & 3, wn = wid >> 2;
    const int mBase = blockIdx.y * 128;
    const int nBase = blockIdx.x * 128;
    const int z = blockIdx.z;

    float d[2][8][4];
#pragma unroll
    for (int i = 0; i < 2; i++)
#pragma unroll
        for (int j = 0; j < 8; j++)
#pragma unroll
            for (int e = 0; e < 4; e++) d[i][j][e] = 0.f;

    gemm_mainloop(Ah + z * sA + (size_t)mBase * lda, Al + z * sA + (size_t)mBase * lda,
                  Bh + z * sB + (size_t)nBase * ldb, Bl + z * sB + (size_t)nBase * ldb,
                  K, lda, ldb, sbase, tid, wm, wn, lane, d);

    const int row0 = mBase + wm * 32 + (lane >> 2);
    const int col0 = nBase + wn * 64 + (lane & 3) * 2;
    float* Cp = Cf + z * sC;

#pragma unroll
    for (int mf = 0; mf < 2; mf++) {
#pragma unroll
        for (int nf = 0; nf < 8; nf++) {
            const int r = row0 + mf * 16;
            const int c = col0 + nf * 8;
            const float* dd = d[mf][nf];
            *(float2*)(Cp + (size_t)r * ldc + c) = make_float2(dd[0], dd[1]);
            *(float2*)(Cp + (size_t)(r + 8) * ldc + c) = make_float2(dd[2], dd[3]);
        }
    }
}

// ---------------------------------------------------------------------------
// AV GEMM: fp16 2-product (unchanged from R12).
// ---------------------------------------------------------------------------
__global__ void __launch_bounds__(NTHREADS, 2)
av_gemm(const __half* __restrict__ Ahg, const __half* __restrict__ Alg,
        const __half* __restrict__ Bg, float* __restrict__ Cf,
        int K, int lda, int ldb, int ldc,
        size_t sA, size_t sB, size_t sC)
{
    extern __shared__ char smem[];
    const uint32_t sbase = smem_u32(smem);
    const int tid = threadIdx.x;
    const int wid = tid >> 5, lane = tid & 31;
    const int wm = wid & 3, wn = wid >> 2;
    const int mBase = blockIdx.y * 128;
    const int nBase = blockIdx.x * 128;
    const int z = blockIdx.z;

    const __nv_bfloat16* Ahb = (const __nv_bfloat16*)(Ahg + z * sA + (size_t)mBase * lda);
    const __nv_bfloat16* Alb = (const __nv_bfloat16*)(Alg + z * sA + (size_t)mBase * lda);
    const __nv_bfloat16* Bb  = (const __nv_bfloat16*)(Bg + z * sB + (size_t)nBase * ldb);

    const int w8 = lane & 7, j8 = lane >> 3;
    int aoff[2], boff[4];
#pragma unroll
    for (int mf = 0; mf < 2; mf++)
        aoff[mf] = (wm * 32 + mf * 16 + w8 + 8 * (j8 & 1)) * ROWB + (j8 >> 1) * 16;
#pragma unroll
    for (int g = 0; g < 4; g++)
        boff[g] = (wn * 64 + g * 16 + w8 + 8 * (j8 >> 1)) * ROWB + (j8 & 1) * 16;

    float d[2][8][4];
#pragma unroll
    for (int i = 0; i < 2; i++)
#pragma unroll
        for (int j = 0; j < 8; j++)
#pragma unroll
            for (int e = 0; e < 4; e++) d[i][j][e] = 0.f;

    const int T = K / KT;

#pragma unroll
    for (int p = 0; p < 2; p++) {
        uint32_t b = sbase + p * AV_STG;
        load_arr(Ahb, lda, p * KT, b + AV_OFF_AH, tid);
        load_arr(Alb, lda, p * KT, b + AV_OFF_AL, tid);
        load_arr(Bb,  ldb, p * KT, b + AV_OFF_B, tid);
        CP_COMMIT();
    }

    for (int t = 0; t < T; t++) {
        CP_WAIT1();
        __syncthreads();

        const uint32_t sb = sbase + (t & 1) * AV_STG;
        const uint32_t sAh = sb + AV_OFF_AH;
        const uint32_t sAl = sb + AV_OFF_AL;
        const uint32_t sB  = sb + AV_OFF_B;

#pragma unroll
        for (int ks = 0; ks < 2; ks++) {
            const int kb = ks * 32;
            uint32_t ah[2][4], al[2][4];
            ldsm4(ah[0], sAh + aoff[0] + kb);
            ldsm4(ah[1], sAh + aoff[1] + kb);
            ldsm4(al[0], sAl + aoff[0] + kb);
            ldsm4(al[1], sAl + aoff[1] + kb);
#pragma unroll
            for (int g = 0; g < 4; g++) {
                uint32_t bh[4];
                ldsm4(bh, sB + boff[g] + kb);
#pragma unroll
                for (int sub = 0; sub < 2; sub++) {
                    const int nf = g * 2 + sub;
                    const uint32_t b0 = bh[sub * 2], b1 = bh[sub * 2 + 1];
                    mma_fp16(d[0][nf], ah[0], b0, b1);
                    mma_fp16(d[1][nf], ah[1], b0, b1);
                    mma_fp16(d[0][nf], al[0], b0, b1);
                    mma_fp16(d[1][nf], al[1], b0, b1);
                }
            }
        }

        __syncthreads();
        if (t + 2 < T) {
            const int kt = (t + 2) * KT;
            load_arr(Ahb, lda, kt, sb + AV_OFF_AH, tid);
            load_arr(Alb, lda, kt, sb + AV_OFF_AL, tid);
            load_arr(Bb,  ldb, kt, sb + AV_OFF_B, tid);
        }
        CP_COMMIT();
    }

    const int row0 = mBase + wm * 32 + (lane >> 2);
    const int col0 = nBase + wn * 64 + (lane & 3) * 2;
    float* Cp = Cf + z * sC;

#pragma unroll
    for (int mf = 0; mf < 2; mf++) {
#pragma unroll
        for (int nf = 0; nf < 8; nf++) {
            const int r = row0 + mf * 16;
            const int c = col0 + nf * 8;
            const float* dd = d[mf][nf];
            *(float2*)(Cp + (size_t)r * ldc + c) = make_float2(dd[0], dd[1]);
            *(float2*)(Cp + (size_t)(r + 8) * ldc + c) = make_float2(dd[2], dd[3]);
        }
    }
}

// ---------------------------------------------------------------------------
// 5-way fp32 -> bf16 hi/lo split (q, k, v, Wq, Wk)
// ---------------------------------------------------------------------------
__global__ void __launch_bounds__(256)
split5(const float4* x0, __nv_bfloat16* h0, __nv_bfloat16* l0, int n0,
       const float4* x1, __nv_bfloat16* h1, __nv_bfloat16* l1, int n1,
       const float4* x2, __nv_bfloat16* h2, __nv_bfloat16* l2, int n2,
       const float4* x3, __nv_bfloat16* h3, __nv_bfloat16* l3, int n3,
       const float4* x4, __nv_bfloat16* h4, __nv_bfloat16* l4, int n4v)
{
    int i = blockIdx.x * 256 + threadIdx.x;
    int s = blockIdx.y;
    const float4* x; __nv_bfloat16* hi; __nv_bfloat16* lo; int n;
    switch (s) {
        case 0: x = x0; hi = h0; lo = l0; n = n0; break;
        case 1: x = x1; hi = h1; lo = l1; n = n1; break;
        case 2: x = x2; hi = h2; lo = l2; n = n2; break;
        case 3: x = x3; hi = h3; lo = l3; n = n3; break;
        default: x = x4; hi = h4; lo = l4; n = n4v; break;
    }
    if (i >= n) return;

    float4 v = x[i];
    float vv[4] = {v.x, v.y, v.z, v.w};
    __nv_bfloat162 h2v[2], l2v[2];
#pragma unroll
    for (int j = 0; j < 4; j++) {
        __nv_bfloat16 h = __float2bfloat16(vv[j]);
        __nv_bfloat16 l = __float2bfloat16(vv[j] - __bfloat162float(h));
        ((__nv_bfloat16*)h2v)[j] = h;
        ((__nv_bfloat16*)l2v)[j] = l;
    }
    ((__nv_bfloat162*)hi)[i * 2]     = h2v[0];
    ((__nv_bfloat162*)hi)[i * 2 + 1] = h2v[1];
    ((__nv_bfloat162*)lo)[i * 2]     = l2v[0];
    ((__nv_bfloat162*)lo)[i * 2 + 1] = l2v[1];
}

// W[K,N] fp32 -> WT hi/lo [N,K] bf16 (single tensor: Wv)
__global__ void __launch_bounds__(256)
transpose_split(const float* __restrict__ W, __nv_bfloat16* __restrict__ Th,
                __nv_bfloat16* __restrict__ Tl, int rows, int cols)
{
    __shared__ float tile[32][33];
    int bx = blockIdx.x * 32;
    int by = blockIdx.y * 32;
    int tx = threadIdx.x & 31;
    int ty = threadIdx.x >> 5;
#pragma unroll
    for (int i = ty; i < 32; i += 8)
        tile[i][tx] = W[(size_t)(by + i) * cols + bx + tx];
    __syncthreads();
#pragma unroll
    for (int i = ty; i < 32; i += 8) {
        float v = tile[tx][i];
        __nv_bfloat16 h = __float2bfloat16(v);
        __nv_bfloat16 l = __float2bfloat16(v - __bfloat162float(h));
        size_t o = (size_t)(bx + i) * rows + by + tx;
        Th[o] = h;
        Tl[o] = l;
    }
}

// ---------------------------------------------------------------------------
// uv_prep: w1 = Wq bk, w2 = Wk bq, c = bq.bk   (one warp per row)
// ---------------------------------------------------------------------------
__global__ void __launch_bounds__(256)
uv_prep(const float* __restrict__ wq, const float* __restrict__ wk,
        const float* __restrict__ bq, const float* __restrict__ bk,
        float* __restrict__ w1, float* __restrict__ w2, float* __restrict__ cOut)
{
    int wid = threadIdx.x >> 5, lane = threadIdx.x & 31;
    int s = blockIdx.y;
    int row = blockIdx.x * 8 + wid;
    const float* W = s ? wk : wq;
    const float* b = s ? bq : bk;

    float acc = 0.f;
#pragma unroll
    for (int j = 0; j < 32; j++)
        acc += W[(size_t)row * DDIM + lane + 32 * j] * b[lane + 32 * j];
#pragma unroll
    for (int o = 16; o; o >>= 1) acc += __shfl_xor_sync(0xffffffffu, acc, o);
    if (lane == 0) (s ? w2 : w1)[row] = acc;

    if (blockIdx.x == 0 && s == 0 && wid == 0) {
        float cc = 0.f;
#pragma unroll
        for (int j = 0; j < 32; j++)
            cc += bq[lane + 32 * j] * bk[lane + 32 * j];
#pragma unroll
        for (int o = 16; o; o >>= 1) cc += __shfl_xor_sync(0xffffffffu, cc, o);
        if (lane == 0) cOut[0] = cc;
    }
}

// uv_main: u[i] = (q[i].w1 + c)*scale ; v[j] = (k[j].w2)*scale
__global__ void __launch_bounds__(256)
uv_main(const float* __restrict__ q, const float* __restrict__ k,
        const float* __restrict__ w1, const float* __restrict__ w2,
        const float* __restrict__ cIn,
        float* __restrict__ u, float* __restrict__ v, float scale)
{
    int wid = threadIdx.x >> 5, lane = threadIdx.x & 31;
    int s = blockIdx.y;
    int row = blockIdx.x * 8 + wid;
    const float* src = s ? k : q;
    const float* w = s ? w2 : w1;

    float acc = 0.f;
#pragma unroll
    for (int j = 0; j < 32; j++)
        acc += src[(size_t)row * IDIM + lane + 32 * j] * w[lane + 32 * j];
#pragma unroll
    for (int o = 16; o; o >>= 1) acc += __shfl_xor_sync(0xffffffffu, acc, o);
    if (lane == 0) {
        if (s == 0) u[row] = (acc + cIn[0]) * scale;
        else        v[row] = acc * scale;
    }
}

// ---------------------------------------------------------------------------
// softmax: x = lg*scale + mask + u[row] + v[col];  -> fp16 hi/lo attn
// ---------------------------------------------------------------------------
__global__ void __launch_bounds__(256)
softmax_split(const float* __restrict__ logits, const float* __restrict__ mask,
              const float* __restrict__ u, const float* __restrict__ vv,
              __half* __restrict__ ah, __half* __restrict__ al,
              float scale)
{
    __shared__ float red[8];
    __shared__ float bval;

    size_t row = blockIdx.x;
    int q = (int)(row & (SDIM - 1));
    const float* rp = logits + row * (size_t)SDIM;
    const float* mp = mask + (size_t)q * SDIM;
    const float* vr = vv + (row >> 11) * SDIM;   // batch base
    const float uval = u[row];
    int t = threadIdx.x;

    float4 a = ((const float4*)rp)[t];
    float4 b = ((const float4*)rp)[t + 256];
    float4 ma = ((const float4*)mp)[t];
    float4 mb = ((const float4*)mp)[t + 256];
    float4 va = ((const float4*)vr)[t];
    float4 vb = ((const float4*)vr)[t + 256];
    float x[8];
    x[0] = fmaf(a.x, scale, ma.x + uval + va.x);
    x[1] = fmaf(a.y, scale, ma.y + uval + va.y);
    x[2] = fmaf(a.z, scale, ma.z + uval + va.z);
    x[3] = fmaf(a.w, scale, ma.w + uval + va.w);
    x[4] = fmaf(b.x, scale, mb.x + uval + vb.x);
    x[5] = fmaf(b.y, scale, mb.y + uval + vb.y);
    x[6] = fmaf(b.z, scale, mb.z + uval + vb.z);
    x[7] = fmaf(b.w, scale, mb.w + uval + vb.w);

    float mx = x[0];
#pragma unroll
    for (int i = 1; i < 8; i++) mx = fmaxf(mx, x[i]);
#pragma unroll
    for (int o = 16; o; o >>= 1) mx = fmaxf(mx, __shfl_xor_sync(0xffffffffu, mx, o));
    if ((t & 31) == 0) red[t >> 5] = mx;
    __syncthreads();
    if (t == 0) {
        float m = red[0];
#pragma unroll
        for (int i = 1; i < 8; i++) m = fmaxf(m, red[i]);
        bval = m;
    }
    __syncthreads();
    mx = bval;

    float s = 0.f;
#pragma unroll
    for (int i = 0; i < 8; i++) { x[i] = __expf(x[i] - mx); s += x[i]; }
#pragma unroll
    for (int o = 16; o; o >>= 1) s += __shfl_xor_sync(0xffffffffu, s, o);
    if ((t & 31) == 0) red[t >> 5] = s;
    __syncthreads();
    if (t == 0) {
        float ss = 0.f;
#pragma unroll
        for (int i = 0; i < 8; i++) ss += red[i];
        bval = 1.f / ss;
    }
    __syncthreads();
    float inv = bval;

    __half2* ah2 = (__half2*)(ah + row * (size_t)SDIM);
    __half2* al2 = (__half2*)(al + row * (size_t)SDIM);
#pragma unroll
    for (int half = 0; half < 2; half++) {
#pragma unroll
        for (int p = 0; p < 2; p++) {
            float p0 = x[half * 4 + p * 2 + 0] * inv;
            float p1 = x[half * 4 + p * 2 + 1] * inv;
            __half h0 = __float2half_rn(p0);
            __half h1 = __float2half_rn(p1);
            __half l0 = __float2half_rn(p0 - __half2float(h0));
            __half l1 = __float2half_rn(p1 - __half2float(h1));
            int idx = half * 512 + t * 2 + p;
            ah2[idx] = __halves2half2(h0, h1);
            al2[idx] = __halves2half2(l0, l1);
        }
    }
}

// ---------------------------------------------------------------------------
extern "C" void kernel_launch(void* const* d_in, const int* in_sizes, int n_in,
                              void* d_out, int out_size)
{
    const float* q    = (const float*)d_in[0];
    const float* k    = (const float*)d_in[1];
    const float* v    = (const float*)d_in[2];
    const float* mask = (const float*)d_in[3];
    const float* wq   = (const float*)d_in[4];
    const float* bq   = (const float*)d_in[5];
    const float* wk   = (const float*)d_in[6];
    const float* bk   = (const float*)d_in[7];
    const float* wv   = (const float*)d_in[8];
    const float* bv   = (const float*)d_in[9];
    float* out = (float*)d_out;

#define SYM(p, s) do { void* _t; cudaGetSymbolAddress(&_t, s); p = (decltype(p))_t; } while (0)
    __nv_bfloat16 *qh, *ql, *kh, *kl, *vh, *vl;
    __nv_bfloat16 *wqh, *wql, *wkh, *wkl, *wvth, *wvtl;
    __nv_bfloat16 *Mh, *Ml, *Ph, *Pl;
    __half *vpth, *ah, *al;
    float *lg, *w1, *w2, *cptr, *u, *vvp;
    SYM(qh, g_qh); SYM(ql, g_ql); SYM(kh, g_kh); SYM(kl, g_kl);
    SYM(vh, g_vh); SYM(vl, g_vl);
    SYM(wqh, g_wqh); SYM(wql, g_wql); SYM(wkh, g_wkh); SYM(wkl, g_wkl);
    SYM(wvth, g_wvt_h); SYM(wvtl, g_wvt_l);
    SYM(Mh, g_Mh); SYM(Ml, g_Ml); SYM(Ph, g_Ph); SYM(Pl, g_Pl);
    SYM(vpth, g_vpth); SYM(ah, g_ah); SYM(al, g_al);
    SYM(lg, g_logits);
    SYM(w1, g_w1); SYM(w2, g_w2); SYM(cptr, g_c); SYM(u, g_u); SYM(vvp, g_v);
#undef SYM

    cudaFuncSetAttribute(m_gemm, cudaFuncAttributeMaxDynamicSharedMemorySize, SMEM_TOTAL);
    cudaFuncSetAttribute(pv_gemm, cudaFuncAttributeMaxDynamicSharedMemorySize, SMEM_TOTAL);
    cudaFuncSetAttribute(hmma_gemm_f32, cudaFuncAttributeMaxDynamicSharedMemorySize, SMEM_TOTAL);
    cudaFuncSetAttribute(av_gemm, cudaFuncAttributeMaxDynamicSharedMemorySize, AV_SMEM_TOTAL);

    const int n4_act = NTOK * IDIM / 4;     // q,k,v
    const int n4_w = IDIM * DDIM / 4;       // Wq,Wk
    const float scale = 0.03125f;

    // 1: split q,k,v,Wq,Wk to bf16 hi/lo
    split5<<<dim3(n4_act / 256, 5), 256>>>(
        (const float4*)q, qh, ql, n4_act,
        (const float4*)k, kh, kl, n4_act,
        (const float4*)v, vh, vl, n4_act,
        (const float4*)wq, wqh, wql, n4_w,
        (const float4*)wk, wkh, wkl, n4_w);

    // 2: transpose+split Wv
    transpose_split<<<dim3(IDIM / 32, IDIM / 32), 256>>>(wv, wvth, wvtl, IDIM, DDIM);

    // 3: M = Wq Wk^T (split epilogue)
    m_gemm<<<dim3(8, 8), NTHREADS, SMEM_TOTAL>>>(wqh, wql, wkh, wkl, Mh, Ml);

    // 4: P = k M^T (z=0) and vp^T fp16 (z=1)    <- ncu profiles this launch
    pv_gemm<<<dim3(IDIM / 128, NTOK / 128, 2), NTHREADS, SMEM_TOTAL>>>(
        kh, kl, Mh, Ml, vh, vl, wvth, wvtl, bv, Ph, Pl, vpth);

    // 5-6: rank-1 bias terms
    uv_prep<<<dim3(IDIM / 8, 2), 256>>>(wq, wk, bq, bk, w1, w2, cptr);
    uv_main<<<dim3(NTOK / 8, 2), 256>>>(q, k, w1, w2, cptr, u, vvp, scale);

    // 7: logits = q P^T (batched)
    dim3 gl(SDIM / 128, SDIM / 128, BDIM);
    hmma_gemm_f32<<<gl, NTHREADS, SMEM_TOTAL>>>(qh, ql, Ph, Pl, lg,
                                                IDIM, IDIM, IDIM, SDIM,
                                                (size_t)SDIM * IDIM, (size_t)SDIM * IDIM,
                                                (size_t)SDIM * SDIM);

    // 8: softmax with u/v/c folded in -> fp16 hi/lo attn
    softmax_split<<<BDIM * SDIM, 256>>>(lg, mask, u, vvp, ah, al, scale);

    // 9: out = (ah + al) @ vph (fp16 2-product)
    dim3 ga(DDIM / 128, SDIM / 128, BDIM);
    av_gemm<<<ga, NTHREADS, AV_SMEM_TOTAL>>>(ah, al, vpth, out,
                                             SDIM, SDIM, NTOK, DDIM,
                                             (size_t)SDIM * SDIM, (size_t)SDIM,
                                             (size_t)SDIM * DDIM);
}

// round 14
// speedup vs baseline: 1.4409x; 1.1987x over previous
#include <cuda_runtime.h>
#include <cuda_bf16.h>
#include <cuda_fp16.h>
#include <cstdint>

#define BDIM 4
#define SDIM 2048
#define IDIM 1024
#define DDIM 1024
#define NTOK (BDIM * SDIM)   // 8192

// ---------------------------------------------------------------------------
// Device scratch (allocation-free rule)
// ---------------------------------------------------------------------------
__device__ __align__(128) __nv_bfloat16 g_qh[(size_t)NTOK * IDIM];
__device__ __align__(128) __nv_bfloat16 g_ql[(size_t)NTOK * IDIM];
__device__ __align__(128) __nv_bfloat16 g_kh[(size_t)NTOK * IDIM];
__device__ __align__(128) __nv_bfloat16 g_kl[(size_t)NTOK * IDIM];
__device__ __align__(128) __half g_vh[(size_t)NTOK * IDIM];          // fp16 hi
__device__ __align__(128) __half g_vl[(size_t)NTOK * IDIM];          // fp16 lo
__device__ __align__(128) __nv_bfloat16 g_wqh[(size_t)IDIM * DDIM];
__device__ __align__(128) __nv_bfloat16 g_wql[(size_t)IDIM * DDIM];
__device__ __align__(128) __nv_bfloat16 g_wkh[(size_t)IDIM * DDIM];
__device__ __align__(128) __nv_bfloat16 g_wkl[(size_t)IDIM * DDIM];
__device__ __align__(128) __half g_wvt[(size_t)DDIM * IDIM];          // fp16, transposed
__device__ __align__(128) __nv_bfloat16 g_Mh[(size_t)IDIM * IDIM];   // M = Wq Wk^T
__device__ __align__(128) __nv_bfloat16 g_Ml[(size_t)IDIM * IDIM];
__device__ __align__(128) __nv_bfloat16 g_Ph[(size_t)NTOK * IDIM];   // P = k M^T
__device__ __align__(128) __nv_bfloat16 g_Pl[(size_t)NTOK * IDIM];
__device__ __align__(128) __half g_vpth[(size_t)DDIM * NTOK];        // vp^T fp16
__device__ __align__(128) float g_logits[(size_t)BDIM * SDIM * SDIM];
__device__ __align__(128) __half g_ah[(size_t)BDIM * SDIM * SDIM];   // attn fp16
__device__ float g_w1[IDIM];
__device__ float g_w2[IDIM];
__device__ float g_c[1];
__device__ float g_u[NTOK];
__device__ float g_v[NTOK];

// ---------------------------------------------------------------------------
// PTX helpers
// ---------------------------------------------------------------------------
__device__ __forceinline__ uint32_t smem_u32(const void* p) {
    uint32_t a;
    asm("{ .reg .u64 t; cvta.to.shared.u64 t, %1; cvt.u32.u64 %0, t; }"
        : "=r"(a) : "l"(p));
    return a;
}

__device__ __forceinline__ void cp16(uint32_t d, const void* g) {
    asm volatile("cp.async.cg.shared.global [%0], [%1], 16;" :: "r"(d), "l"(g) : "memory");
}
#define CP_COMMIT() asm volatile("cp.async.commit_group;" ::: "memory")
#define CP_WAIT1()  asm volatile("cp.async.wait_group 1;" ::: "memory")

__device__ __forceinline__ void ldsm4(uint32_t* r, uint32_t addr) {
    asm volatile("ldmatrix.sync.aligned.m8n8.x4.shared.b16 {%0,%1,%2,%3}, [%4];"
        : "=r"(r[0]), "=r"(r[1]), "=r"(r[2]), "=r"(r[3]) : "r"(addr));
}

__device__ __forceinline__ void mma_bf16(float* d, const uint32_t* a,
                                         uint32_t b0, uint32_t b1) {
    asm volatile(
        "mma.sync.aligned.m16n8k16.row.col.f32.bf16.bf16.f32 "
        "{%0,%1,%2,%3}, {%4,%5,%6,%7}, {%8,%9}, {%0,%1,%2,%3};"
        : "+f"(d[0]), "+f"(d[1]), "+f"(d[2]), "+f"(d[3])
        : "r"(a[0]), "r"(a[1]), "r"(a[2]), "r"(a[3]), "r"(b0), "r"(b1));
}

__device__ __forceinline__ void mma_fp16(float* d, const uint32_t* a,
                                         uint32_t b0, uint32_t b1) {
    asm volatile(
        "mma.sync.aligned.m16n8k16.row.col.f32.f16.f16.f32 "
        "{%0,%1,%2,%3}, {%4,%5,%6,%7}, {%8,%9}, {%0,%1,%2,%3};"
        : "+f"(d[0]), "+f"(d[1]), "+f"(d[2]), "+f"(d[3])
        : "r"(a[0]), "r"(a[1]), "r"(a[2]), "r"(a[3]), "r"(b0), "r"(b1));
}

// SMEM geometry (all GEMMs): 128 rows x 80B pitch arrays, KT=32
#define KT 32
#define ROWB 80
#define ARR_BYTES (128 * ROWB)
#define OFF_AH 0
#define OFF_AL ARR_BYTES
#define OFF_BH (2 * ARR_BYTES)
#define OFF_BL (3 * ARR_BYTES)
#define STG_BYTES (4 * ARR_BYTES)
#define SMEM_TOTAL (2 * STG_BYTES)        // 81920 -> 2 CTAs/SM

// 3-array stage (fp16 2-product V-proj)
#define S3_STG (3 * ARR_BYTES)
// 2-array stage (fp16 1-product AV)
#define S2_STG (2 * ARR_BYTES)
#define AV_SMEM_TOTAL (2 * S2_STG)        // 40960

#define NTHREADS 256
#define TPITCH 132

__device__ __forceinline__ void load_arr(const void* __restrict__ Gv,
                                         int ldg, int kt, uint32_t dst, int tid) {
    const __nv_bfloat16* G = (const __nv_bfloat16*)Gv;
#pragma unroll
    for (int i = 0; i < 2; i++) {
        int idx = tid + i * NTHREADS;
        int row = idx >> 2;
        int c = idx & 3;
        cp16(dst + row * ROWB + c * 16, (const void*)(G + (size_t)row * ldg + kt + c * 8));
    }
}

// ---------------------------------------------------------------------------
// bf16 3-product mainloop: D[128,128] += A[128,K] * B[128,K]^T (NT).
// ---------------------------------------------------------------------------
__device__ __forceinline__ void gemm_mainloop(
    const __nv_bfloat16* __restrict__ Ahb, const __nv_bfloat16* __restrict__ Alb,
    const __nv_bfloat16* __restrict__ Bhb, const __nv_bfloat16* __restrict__ Blb,
    int K, int lda, int ldb,
    uint32_t sbase, int tid, int wm, int wn, int lane,
    float d[2][8][4])
{
    const int w8 = lane & 7, j8 = lane >> 3;
    int aoff[2], boff[4];
#pragma unroll
    for (int mf = 0; mf < 2; mf++)
        aoff[mf] = (wm * 32 + mf * 16 + w8 + 8 * (j8 & 1)) * ROWB + (j8 >> 1) * 16;
#pragma unroll
    for (int g = 0; g < 4; g++)
        boff[g] = (wn * 64 + g * 16 + w8 + 8 * (j8 >> 1)) * ROWB + (j8 & 1) * 16;

    const int T = K / KT;

#pragma unroll
    for (int p = 0; p < 2; p++) {
        uint32_t b = sbase + p * STG_BYTES;
        load_arr(Ahb, lda, p * KT, b + OFF_AH, tid);
        load_arr(Alb, lda, p * KT, b + OFF_AL, tid);
        load_arr(Bhb, ldb, p * KT, b + OFF_BH, tid);
        load_arr(Blb, ldb, p * KT, b + OFF_BL, tid);
        CP_COMMIT();
    }

    for (int t = 0; t < T; t++) {
        CP_WAIT1();
        __syncthreads();

        const uint32_t sb = sbase + (t & 1) * STG_BYTES;
        const uint32_t sAh = sb + OFF_AH;
        const uint32_t sAl = sb + OFF_AL;
        const uint32_t sBh = sb + OFF_BH;
        const uint32_t sBl = sb + OFF_BL;

#pragma unroll
        for (int ks = 0; ks < 2; ks++) {
            const int kb = ks * 32;
            uint32_t ah[2][4], al[2][4];
            ldsm4(ah[0], sAh + aoff[0] + kb);
            ldsm4(ah[1], sAh + aoff[1] + kb);
            ldsm4(al[0], sAl + aoff[0] + kb);
            ldsm4(al[1], sAl + aoff[1] + kb);
#pragma unroll
            for (int g = 0; g < 4; g++) {
                uint32_t bh[4], bl[4];
                ldsm4(bh, sBh + boff[g] + kb);
                ldsm4(bl, sBl + boff[g] + kb);
#pragma unroll
                for (int sub = 0; sub < 2; sub++) {
                    const int nf = g * 2 + sub;
                    const uint32_t bh0 = bh[sub * 2], bh1 = bh[sub * 2 + 1];
                    const uint32_t bl0 = bl[sub * 2], bl1 = bl[sub * 2 + 1];
                    mma_bf16(d[0][nf], ah[0], bh0, bh1);
                    mma_bf16(d[1][nf], ah[1], bh0, bh1);
                    mma_bf16(d[0][nf], ah[0], bl0, bl1);
                    mma_bf16(d[1][nf], ah[1], bl0, bl1);
                    mma_bf16(d[0][nf], al[0], bh0, bh1);
                    mma_bf16(d[1][nf], al[1], bh0, bh1);
                }
            }
        }

        __syncthreads();
        if (t + 2 < T) {
            const int kt = (t + 2) * KT;
            load_arr(Ahb, lda, kt, sb + OFF_AH, tid);
            load_arr(Alb, lda, kt, sb + OFF_AL, tid);
            load_arr(Bhb, ldb, kt, sb + OFF_BH, tid);
            load_arr(Blb, ldb, kt, sb + OFF_BL, tid);
        }
        CP_COMMIT();
    }
}

// Shared epilogue: accum -> bf16 hi/lo split, row-major
__device__ __forceinline__ void epi_split(
    float d[2][8][4], __nv_bfloat16* Ch, __nv_bfloat16* Cl,
    int mBase, int nBase, int ldc, int wm, int wn, int lane)
{
    const int row0 = mBase + wm * 32 + (lane >> 2);
    const int col0 = nBase + wn * 64 + (lane & 3) * 2;
#pragma unroll
    for (int mf = 0; mf < 2; mf++) {
#pragma unroll
        for (int nf = 0; nf < 8; nf++) {
            const int r = row0 + mf * 16;
            const int c = col0 + nf * 8;
            const float* dd = d[mf][nf];
#pragma unroll
            for (int h = 0; h < 2; h++) {
                float v0 = dd[h * 2 + 0];
                float v1 = dd[h * 2 + 1];
                __nv_bfloat16 h0 = __float2bfloat16(v0);
                __nv_bfloat16 h1 = __float2bfloat16(v1);
                __nv_bfloat16 l0 = __float2bfloat16(v0 - __bfloat162float(h0));
                __nv_bfloat16 l1 = __float2bfloat16(v1 - __bfloat162float(h1));
                size_t o = (size_t)(r + h * 8) * ldc + c;
                *(__nv_bfloat162*)(Ch + o) = __nv_bfloat162(h0, h1);
                *(__nv_bfloat162*)(Cl + o) = __nv_bfloat162(l0, l1);
            }
        }
    }
}

// ---------------------------------------------------------------------------
// M = Wq (Wk)^T with split epilogue. Grid (8, 8).
// ---------------------------------------------------------------------------
__global__ void __launch_bounds__(NTHREADS, 2)
m_gemm(const __nv_bfloat16* __restrict__ Ah, const __nv_bfloat16* __restrict__ Al,
       const __nv_bfloat16* __restrict__ Bh, const __nv_bfloat16* __restrict__ Bl,
       __nv_bfloat16* __restrict__ Ch, __nv_bfloat16* __restrict__ Cl)
{
    extern __shared__ char smem[];
    const uint32_t sbase = smem_u32(smem);
    const int tid = threadIdx.x;
    const int wid = tid >> 5, lane = tid & 31;
    const int wm = wid & 3, wn = wid >> 2;
    const int mBase = blockIdx.y * 128;
    const int nBase = blockIdx.x * 128;

    float d[2][8][4];
#pragma unroll
    for (int i = 0; i < 2; i++)
#pragma unroll
        for (int j = 0; j < 8; j++)
#pragma unroll
            for (int e = 0; e < 4; e++) d[i][j][e] = 0.f;

    gemm_mainloop(Ah + (size_t)mBase * DDIM, Al + (size_t)mBase * DDIM,
                  Bh + (size_t)nBase * DDIM, Bl + (size_t)nBase * DDIM,
                  DDIM, DDIM, DDIM, sbase, tid, wm, wn, lane, d);

    epi_split(d, Ch, Cl, mBase, nBase, IDIM, wm, wn, lane);
}

// ---------------------------------------------------------------------------
// Merged P / V GEMM. z=0: P = k M^T (bf16 3-prod) -> split epilogue.
// z=1: vp = v Wv + bv (fp16 2-prod) -> fp16 transposed [DDIM, NTOK].
// ---------------------------------------------------------------------------
__global__ void __launch_bounds__(NTHREADS, 2)
pv_gemm(const __nv_bfloat16* __restrict__ kh, const __nv_bfloat16* __restrict__ kl,
        const __nv_bfloat16* __restrict__ Mh, const __nv_bfloat16* __restrict__ Ml,
        const __half* __restrict__ vh, const __half* __restrict__ vl,
        const __half* __restrict__ wvt,
        const float* __restrict__ bv,
        __nv_bfloat16* __restrict__ Ph, __nv_bfloat16* __restrict__ Pl,
        __half* __restrict__ vpth)
{
    extern __shared__ char smem[];
    const uint32_t sbase = smem_u32(smem);
    const int tid = threadIdx.x;
    const int wid = tid >> 5, lane = tid & 31;
    const int wm = wid & 3, wn = wid >> 2;
    const int mBase = blockIdx.y * 128;
    const int nBase = blockIdx.x * 128;
    const int z = blockIdx.z;

    float d[2][8][4];
#pragma unroll
    for (int i = 0; i < 2; i++)
#pragma unroll
        for (int j = 0; j < 8; j++)
#pragma unroll
            for (int e = 0; e < 4; e++) d[i][j][e] = 0.f;

    if (z == 0) {
        gemm_mainloop(kh + (size_t)mBase * IDIM, kl + (size_t)mBase * IDIM,
                      Mh + (size_t)nBase * IDIM, Ml + (size_t)nBase * IDIM,
                      IDIM, IDIM, IDIM, sbase, tid, wm, wn, lane, d);
        epi_split(d, Ph, Pl, mBase, nBase, IDIM, wm, wn, lane);
        return;
    }

    // ---- z=1: fp16 2-product mainloop (3 smem arrays) ----
    const __half* Ahb = vh + (size_t)mBase * IDIM;
    const __half* Alb = vl + (size_t)mBase * IDIM;
    const __half* Bb  = wvt + (size_t)nBase * IDIM;

    const int w8 = lane & 7, j8 = lane >> 3;
    int aoff[2], boff[4];
#pragma unroll
    for (int mf = 0; mf < 2; mf++)
        aoff[mf] = (wm * 32 + mf * 16 + w8 + 8 * (j8 & 1)) * ROWB + (j8 >> 1) * 16;
#pragma unroll
    for (int g = 0; g < 4; g++)
        boff[g] = (wn * 64 + g * 16 + w8 + 8 * (j8 >> 1)) * ROWB + (j8 & 1) * 16;

    const int T = IDIM / KT;

#pragma unroll
    for (int p = 0; p < 2; p++) {
        uint32_t b = sbase + p * S3_STG;
        load_arr(Ahb, IDIM, p * KT, b + 0, tid);
        load_arr(Alb, IDIM, p * KT, b + ARR_BYTES, tid);
        load_arr(Bb,  IDIM, p * KT, b + 2 * ARR_BYTES, tid);
        CP_COMMIT();
    }

    for (int t = 0; t < T; t++) {
        CP_WAIT1();
        __syncthreads();

        const uint32_t sb = sbase + (t & 1) * S3_STG;
        const uint32_t sAh = sb;
        const uint32_t sAl = sb + ARR_BYTES;
        const uint32_t sB  = sb + 2 * ARR_BYTES;

#pragma unroll
        for (int ks = 0; ks < 2; ks++) {
            const int kb = ks * 32;
            uint32_t ah[2][4], al[2][4];
            ldsm4(ah[0], sAh + aoff[0] + kb);
            ldsm4(ah[1], sAh + aoff[1] + kb);
            ldsm4(al[0], sAl + aoff[0] + kb);
            ldsm4(al[1], sAl + aoff[1] + kb);
#pragma unroll
            for (int g = 0; g < 4; g++) {
                uint32_t bh[4];
                ldsm4(bh, sB + boff[g] + kb);
#pragma unroll
                for (int sub = 0; sub < 2; sub++) {
                    const int nf = g * 2 + sub;
                    const uint32_t b0 = bh[sub * 2], b1 = bh[sub * 2 + 1];
                    mma_fp16(d[0][nf], ah[0], b0, b1);
                    mma_fp16(d[1][nf], ah[1], b0, b1);
                    mma_fp16(d[0][nf], al[0], b0, b1);
                    mma_fp16(d[1][nf], al[1], b0, b1);
                }
            }
        }

        __syncthreads();
        if (t + 2 < T) {
            const int kt = (t + 2) * KT;
            load_arr(Ahb, IDIM, kt, sb + 0, tid);
            load_arr(Alb, IDIM, kt, sb + ARR_BYTES, tid);
            load_arr(Bb,  IDIM, kt, sb + 2 * ARR_BYTES, tid);
        }
        CP_COMMIT();
    }

    // fp16 transpose epilogue via smem staging
    __syncthreads();
    __half* sh = (__half*)smem;
    const int lr0 = wm * 32 + (lane >> 2);
    const int lc0 = wn * 64 + (lane & 3) * 2;
#pragma unroll
    for (int mf = 0; mf < 2; mf++) {
#pragma unroll
        for (int nf = 0; nf < 8; nf++) {
            const float* dd = d[mf][nf];
            const int c = lc0 + nf * 8;
            const float b0v = bv[nBase + c], b1v = bv[nBase + c + 1];
#pragma unroll
            for (int h = 0; h < 2; h++) {
                const int r = lr0 + mf * 16 + h * 8;
                sh[c * TPITCH + r] = __float2half_rn(dd[h * 2 + 0] + b0v);
                sh[(c + 1) * TPITCH + r] = __float2half_rn(dd[h * 2 + 1] + b1v);
            }
        }
    }
    __syncthreads();
#pragma unroll
    for (int i = 0; i < 16; i++) {
        const int c = wid * 16 + i;
        uint2 vh2 = *(const uint2*)(sh + c * TPITCH + lane * 4);
        size_t o = (size_t)(nBase + c) * NTOK + mBase + lane * 4;
        *(uint2*)(vpth + o) = vh2;
    }
}

// ---------------------------------------------------------------------------
// Logits GEMM (bf16 3-product), fp32 out, batched. logits = q P^T.
// ---------------------------------------------------------------------------
__global__ void __launch_bounds__(NTHREADS, 2)
hmma_gemm_f32(const __nv_bfloat16* __restrict__ Ah, const __nv_bfloat16* __restrict__ Al,
              const __nv_bfloat16* __restrict__ Bh, const __nv_bfloat16* __restrict__ Bl,
              float* __restrict__ Cf,
              int K, int lda, int ldb, int ldc,
              size_t sA, size_t sB, size_t sC)
{
    extern __shared__ char smem[];
    const uint32_t sbase = smem_u32(smem);
    const int tid = threadIdx.x;
    const int wid = tid >> 5, lane = tid & 31;
    const int wm = wid & 3, wn = wid >> 2;
    const int mBase = blockIdx.y * 128;
    const int nBase = blockIdx.x * 128;
    const int z = blockIdx.z;

    float d[2][8][4];
#pragma unroll
    for (int i = 0; i < 2; i++)
#pragma unroll
        for (int j = 0; j < 8; j++)
#pragma unroll
            for (int e = 0; e < 4; e++) d[i][j][e] = 0.f;

    gemm_mainloop(Ah + z * sA + (size_t)mBase * lda, Al + z * sA + (size_t)mBase * lda,
                  Bh + z * sB + (size_t)nBase * ldb, Bl + z * sB + (size_t)nBase * ldb,
                  K, lda, ldb, sbase, tid, wm, wn, lane, d);

    const int row0 = mBase + wm * 32 + (lane >> 2);
    const int col0 = nBase + wn * 64 + (lane & 3) * 2;
    float* Cp = Cf + z * sC;

#pragma unroll
    for (int mf = 0; mf < 2; mf++) {
#pragma unroll
        for (int nf = 0; nf < 8; nf++) {
            const int r = row0 + mf * 16;
            const int c = col0 + nf * 8;
            const float* dd = d[mf][nf];
            *(float2*)(Cp + (size_t)r * ldc + c) = make_float2(dd[0], dd[1]);
            *(float2*)(Cp + (size_t)(r + 8) * ldc + c) = make_float2(dd[2], dd[3]);
        }
    }
}

// ---------------------------------------------------------------------------
// AV GEMM: fp16 1-product. D = attn @ vp (NT; B = vp^T K-major).
// ---------------------------------------------------------------------------
__global__ void __launch_bounds__(NTHREADS, 2)
av_gemm(const __half* __restrict__ Ag, const __half* __restrict__ Bg,
        float* __restrict__ Cf,
        int K, int lda, int ldb, int ldc,
        size_t sA, size_t sB, size_t sC)
{
    extern __shared__ char smem[];
    const uint32_t sbase = smem_u32(smem);
    const int tid = threadIdx.x;
    const int wid = tid >> 5, lane = tid & 31;
    const int wm = wid & 3, wn = wid >> 2;
    const int mBase = blockIdx.y * 128;
    const int nBase = blockIdx.x * 128;
    const int z = blockIdx.z;

    const __half* Ab = Ag + z * sA + (size_t)mBase * lda;
    const __half* Bb = Bg + z * sB + (size_t)nBase * ldb;

    const int w8 = lane & 7, j8 = lane >> 3;
    int aoff[2], boff[4];
#pragma unroll
    for (int mf = 0; mf < 2; mf++)
        aoff[mf] = (wm * 32 + mf * 16 + w8 + 8 * (j8 & 1)) * ROWB + (j8 >> 1) * 16;
#pragma unroll
    for (int g = 0; g < 4; g++)
        boff[g] = (wn * 64 + g * 16 + w8 + 8 * (j8 >> 1)) * ROWB + (j8 & 1) * 16;

    float d[2][8][4];
#pragma unroll
    for (int i = 0; i < 2; i++)
#pragma unroll
        for (int j = 0; j < 8; j++)
#pragma unroll
            for (int e = 0; e < 4; e++) d[i][j][e] = 0.f;

    const int T = K / KT;

#pragma unroll
    for (int p = 0; p < 2; p++) {
        uint32_t b = sbase + p * S2_STG;
        load_arr(Ab, lda, p * KT, b + 0, tid);
        load_arr(Bb, ldb, p * KT, b + ARR_BYTES, tid);
        CP_COMMIT();
    }

    for (int t = 0; t < T; t++) {
        CP_WAIT1();
        __syncthreads();

        const uint32_t sb = sbase + (t & 1) * S2_STG;
        const uint32_t sA_ = sb;
        const uint32_t sB_ = sb + ARR_BYTES;

#pragma unroll
        for (int ks = 0; ks < 2; ks++) {
            const int kb = ks * 32;
            uint32_t a[2][4];
            ldsm4(a[0], sA_ + aoff[0] + kb);
            ldsm4(a[1], sA_ + aoff[1] + kb);
#pragma unroll
            for (int g = 0; g < 4; g++) {
                uint32_t bh[4];
                ldsm4(bh, sB_ + boff[g] + kb);
#pragma unroll
                for (int sub = 0; sub < 2; sub++) {
                    const int nf = g * 2 + sub;
                    const uint32_t b0 = bh[sub * 2], b1 = bh[sub * 2 + 1];
                    mma_fp16(d[0][nf], a[0], b0, b1);
                    mma_fp16(d[1][nf], a[1], b0, b1);
                }
            }
        }

        __syncthreads();
        if (t + 2 < T) {
            const int kt = (t + 2) * KT;
            load_arr(Ab, lda, kt, sb + 0, tid);
            load_arr(Bb, ldb, kt, sb + ARR_BYTES, tid);
        }
        CP_COMMIT();
    }

    const int row0 = mBase + wm * 32 + (lane >> 2);
    const int col0 = nBase + wn * 64 + (lane & 3) * 2;
    float* Cp = Cf + z * sC;

#pragma unroll
    for (int mf = 0; mf < 2; mf++) {
#pragma unroll
        for (int nf = 0; nf < 8; nf++) {
            const int r = row0 + mf * 16;
            const int c = col0 + nf * 8;
            const float* dd = d[mf][nf];
            *(float2*)(Cp + (size_t)r * ldc + c) = make_float2(dd[0], dd[1]);
            *(float2*)(Cp + (size_t)(r + 8) * ldc + c) = make_float2(dd[2], dd[3]);
        }
    }
}

// ---------------------------------------------------------------------------
// 5-way fp32 split: slices 0,1,3,4 -> bf16 hi/lo; slice 2 (v) -> fp16 hi/lo
// ---------------------------------------------------------------------------
__global__ void __launch_bounds__(256)
split5(const float4* x0, __nv_bfloat16* h0, __nv_bfloat16* l0, int n0,
       const float4* x1, __nv_bfloat16* h1, __nv_bfloat16* l1, int n1,
       const float4* x2, __half* h2, __half* l2, int n2,
       const float4* x3, __nv_bfloat16* h3, __nv_bfloat16* l3, int n3,
       const float4* x4, __nv_bfloat16* h4, __nv_bfloat16* l4, int n4v)
{
    int i = blockIdx.x * 256 + threadIdx.x;
    int s = blockIdx.y;

    if (s == 2) {
        if (i >= n2) return;
        float4 v = x2[i];
        float vv[4] = {v.x, v.y, v.z, v.w};
        __half hh[4], ll[4];
#pragma unroll
        for (int j = 0; j < 4; j++) {
            __half h = __float2half_rn(vv[j]);
            hh[j] = h;
            ll[j] = __float2half_rn(vv[j] - __half2float(h));
        }
        ((uint2*)h2)[i] = *(uint2*)hh;
        ((uint2*)l2)[i] = *(uint2*)ll;
        return;
    }

    const float4* x; __nv_bfloat16* hi; __nv_bfloat16* lo; int n;
    switch (s) {
        case 0: x = x0; hi = h0; lo = l0; n = n0; break;
        case 1: x = x1; hi = h1; lo = l1; n = n1; break;
        case 3: x = x3; hi = h3; lo = l3; n = n3; break;
        default: x = x4; hi = h4; lo = l4; n = n4v; break;
    }
    if (i >= n) return;

    float4 v = x[i];
    float vv[4] = {v.x, v.y, v.z, v.w};
    __nv_bfloat16 hh[4], ll[4];
#pragma unroll
    for (int j = 0; j < 4; j++) {
        __nv_bfloat16 h = __float2bfloat16(vv[j]);
        hh[j] = h;
        ll[j] = __float2bfloat16(vv[j] - __bfloat162float(h));
    }
    ((uint2*)hi)[i] = *(uint2*)hh;
    ((uint2*)lo)[i] = *(uint2*)ll;
}

// W[K,N] fp32 -> WT [N,K] fp16 (round only; for Wv)
__global__ void __launch_bounds__(256)
transpose_half(const float* __restrict__ W, __half* __restrict__ T,
               int rows, int cols)
{
    __shared__ float tile[32][33];
    int bx = blockIdx.x * 32;
    int by = blockIdx.y * 32;
    int tx = threadIdx.x & 31;
    int ty = threadIdx.x >> 5;
#pragma unroll
    for (int i = ty; i < 32; i += 8)
        tile[i][tx] = W[(size_t)(by + i) * cols + bx + tx];
    __syncthreads();
#pragma unroll
    for (int i = ty; i < 32; i += 8)
        T[(size_t)(bx + i) * rows + by + tx] = __float2half_rn(tile[tx][i]);
}

// ---------------------------------------------------------------------------
// uv_prep / uv_main (rank-1 bias terms), unchanged from R13
// ---------------------------------------------------------------------------
__global__ void __launch_bounds__(256)
uv_prep(const float* __restrict__ wq, const float* __restrict__ wk,
        const float* __restrict__ bq, const float* __restrict__ bk,
        float* __restrict__ w1, float* __restrict__ w2, float* __restrict__ cOut)
{
    int wid = threadIdx.x >> 5, lane = threadIdx.x & 31;
    int s = blockIdx.y;
    int row = blockIdx.x * 8 + wid;
    const float* W = s ? wk : wq;
    const float* b = s ? bq : bk;

    float acc = 0.f;
#pragma unroll
    for (int j = 0; j < 32; j++)
        acc += W[(size_t)row * DDIM + lane + 32 * j] * b[lane + 32 * j];
#pragma unroll
    for (int o = 16; o; o >>= 1) acc += __shfl_xor_sync(0xffffffffu, acc, o);
    if (lane == 0) (s ? w2 : w1)[row] = acc;

    if (blockIdx.x == 0 && s == 0 && wid == 0) {
        float cc = 0.f;
#pragma unroll
        for (int j = 0; j < 32; j++)
            cc += bq[lane + 32 * j] * bk[lane + 32 * j];
#pragma unroll
        for (int o = 16; o; o >>= 1) cc += __shfl_xor_sync(0xffffffffu, cc, o);
        if (lane == 0) cOut[0] = cc;
    }
}

__global__ void __launch_bounds__(256)
uv_main(const float* __restrict__ q, const float* __restrict__ k,
        const float* __restrict__ w1, const float* __restrict__ w2,
        const float* __restrict__ cIn,
        float* __restrict__ u, float* __restrict__ v, float scale)
{
    int wid = threadIdx.x >> 5, lane = threadIdx.x & 31;
    int s = blockIdx.y;
    int row = blockIdx.x * 8 + wid;
    const float* src = s ? k : q;
    const float* w = s ? w2 : w1;

    float acc = 0.f;
#pragma unroll
    for (int j = 0; j < 32; j++)
        acc += src[(size_t)row * IDIM + lane + 32 * j] * w[lane + 32 * j];
#pragma unroll
    for (int o = 16; o; o >>= 1) acc += __shfl_xor_sync(0xffffffffu, acc, o);
    if (lane == 0) {
        if (s == 0) u[row] = (acc + cIn[0]) * scale;
        else        v[row] = acc * scale;
    }
}

// ---------------------------------------------------------------------------
// softmax: x = lg*scale + mask + u[row] + v[col]; -> fp16 attn (hi only)
// ---------------------------------------------------------------------------
__global__ void __launch_bounds__(256)
softmax_split(const float* __restrict__ logits, const float* __restrict__ mask,
              const float* __restrict__ u, const float* __restrict__ vv,
              __half* __restrict__ ah, float scale)
{
    __shared__ float red[8];
    __shared__ float bval;

    size_t row = blockIdx.x;
    int q = (int)(row & (SDIM - 1));
    const float* rp = logits + row * (size_t)SDIM;
    const float* mp = mask + (size_t)q * SDIM;
    const float* vr = vv + (row >> 11) * SDIM;
    const float uval = u[row];
    int t = threadIdx.x;

    float4 a = ((const float4*)rp)[t];
    float4 b = ((const float4*)rp)[t + 256];
    float4 ma = ((const float4*)mp)[t];
    float4 mb = ((const float4*)mp)[t + 256];
    float4 va = ((const float4*)vr)[t];
    float4 vb = ((const float4*)vr)[t + 256];
    float x[8];
    x[0] = fmaf(a.x, scale, ma.x + uval + va.x);
    x[1] = fmaf(a.y, scale, ma.y + uval + va.y);
    x[2] = fmaf(a.z, scale, ma.z + uval + va.z);
    x[3] = fmaf(a.w, scale, ma.w + uval + va.w);
    x[4] = fmaf(b.x, scale, mb.x + uval + vb.x);
    x[5] = fmaf(b.y, scale, mb.y + uval + vb.y);
    x[6] = fmaf(b.z, scale, mb.z + uval + vb.z);
    x[7] = fmaf(b.w, scale, mb.w + uval + vb.w);

    float mx = x[0];
#pragma unroll
    for (int i = 1; i < 8; i++) mx = fmaxf(mx, x[i]);
#pragma unroll
    for (int o = 16; o; o >>= 1) mx = fmaxf(mx, __shfl_xor_sync(0xffffffffu, mx, o));
    if ((t & 31) == 0) red[t >> 5] = mx;
    __syncthreads();
    if (t == 0) {
        float m = red[0];
#pragma unroll
        for (int i = 1; i < 8; i++) m = fmaxf(m, red[i]);
        bval = m;
    }
    __syncthreads();
    mx = bval;

    float s = 0.f;
#pragma unroll
    for (int i = 0; i < 8; i++) { x[i] = __expf(x[i] - mx); s += x[i]; }
#pragma unroll
    for (int o = 16; o; o >>= 1) s += __shfl_xor_sync(0xffffffffu, s, o);
    if ((t & 31) == 0) red[t >> 5] = s;
    __syncthreads();
    if (t == 0) {
        float ss = 0.f;
#pragma unroll
        for (int i = 0; i < 8; i++) ss += red[i];
        bval = 1.f / ss;
    }
    __syncthreads();
    float inv = bval;

    __half2* ah2 = (__half2*)(ah + row * (size_t)SDIM);
#pragma unroll
    for (int half = 0; half < 2; half++) {
#pragma unroll
        for (int p = 0; p < 2; p++) {
            float p0 = x[half * 4 + p * 2 + 0] * inv;
            float p1 = x[half * 4 + p * 2 + 1] * inv;
            int idx = half * 512 + t * 2 + p;
            ah2[idx] = __halves2half2(__float2half_rn(p0), __float2half_rn(p1));
        }
    }
}

// ---------------------------------------------------------------------------
extern "C" void kernel_launch(void* const* d_in, const int* in_sizes, int n_in,
                              void* d_out, int out_size)
{
    const float* q    = (const float*)d_in[0];
    const float* k    = (const float*)d_in[1];
    const float* v    = (const float*)d_in[2];
    const float* mask = (const float*)d_in[3];
    const float* wq   = (const float*)d_in[4];
    const float* bq   = (const float*)d_in[5];
    const float* wk   = (const float*)d_in[6];
    const float* bk   = (const float*)d_in[7];
    const float* wv   = (const float*)d_in[8];
    const float* bv   = (const float*)d_in[9];
    float* out = (float*)d_out;

#define SYM(p, s) do { void* _t; cudaGetSymbolAddress(&_t, s); p = (decltype(p))_t; } while (0)
    __nv_bfloat16 *qh, *ql, *kh, *kl;
    __half *vh, *vl, *wvt, *vpth, *ah;
    __nv_bfloat16 *wqh, *wql, *wkh, *wkl;
    __nv_bfloat16 *Mh, *Ml, *Ph, *Pl;
    float *lg, *w1, *w2, *cptr, *u, *vvp;
    SYM(qh, g_qh); SYM(ql, g_ql); SYM(kh, g_kh); SYM(kl, g_kl);
    SYM(vh, g_vh); SYM(vl, g_vl);
    SYM(wqh, g_wqh); SYM(wql, g_wql); SYM(wkh, g_wkh); SYM(wkl, g_wkl);
    SYM(wvt, g_wvt);
    SYM(Mh, g_Mh); SYM(Ml, g_Ml); SYM(Ph, g_Ph); SYM(Pl, g_Pl);
    SYM(vpth, g_vpth); SYM(ah, g_ah);
    SYM(lg, g_logits);
    SYM(w1, g_w1); SYM(w2, g_w2); SYM(cptr, g_c); SYM(u, g_u); SYM(vvp, g_v);
#undef SYM

    cudaFuncSetAttribute(m_gemm, cudaFuncAttributeMaxDynamicSharedMemorySize, SMEM_TOTAL);
    cudaFuncSetAttribute(pv_gemm, cudaFuncAttributeMaxDynamicSharedMemorySize, SMEM_TOTAL);
    cudaFuncSetAttribute(hmma_gemm_f32, cudaFuncAttributeMaxDynamicSharedMemorySize, SMEM_TOTAL);
    cudaFuncSetAttribute(av_gemm, cudaFuncAttributeMaxDynamicSharedMemorySize, AV_SMEM_TOTAL);

    const int n4_act = NTOK * IDIM / 4;
    const int n4_w = IDIM * DDIM / 4;
    const float scale = 0.03125f;

    // 1: split q,k (bf16), v (fp16), Wq,Wk (bf16)
    split5<<<dim3(n4_act / 256, 5), 256>>>(
        (const float4*)q, qh, ql, n4_act,
        (const float4*)k, kh, kl, n4_act,
        (const float4*)v, vh, vl, n4_act,
        (const float4*)wq, wqh, wql, n4_w,
        (const float4*)wk, wkh, wkl, n4_w);

    // 2: transpose Wv -> fp16
    transpose_half<<<dim3(IDIM / 32, IDIM / 32), 256>>>(wv, wvt, IDIM, DDIM);

    // 3: M = Wq Wk^T (bf16 3-prod, split epilogue)
    m_gemm<<<dim3(8, 8), NTHREADS, SMEM_TOTAL>>>(wqh, wql, wkh, wkl, Mh, Ml);

    // 4: P = k M^T (z=0, bf16) and vp^T (z=1, fp16 2-prod)  <- ncu slot
    pv_gemm<<<dim3(IDIM / 128, NTOK / 128, 2), NTHREADS, SMEM_TOTAL>>>(
        kh, kl, Mh, Ml, vh, vl, wvt, bv, Ph, Pl, vpth);

    // 5-6: rank-1 bias terms
    uv_prep<<<dim3(IDIM / 8, 2), 256>>>(wq, wk, bq, bk, w1, w2, cptr);
    uv_main<<<dim3(NTOK / 8, 2), 256>>>(q, k, w1, w2, cptr, u, vvp, scale);

    // 7: logits = q P^T (batched, bf16 3-prod)
    dim3 gl(SDIM / 128, SDIM / 128, BDIM);
    hmma_gemm_f32<<<gl, NTHREADS, SMEM_TOTAL>>>(qh, ql, Ph, Pl, lg,
                                                IDIM, IDIM, IDIM, SDIM,
                                                (size_t)SDIM * IDIM, (size_t)SDIM * IDIM,
                                                (size_t)SDIM * SDIM);

    // 8: softmax (u/v/c folded) -> fp16 attn
    softmax_split<<<BDIM * SDIM, 256>>>(lg, mask, u, vvp, ah, scale);

    // 9: out = attn @ vp (fp16 1-product)
    dim3 ga(DDIM / 128, SDIM / 128, BDIM);
    av_gemm<<<ga, NTHREADS, AV_SMEM_TOTAL>>>(ah, vpth, out,
                                             SDIM, SDIM, NTOK, DDIM,
                                             (size_t)SDIM * SDIM, (size_t)SDIM,
                                             (size_t)SDIM * DDIM);
}

// round 15
// speedup vs baseline: 1.7743x; 1.2314x over previous
#include <cuda_runtime.h>
#include <cuda_bf16.h>
#include <cuda_fp16.h>
#include <cstdint>

#define BDIM 4
#define SDIM 2048
#define IDIM 1024
#define DDIM 1024
#define NTOK (BDIM * SDIM)   // 8192

// ---------------------------------------------------------------------------
// Device scratch (allocation-free rule)
// ---------------------------------------------------------------------------
__device__ __align__(128) __half g_qh[(size_t)NTOK * IDIM];
__device__ __align__(128) __half g_ql[(size_t)NTOK * IDIM];
__device__ __align__(128) __half g_kh[(size_t)NTOK * IDIM];
__device__ __align__(128) __half g_kl[(size_t)NTOK * IDIM];
__device__ __align__(128) __half g_vh[(size_t)NTOK * IDIM];
__device__ __align__(128) __half g_vl[(size_t)NTOK * IDIM];
__device__ __align__(128) __nv_bfloat16 g_wqh[(size_t)IDIM * DDIM];
__device__ __align__(128) __nv_bfloat16 g_wql[(size_t)IDIM * DDIM];
__device__ __align__(128) __nv_bfloat16 g_wkh[(size_t)IDIM * DDIM];
__device__ __align__(128) __nv_bfloat16 g_wkl[(size_t)IDIM * DDIM];
__device__ __align__(128) __half g_wvt[(size_t)DDIM * IDIM];       // fp16 Wv^T
__device__ __align__(128) __half g_M[(size_t)IDIM * IDIM];         // M = Wq Wk^T fp16
__device__ __align__(128) __half g_P[(size_t)NTOK * IDIM];         // P = k M^T fp16
__device__ __align__(128) __half g_vpth[(size_t)DDIM * NTOK];      // vp^T fp16
__device__ __align__(128) float g_logits[(size_t)BDIM * SDIM * SDIM];
__device__ __align__(128) __half g_ah[(size_t)BDIM * SDIM * SDIM]; // attn fp16
__device__ float g_w1[IDIM];
__device__ float g_w2[IDIM];
__device__ float g_c[1];
__device__ float g_u[NTOK];
__device__ float g_v[NTOK];

// ---------------------------------------------------------------------------
// PTX helpers
// ---------------------------------------------------------------------------
__device__ __forceinline__ uint32_t smem_u32(const void* p) {
    uint32_t a;
    asm("{ .reg .u64 t; cvta.to.shared.u64 t, %1; cvt.u32.u64 %0, t; }"
        : "=r"(a) : "l"(p));
    return a;
}

__device__ __forceinline__ void cp16(uint32_t d, const void* g) {
    asm volatile("cp.async.cg.shared.global [%0], [%1], 16;" :: "r"(d), "l"(g) : "memory");
}
#define CP_COMMIT() asm volatile("cp.async.commit_group;" ::: "memory")
#define CP_WAIT1()  asm volatile("cp.async.wait_group 1;" ::: "memory")

__device__ __forceinline__ void ldsm4(uint32_t* r, uint32_t addr) {
    asm volatile("ldmatrix.sync.aligned.m8n8.x4.shared.b16 {%0,%1,%2,%3}, [%4];"
        : "=r"(r[0]), "=r"(r[1]), "=r"(r[2]), "=r"(r[3]) : "r"(addr));
}

__device__ __forceinline__ void mma_bf16(float* d, const uint32_t* a,
                                         uint32_t b0, uint32_t b1) {
    asm volatile(
        "mma.sync.aligned.m16n8k16.row.col.f32.bf16.bf16.f32 "
        "{%0,%1,%2,%3}, {%4,%5,%6,%7}, {%8,%9}, {%0,%1,%2,%3};"
        : "+f"(d[0]), "+f"(d[1]), "+f"(d[2]), "+f"(d[3])
        : "r"(a[0]), "r"(a[1]), "r"(a[2]), "r"(a[3]), "r"(b0), "r"(b1));
}

__device__ __forceinline__ void mma_fp16(float* d, const uint32_t* a,
                                         uint32_t b0, uint32_t b1) {
    asm volatile(
        "mma.sync.aligned.m16n8k16.row.col.f32.f16.f16.f32 "
        "{%0,%1,%2,%3}, {%4,%5,%6,%7}, {%8,%9}, {%0,%1,%2,%3};"
        : "+f"(d[0]), "+f"(d[1]), "+f"(d[2]), "+f"(d[3])
        : "r"(a[0]), "r"(a[1]), "r"(a[2]), "r"(a[3]), "r"(b0), "r"(b1));
}

// SMEM geometry: 128 rows x 80B pitch arrays, KT=32
#define KT 32
#define ROWB 80
#define ARR_BYTES (128 * ROWB)
#define STG4 (4 * ARR_BYTES)
#define SMEM4_TOTAL (2 * STG4)      // 81920 (m_gemm, bf16 3-prod)
#define STG3 (3 * ARR_BYTES)
#define SMEM3_TOTAL (2 * STG3)      // 61440 (2-prod fp16 GEMMs)
#define STG2 (2 * ARR_BYTES)
#define SMEM2_TOTAL (2 * STG2)      // 40960 (AV 1-prod)

#define NTHREADS 256
#define TPITCH 132

__device__ __forceinline__ void load_arr(const void* __restrict__ Gv,
                                         int ldg, int kt, uint32_t dst, int tid) {
    const __half* G = (const __half*)Gv;
#pragma unroll
    for (int i = 0; i < 2; i++) {
        int idx = tid + i * NTHREADS;
        int row = idx >> 2;
        int c = idx & 3;
        cp16(dst + row * ROWB + c * 16, (const void*)(G + (size_t)row * ldg + kt + c * 8));
    }
}

// ---------------------------------------------------------------------------
// fp16 2-product mainloop: D[128,128] += (Ah+Al)[128,K] * B[128,K]^T (NT).
// 3 smem arrays per stage.
// ---------------------------------------------------------------------------
__device__ __forceinline__ void gemm2p_mainloop(
    const __half* __restrict__ Ahb, const __half* __restrict__ Alb,
    const __half* __restrict__ Bb,
    int K, int lda, int ldb,
    uint32_t sbase, int tid, int wm, int wn, int lane,
    float d[2][8][4])
{
    const int w8 = lane & 7, j8 = lane >> 3;
    int aoff[2], boff[4];
#pragma unroll
    for (int mf = 0; mf < 2; mf++)
        aoff[mf] = (wm * 32 + mf * 16 + w8 + 8 * (j8 & 1)) * ROWB + (j8 >> 1) * 16;
#pragma unroll
    for (int g = 0; g < 4; g++)
        boff[g] = (wn * 64 + g * 16 + w8 + 8 * (j8 >> 1)) * ROWB + (j8 & 1) * 16;

    const int T = K / KT;

#pragma unroll
    for (int p = 0; p < 2; p++) {
        uint32_t b = sbase + p * STG3;
        load_arr(Ahb, lda, p * KT, b + 0, tid);
        load_arr(Alb, lda, p * KT, b + ARR_BYTES, tid);
        load_arr(Bb,  ldb, p * KT, b + 2 * ARR_BYTES, tid);
        CP_COMMIT();
    }

    for (int t = 0; t < T; t++) {
        CP_WAIT1();
        __syncthreads();

        const uint32_t sb = sbase + (t & 1) * STG3;
        const uint32_t sAh = sb;
        const uint32_t sAl = sb + ARR_BYTES;
        const uint32_t sB  = sb + 2 * ARR_BYTES;

#pragma unroll
        for (int ks = 0; ks < 2; ks++) {
            const int kb = ks * 32;
            uint32_t ah[2][4], al[2][4];
            ldsm4(ah[0], sAh + aoff[0] + kb);
            ldsm4(ah[1], sAh + aoff[1] + kb);
            ldsm4(al[0], sAl + aoff[0] + kb);
            ldsm4(al[1], sAl + aoff[1] + kb);
#pragma unroll
            for (int g = 0; g < 4; g++) {
                uint32_t bh[4];
                ldsm4(bh, sB + boff[g] + kb);
#pragma unroll
                for (int sub = 0; sub < 2; sub++) {
                    const int nf = g * 2 + sub;
                    const uint32_t b0 = bh[sub * 2], b1 = bh[sub * 2 + 1];
                    mma_fp16(d[0][nf], ah[0], b0, b1);
                    mma_fp16(d[1][nf], ah[1], b0, b1);
                    mma_fp16(d[0][nf], al[0], b0, b1);
                    mma_fp16(d[1][nf], al[1], b0, b1);
                }
            }
        }

        __syncthreads();
        if (t + 2 < T) {
            const int kt = (t + 2) * KT;
            load_arr(Ahb, lda, kt, sb + 0, tid);
            load_arr(Alb, lda, kt, sb + ARR_BYTES, tid);
            load_arr(Bb,  ldb, kt, sb + 2 * ARR_BYTES, tid);
        }
        CP_COMMIT();
    }
}

// ---------------------------------------------------------------------------
// m_gemm: M = Wq Wk^T (bf16 3-product) -> single fp16. Grid (8, 8).
// ---------------------------------------------------------------------------
__global__ void __launch_bounds__(NTHREADS, 2)
m_gemm(const __nv_bfloat16* __restrict__ Ah, const __nv_bfloat16* __restrict__ Al,
       const __nv_bfloat16* __restrict__ Bh, const __nv_bfloat16* __restrict__ Bl,
       __half* __restrict__ Mo)
{
    extern __shared__ char smem[];
    const uint32_t sbase = smem_u32(smem);
    const int tid = threadIdx.x;
    const int wid = tid >> 5, lane = tid & 31;
    const int wm = wid & 3, wn = wid >> 2;
    const int mBase = blockIdx.y * 128;
    const int nBase = blockIdx.x * 128;

    const __nv_bfloat16* Ahb = Ah + (size_t)mBase * DDIM;
    const __nv_bfloat16* Alb = Al + (size_t)mBase * DDIM;
    const __nv_bfloat16* Bhb = Bh + (size_t)nBase * DDIM;
    const __nv_bfloat16* Blb = Bl + (size_t)nBase * DDIM;

    const int w8 = lane & 7, j8 = lane >> 3;
    int aoff[2], boff[4];
#pragma unroll
    for (int mf = 0; mf < 2; mf++)
        aoff[mf] = (wm * 32 + mf * 16 + w8 + 8 * (j8 & 1)) * ROWB + (j8 >> 1) * 16;
#pragma unroll
    for (int g = 0; g < 4; g++)
        boff[g] = (wn * 64 + g * 16 + w8 + 8 * (j8 >> 1)) * ROWB + (j8 & 1) * 16;

    float d[2][8][4];
#pragma unroll
    for (int i = 0; i < 2; i++)
#pragma unroll
        for (int j = 0; j < 8; j++)
#pragma unroll
            for (int e = 0; e < 4; e++) d[i][j][e] = 0.f;

    const int T = DDIM / KT;

#pragma unroll
    for (int p = 0; p < 2; p++) {
        uint32_t b = sbase + p * STG4;
        load_arr(Ahb, DDIM, p * KT, b + 0, tid);
        load_arr(Alb, DDIM, p * KT, b + ARR_BYTES, tid);
        load_arr(Bhb, DDIM, p * KT, b + 2 * ARR_BYTES, tid);
        load_arr(Blb, DDIM, p * KT, b + 3 * ARR_BYTES, tid);
        CP_COMMIT();
    }

    for (int t = 0; t < T; t++) {
        CP_WAIT1();
        __syncthreads();

        const uint32_t sb = sbase + (t & 1) * STG4;
        const uint32_t sAh = sb, sAl = sb + ARR_BYTES;
        const uint32_t sBh = sb + 2 * ARR_BYTES, sBl = sb + 3 * ARR_BYTES;

#pragma unroll
        for (int ks = 0; ks < 2; ks++) {
            const int kb = ks * 32;
            uint32_t ah[2][4], al[2][4];
            ldsm4(ah[0], sAh + aoff[0] + kb);
            ldsm4(ah[1], sAh + aoff[1] + kb);
            ldsm4(al[0], sAl + aoff[0] + kb);
            ldsm4(al[1], sAl + aoff[1] + kb);
#pragma unroll
            for (int g = 0; g < 4; g++) {
                uint32_t bh[4], bl[4];
                ldsm4(bh, sBh + boff[g] + kb);
                ldsm4(bl, sBl + boff[g] + kb);
#pragma unroll
                for (int sub = 0; sub < 2; sub++) {
                    const int nf = g * 2 + sub;
                    const uint32_t bh0 = bh[sub * 2], bh1 = bh[sub * 2 + 1];
                    const uint32_t bl0 = bl[sub * 2], bl1 = bl[sub * 2 + 1];
                    mma_bf16(d[0][nf], ah[0], bh0, bh1);
                    mma_bf16(d[1][nf], ah[1], bh0, bh1);
                    mma_bf16(d[0][nf], ah[0], bl0, bl1);
                    mma_bf16(d[1][nf], ah[1], bl0, bl1);
                    mma_bf16(d[0][nf], al[0], bh0, bh1);
                    mma_bf16(d[1][nf], al[1], bh0, bh1);
                }
            }
        }

        __syncthreads();
        if (t + 2 < T) {
            const int kt = (t + 2) * KT;
            load_arr(Ahb, DDIM, kt, sb + 0, tid);
            load_arr(Alb, DDIM, kt, sb + ARR_BYTES, tid);
            load_arr(Bhb, DDIM, kt, sb + 2 * ARR_BYTES, tid);
            load_arr(Blb, DDIM, kt, sb + 3 * ARR_BYTES, tid);
        }
        CP_COMMIT();
    }

    const int row0 = mBase + wm * 32 + (lane >> 2);
    const int col0 = nBase + wn * 64 + (lane & 3) * 2;
#pragma unroll
    for (int mf = 0; mf < 2; mf++) {
#pragma unroll
        for (int nf = 0; nf < 8; nf++) {
            const int r = row0 + mf * 16;
            const int c = col0 + nf * 8;
            const float* dd = d[mf][nf];
#pragma unroll
            for (int h = 0; h < 2; h++) {
                size_t o = (size_t)(r + h * 8) * IDIM + c;
                *(__half2*)(Mo + o) = __halves2half2(
                    __float2half_rn(dd[h * 2 + 0]), __float2half_rn(dd[h * 2 + 1]));
            }
        }
    }
}

// ---------------------------------------------------------------------------
// pv_gemm (fp16 2-product). z=0: P = k M^T -> fp16 row-major.
// z=1: vp = v Wv + bv -> fp16 transposed [DDIM, NTOK].
// ---------------------------------------------------------------------------
__global__ void __launch_bounds__(NTHREADS, 2)
pv_gemm(const __half* __restrict__ kh, const __half* __restrict__ kl,
        const __half* __restrict__ M,
        const __half* __restrict__ vh, const __half* __restrict__ vl,
        const __half* __restrict__ wvt,
        const float* __restrict__ bv,
        __half* __restrict__ P, __half* __restrict__ vpth)
{
    extern __shared__ char smem[];
    const uint32_t sbase = smem_u32(smem);
    const int tid = threadIdx.x;
    const int wid = tid >> 5, lane = tid & 31;
    const int wm = wid & 3, wn = wid >> 2;
    const int mBase = blockIdx.y * 128;
    const int nBase = blockIdx.x * 128;
    const int z = blockIdx.z;

    const __half* Ah = z ? vh : kh;
    const __half* Al = z ? vl : kl;
    const __half* B  = z ? wvt : M;

    float d[2][8][4];
#pragma unroll
    for (int i = 0; i < 2; i++)
#pragma unroll
        for (int j = 0; j < 8; j++)
#pragma unroll
            for (int e = 0; e < 4; e++) d[i][j][e] = 0.f;

    gemm2p_mainloop(Ah + (size_t)mBase * IDIM, Al + (size_t)mBase * IDIM,
                    B + (size_t)nBase * IDIM,
                    IDIM, IDIM, IDIM, sbase, tid, wm, wn, lane, d);

    if (z == 0) {
        const int row0 = mBase + wm * 32 + (lane >> 2);
        const int col0 = nBase + wn * 64 + (lane & 3) * 2;
#pragma unroll
        for (int mf = 0; mf < 2; mf++) {
#pragma unroll
            for (int nf = 0; nf < 8; nf++) {
                const int r = row0 + mf * 16;
                const int c = col0 + nf * 8;
                const float* dd = d[mf][nf];
#pragma unroll
                for (int h = 0; h < 2; h++) {
                    size_t o = (size_t)(r + h * 8) * IDIM + c;
                    *(__half2*)(P + o) = __halves2half2(
                        __float2half_rn(dd[h * 2 + 0]), __float2half_rn(dd[h * 2 + 1]));
                }
            }
        }
    } else {
        __syncthreads();
        __half* sh = (__half*)smem;
        const int lr0 = wm * 32 + (lane >> 2);
        const int lc0 = wn * 64 + (lane & 3) * 2;
#pragma unroll
        for (int mf = 0; mf < 2; mf++) {
#pragma unroll
            for (int nf = 0; nf < 8; nf++) {
                const float* dd = d[mf][nf];
                const int c = lc0 + nf * 8;
                const float b0v = bv[nBase + c], b1v = bv[nBase + c + 1];
#pragma unroll
                for (int h = 0; h < 2; h++) {
                    const int r = lr0 + mf * 16 + h * 8;
                    sh[c * TPITCH + r] = __float2half_rn(dd[h * 2 + 0] + b0v);
                    sh[(c + 1) * TPITCH + r] = __float2half_rn(dd[h * 2 + 1] + b1v);
                }
            }
        }
        __syncthreads();
#pragma unroll
        for (int i = 0; i < 16; i++) {
            const int c = wid * 16 + i;
            uint2 vh2 = *(const uint2*)(sh + c * TPITCH + lane * 4);
            size_t o = (size_t)(nBase + c) * NTOK + mBase + lane * 4;
            *(uint2*)(vpth + o) = vh2;
        }
    }
}

// ---------------------------------------------------------------------------
// Logits GEMM (fp16 2-product): logits = (qh+ql) P^T, fp32 out, batched.
// ---------------------------------------------------------------------------
__global__ void __launch_bounds__(NTHREADS, 2)
logits_gemm(const __half* __restrict__ Ah, const __half* __restrict__ Al,
            const __half* __restrict__ B, float* __restrict__ Cf,
            int K, int lda, int ldb, int ldc,
            size_t sA, size_t sB, size_t sC)
{
    extern __shared__ char smem[];
    const uint32_t sbase = smem_u32(smem);
    const int tid = threadIdx.x;
    const int wid = tid >> 5, lane = tid & 31;
    const int wm = wid & 3, wn = wid >> 2;
    const int mBase = blockIdx.y * 128;
    const int nBase = blockIdx.x * 128;
    const int z = blockIdx.z;

    float d[2][8][4];
#pragma unroll
    for (int i = 0; i < 2; i++)
#pragma unroll
        for (int j = 0; j < 8; j++)
#pragma unroll
            for (int e = 0; e < 4; e++) d[i][j][e] = 0.f;

    gemm2p_mainloop(Ah + z * sA + (size_t)mBase * lda,
                    Al + z * sA + (size_t)mBase * lda,
                    B + z * sB + (size_t)nBase * ldb,
                    K, lda, ldb, sbase, tid, wm, wn, lane, d);

    const int row0 = mBase + wm * 32 + (lane >> 2);
    const int col0 = nBase + wn * 64 + (lane & 3) * 2;
    float* Cp = Cf + z * sC;

#pragma unroll
    for (int mf = 0; mf < 2; mf++) {
#pragma unroll
        for (int nf = 0; nf < 8; nf++) {
            const int r = row0 + mf * 16;
            const int c = col0 + nf * 8;
            const float* dd = d[mf][nf];
            *(float2*)(Cp + (size_t)r * ldc + c) = make_float2(dd[0], dd[1]);
            *(float2*)(Cp + (size_t)(r + 8) * ldc + c) = make_float2(dd[2], dd[3]);
        }
    }
}

// ---------------------------------------------------------------------------
// AV GEMM: fp16 1-product. D = attn @ vp (NT; B = vp^T K-major).
// ---------------------------------------------------------------------------
__global__ void __launch_bounds__(NTHREADS, 2)
av_gemm(const __half* __restrict__ Ag, const __half* __restrict__ Bg,
        float* __restrict__ Cf,
        int K, int lda, int ldb, int ldc,
        size_t sA, size_t sB, size_t sC)
{
    extern __shared__ char smem[];
    const uint32_t sbase = smem_u32(smem);
    const int tid = threadIdx.x;
    const int wid = tid >> 5, lane = tid & 31;
    const int wm = wid & 3, wn = wid >> 2;
    const int mBase = blockIdx.y * 128;
    const int nBase = blockIdx.x * 128;
    const int z = blockIdx.z;

    const __half* Ab = Ag + z * sA + (size_t)mBase * lda;
    const __half* Bb = Bg + z * sB + (size_t)nBase * ldb;

    const int w8 = lane & 7, j8 = lane >> 3;
    int aoff[2], boff[4];
#pragma unroll
    for (int mf = 0; mf < 2; mf++)
        aoff[mf] = (wm * 32 + mf * 16 + w8 + 8 * (j8 & 1)) * ROWB + (j8 >> 1) * 16;
#pragma unroll
    for (int g = 0; g < 4; g++)
        boff[g] = (wn * 64 + g * 16 + w8 + 8 * (j8 >> 1)) * ROWB + (j8 & 1) * 16;

    float d[2][8][4];
#pragma unroll
    for (int i = 0; i < 2; i++)
#pragma unroll
        for (int j = 0; j < 8; j++)
#pragma unroll
            for (int e = 0; e < 4; e++) d[i][j][e] = 0.f;

    const int T = K / KT;

#pragma unroll
    for (int p = 0; p < 2; p++) {
        uint32_t b = sbase + p * STG2;
        load_arr(Ab, lda, p * KT, b + 0, tid);
        load_arr(Bb, ldb, p * KT, b + ARR_BYTES, tid);
        CP_COMMIT();
    }

    for (int t = 0; t < T; t++) {
        CP_WAIT1();
        __syncthreads();

        const uint32_t sb = sbase + (t & 1) * STG2;
        const uint32_t sA_ = sb;
        const uint32_t sB_ = sb + ARR_BYTES;

#pragma unroll
        for (int ks = 0; ks < 2; ks++) {
            const int kb = ks * 32;
            uint32_t a[2][4];
            ldsm4(a[0], sA_ + aoff[0] + kb);
            ldsm4(a[1], sA_ + aoff[1] + kb);
#pragma unroll
            for (int g = 0; g < 4; g++) {
                uint32_t bh[4];
                ldsm4(bh, sB_ + boff[g] + kb);
#pragma unroll
                for (int sub = 0; sub < 2; sub++) {
                    const int nf = g * 2 + sub;
                    const uint32_t b0 = bh[sub * 2], b1 = bh[sub * 2 + 1];
                    mma_fp16(d[0][nf], a[0], b0, b1);
                    mma_fp16(d[1][nf], a[1], b0, b1);
                }
            }
        }

        __syncthreads();
        if (t + 2 < T) {
            const int kt = (t + 2) * KT;
            load_arr(Ab, lda, kt, sb + 0, tid);
            load_arr(Bb, ldb, kt, sb + ARR_BYTES, tid);
        }
        CP_COMMIT();
    }

    const int row0 = mBase + wm * 32 + (lane >> 2);
    const int col0 = nBase + wn * 64 + (lane & 3) * 2;
    float* Cp = Cf + z * sC;

#pragma unroll
    for (int mf = 0; mf < 2; mf++) {
#pragma unroll
        for (int nf = 0; nf < 8; nf++) {
            const int r = row0 + mf * 16;
            const int c = col0 + nf * 8;
            const float* dd = d[mf][nf];
            *(float2*)(Cp + (size_t)r * ldc + c) = make_float2(dd[0], dd[1]);
            *(float2*)(Cp + (size_t)(r + 8) * ldc + c) = make_float2(dd[2], dd[3]);
        }
    }
}

// ---------------------------------------------------------------------------
// 5-way fp32 split: q,k,v -> fp16 hi/lo; Wq,Wk -> bf16 hi/lo
// ---------------------------------------------------------------------------
__global__ void __launch_bounds__(256)
split5(const float4* x0, __half* h0, __half* l0, int n0,
       const float4* x1, __half* h1, __half* l1, int n1,
       const float4* x2, __half* h2, __half* l2, int n2,
       const float4* x3, __nv_bfloat16* h3, __nv_bfloat16* l3, int n3,
       const float4* x4, __nv_bfloat16* h4, __nv_bfloat16* l4, int n4v)
{
    int i = blockIdx.x * 256 + threadIdx.x;
    int s = blockIdx.y;

    if (s < 3) {
        const float4* x = (s == 0) ? x0 : (s == 1) ? x1 : x2;
        __half* hi = (s == 0) ? h0 : (s == 1) ? h1 : h2;
        __half* lo = (s == 0) ? l0 : (s == 1) ? l1 : l2;
        int n = (s == 0) ? n0 : (s == 1) ? n1 : n2;
        if (i >= n) return;
        float4 v = x[i];
        float vv[4] = {v.x, v.y, v.z, v.w};
        __half hh[4], ll[4];
#pragma unroll
        for (int j = 0; j < 4; j++) {
            __half h = __float2half_rn(vv[j]);
            hh[j] = h;
            ll[j] = __float2half_rn(vv[j] - __half2float(h));
        }
        ((uint2*)hi)[i] = *(uint2*)hh;
        ((uint2*)lo)[i] = *(uint2*)ll;
        return;
    }

    const float4* x = (s == 3) ? x3 : x4;
    __nv_bfloat16* hi = (s == 3) ? h3 : h4;
    __nv_bfloat16* lo = (s == 3) ? l3 : l4;
    int n = (s == 3) ? n3 : n4v;
    if (i >= n) return;

    float4 v = x[i];
    float vv[4] = {v.x, v.y, v.z, v.w};
    __nv_bfloat16 hh[4], ll[4];
#pragma unroll
    for (int j = 0; j < 4; j++) {
        __nv_bfloat16 h = __float2bfloat16(vv[j]);
        hh[j] = h;
        ll[j] = __float2bfloat16(vv[j] - __bfloat162float(h));
    }
    ((uint2*)hi)[i] = *(uint2*)hh;
    ((uint2*)lo)[i] = *(uint2*)ll;
}

// W[K,N] fp32 -> WT [N,K] fp16 (round only; Wv)
__global__ void __launch_bounds__(256)
transpose_half(const float* __restrict__ W, __half* __restrict__ T,
               int rows, int cols)
{
    __shared__ float tile[32][33];
    int bx = blockIdx.x * 32;
    int by = blockIdx.y * 32;
    int tx = threadIdx.x & 31;
    int ty = threadIdx.x >> 5;
#pragma unroll
    for (int i = ty; i < 32; i += 8)
        tile[i][tx] = W[(size_t)(by + i) * cols + bx + tx];
    __syncthreads();
#pragma unroll
    for (int i = ty; i < 32; i += 8)
        T[(size_t)(bx + i) * rows + by + tx] = __float2half_rn(tile[tx][i]);
}

// ---------------------------------------------------------------------------
// uv_prep / uv_main (rank-1 bias terms)
// ---------------------------------------------------------------------------
__global__ void __launch_bounds__(256)
uv_prep(const float* __restrict__ wq, const float* __restrict__ wk,
        const float* __restrict__ bq, const float* __restrict__ bk,
        float* __restrict__ w1, float* __restrict__ w2, float* __restrict__ cOut)
{
    int wid = threadIdx.x >> 5, lane = threadIdx.x & 31;
    int s = blockIdx.y;
    int row = blockIdx.x * 8 + wid;
    const float* W = s ? wk : wq;
    const float* b = s ? bq : bk;

    float acc = 0.f;
#pragma unroll
    for (int j = 0; j < 32; j++)
        acc += W[(size_t)row * DDIM + lane + 32 * j] * b[lane + 32 * j];
#pragma unroll
    for (int o = 16; o; o >>= 1) acc += __shfl_xor_sync(0xffffffffu, acc, o);
    if (lane == 0) (s ? w2 : w1)[row] = acc;

    if (blockIdx.x == 0 && s == 0 && wid == 0) {
        float cc = 0.f;
#pragma unroll
        for (int j = 0; j < 32; j++)
            cc += bq[lane + 32 * j] * bk[lane + 32 * j];
#pragma unroll
        for (int o = 16; o; o >>= 1) cc += __shfl_xor_sync(0xffffffffu, cc, o);
        if (lane == 0) cOut[0] = cc;
    }
}

__global__ void __launch_bounds__(256)
uv_main(const float* __restrict__ q, const float* __restrict__ k,
        const float* __restrict__ w1, const float* __restrict__ w2,
        const float* __restrict__ cIn,
        float* __restrict__ u, float* __restrict__ v, float scale)
{
    int wid = threadIdx.x >> 5, lane = threadIdx.x & 31;
    int s = blockIdx.y;
    int row = blockIdx.x * 8 + wid;
    const float* src = s ? k : q;
    const float* w = s ? w2 : w1;

    float acc = 0.f;
#pragma unroll
    for (int j = 0; j < 32; j++)
        acc += src[(size_t)row * IDIM + lane + 32 * j] * w[lane + 32 * j];
#pragma unroll
    for (int o = 16; o; o >>= 1) acc += __shfl_xor_sync(0xffffffffu, acc, o);
    if (lane == 0) {
        if (s == 0) u[row] = (acc + cIn[0]) * scale;
        else        v[row] = acc * scale;
    }
}

// ---------------------------------------------------------------------------
// softmax: x = lg*scale + mask + u[row] + v[col]; -> fp16 attn
// ---------------------------------------------------------------------------
__global__ void __launch_bounds__(256)
softmax_split(const float* __restrict__ logits, const float* __restrict__ mask,
              const float* __restrict__ u, const float* __restrict__ vv,
              __half* __restrict__ ah, float scale)
{
    __shared__ float red[8];
    __shared__ float bval;

    size_t row = blockIdx.x;
    int q = (int)(row & (SDIM - 1));
    const float* rp = logits + row * (size_t)SDIM;
    const float* mp = mask + (size_t)q * SDIM;
    const float* vr = vv + (row >> 11) * SDIM;
    const float uval = u[row];
    int t = threadIdx.x;

    float4 a = ((const float4*)rp)[t];
    float4 b = ((const float4*)rp)[t + 256];
    float4 ma = ((const float4*)mp)[t];
    float4 mb = ((const float4*)mp)[t + 256];
    float4 va = ((const float4*)vr)[t];
    float4 vb = ((const float4*)vr)[t + 256];
    float x[8];
    x[0] = fmaf(a.x, scale, ma.x + uval + va.x);
    x[1] = fmaf(a.y, scale, ma.y + uval + va.y);
    x[2] = fmaf(a.z, scale, ma.z + uval + va.z);
    x[3] = fmaf(a.w, scale, ma.w + uval + va.w);
    x[4] = fmaf(b.x, scale, mb.x + uval + vb.x);
    x[5] = fmaf(b.y, scale, mb.y + uval + vb.y);
    x[6] = fmaf(b.z, scale, mb.z + uval + vb.z);
    x[7] = fmaf(b.w, scale, mb.w + uval + vb.w);

    float mx = x[0];
#pragma unroll
    for (int i = 1; i < 8; i++) mx = fmaxf(mx, x[i]);
#pragma unroll
    for (int o = 16; o; o >>= 1) mx = fmaxf(mx, __shfl_xor_sync(0xffffffffu, mx, o));
    if ((t & 31) == 0) red[t >> 5] = mx;
    __syncthreads();
    if (t == 0) {
        float m = red[0];
#pragma unroll
        for (int i = 1; i < 8; i++) m = fmaxf(m, red[i]);
        bval = m;
    }
    __syncthreads();
    mx = bval;

    float s = 0.f;
#pragma unroll
    for (int i = 0; i < 8; i++) { x[i] = __expf(x[i] - mx); s += x[i]; }
#pragma unroll
    for (int o = 16; o; o >>= 1) s += __shfl_xor_sync(0xffffffffu, s, o);
    if ((t & 31) == 0) red[t >> 5] = s;
    __syncthreads();
    if (t == 0) {
        float ss = 0.f;
#pragma unroll
        for (int i = 0; i < 8; i++) ss += red[i];
        bval = 1.f / ss;
    }
    __syncthreads();
    float inv = bval;

    __half2* ah2 = (__half2*)(ah + row * (size_t)SDIM);
#pragma unroll
    for (int half = 0; half < 2; half++) {
#pragma unroll
        for (int p = 0; p < 2; p++) {
            float p0 = x[half * 4 + p * 2 + 0] * inv;
            float p1 = x[half * 4 + p * 2 + 1] * inv;
            int idx = half * 512 + t * 2 + p;
            ah2[idx] = __halves2half2(__float2half_rn(p0), __float2half_rn(p1));
        }
    }
}

// ---------------------------------------------------------------------------
extern "C" void kernel_launch(void* const* d_in, const int* in_sizes, int n_in,
                              void* d_out, int out_size)
{
    const float* q    = (const float*)d_in[0];
    const float* k    = (const float*)d_in[1];
    const float* v    = (const float*)d_in[2];
    const float* mask = (const float*)d_in[3];
    const float* wq   = (const float*)d_in[4];
    const float* bq   = (const float*)d_in[5];
    const float* wk   = (const float*)d_in[6];
    const float* bk   = (const float*)d_in[7];
    const float* wv   = (const float*)d_in[8];
    const float* bv   = (const float*)d_in[9];
    float* out = (float*)d_out;

#define SYM(p, s) do { void* _t; cudaGetSymbolAddress(&_t, s); p = (decltype(p))_t; } while (0)
    __half *qh, *ql, *kh, *kl, *vh, *vl, *wvt, *M, *P, *vpth, *ah;
    __nv_bfloat16 *wqh, *wql, *wkh, *wkl;
    float *lg, *w1, *w2, *cptr, *u, *vvp;
    SYM(qh, g_qh); SYM(ql, g_ql); SYM(kh, g_kh); SYM(kl, g_kl);
    SYM(vh, g_vh); SYM(vl, g_vl);
    SYM(wqh, g_wqh); SYM(wql, g_wql); SYM(wkh, g_wkh); SYM(wkl, g_wkl);
    SYM(wvt, g_wvt); SYM(M, g_M); SYM(P, g_P);
    SYM(vpth, g_vpth); SYM(ah, g_ah);
    SYM(lg, g_logits);
    SYM(w1, g_w1); SYM(w2, g_w2); SYM(cptr, g_c); SYM(u, g_u); SYM(vvp, g_v);
#undef SYM

    cudaFuncSetAttribute(m_gemm, cudaFuncAttributeMaxDynamicSharedMemorySize, SMEM4_TOTAL);
    cudaFuncSetAttribute(pv_gemm, cudaFuncAttributeMaxDynamicSharedMemorySize, SMEM3_TOTAL);
    cudaFuncSetAttribute(logits_gemm, cudaFuncAttributeMaxDynamicSharedMemorySize, SMEM3_TOTAL);
    cudaFuncSetAttribute(av_gemm, cudaFuncAttributeMaxDynamicSharedMemorySize, SMEM2_TOTAL);

    const int n4_act = NTOK * IDIM / 4;
    const int n4_w = IDIM * DDIM / 4;
    const float scale = 0.03125f;

    // 1: split q,k,v (fp16 hi/lo), Wq,Wk (bf16 hi/lo)
    split5<<<dim3(n4_act / 256, 5), 256>>>(
        (const float4*)q, qh, ql, n4_act,
        (const float4*)k, kh, kl, n4_act,
        (const float4*)v, vh, vl, n4_act,
        (const float4*)wq, wqh, wql, n4_w,
        (const float4*)wk, wkh, wkl, n4_w);

    // 2: transpose Wv -> fp16
    transpose_half<<<dim3(IDIM / 32, IDIM / 32), 256>>>(wv, wvt, IDIM, DDIM);

    // 3: M = Wq Wk^T (bf16 3-prod) -> fp16
    m_gemm<<<dim3(8, 8), NTHREADS, SMEM4_TOTAL>>>(wqh, wql, wkh, wkl, M);

    // 4: P = k M^T (z=0) and vp^T (z=1), both fp16 2-prod   <- ncu slot
    pv_gemm<<<dim3(IDIM / 128, NTOK / 128, 2), NTHREADS, SMEM3_TOTAL>>>(
        kh, kl, M, vh, vl, wvt, bv, P, vpth);

    // 5-6: rank-1 bias terms
    uv_prep<<<dim3(IDIM / 8, 2), 256>>>(wq, wk, bq, bk, w1, w2, cptr);
    uv_main<<<dim3(NTOK / 8, 2), 256>>>(q, k, w1, w2, cptr, u, vvp, scale);

    // 7: logits = (qh+ql) P^T (batched, fp16 2-prod)
    dim3 gl(SDIM / 128, SDIM / 128, BDIM);
    logits_gemm<<<gl, NTHREADS, SMEM3_TOTAL>>>(qh, ql, P, lg,
                                               IDIM, IDIM, IDIM, SDIM,
                                               (size_t)SDIM * IDIM, (size_t)SDIM * IDIM,
                                               (size_t)SDIM * SDIM);

    // 8: softmax (u/v/c folded) -> fp16 attn
    softmax_split<<<BDIM * SDIM, 256>>>(lg, mask, u, vvp, ah, scale);

    // 9: out = attn @ vp (fp16 1-product)
    dim3 ga(DDIM / 128, SDIM / 128, BDIM);
    av_gemm<<<ga, NTHREADS, SMEM2_TOTAL>>>(ah, vpth, out,
                                           SDIM, SDIM, NTOK, DDIM,
                                           (size_t)SDIM * SDIM, (size_t)SDIM,
                                           (size_t)SDIM * DDIM);
}

// round 16
// speedup vs baseline: 1.7916x; 1.0097x over previous
#include <cuda_runtime.h>
#include <cuda_bf16.h>
#include <cuda_fp16.h>
#include <cstdint>

#define BDIM 4
#define SDIM 2048
#define IDIM 1024
#define DDIM 1024
#define NTOK (BDIM * SDIM)   // 8192

// ---------------------------------------------------------------------------
// Device scratch (allocation-free rule)
// ---------------------------------------------------------------------------
__device__ __align__(128) __half g_qh[(size_t)NTOK * IDIM];
__device__ __align__(128) __half g_ql[(size_t)NTOK * IDIM];
__device__ __align__(128) __half g_kh[(size_t)NTOK * IDIM];
__device__ __align__(128) __half g_kl[(size_t)NTOK * IDIM];
__device__ __align__(128) __half g_vh[(size_t)NTOK * IDIM];
__device__ __align__(128) __half g_vl[(size_t)NTOK * IDIM];
__device__ __align__(128) __nv_bfloat16 g_wqh[(size_t)IDIM * DDIM];
__device__ __align__(128) __nv_bfloat16 g_wql[(size_t)IDIM * DDIM];
__device__ __align__(128) __nv_bfloat16 g_wkh[(size_t)IDIM * DDIM];
__device__ __align__(128) __nv_bfloat16 g_wkl[(size_t)IDIM * DDIM];
__device__ __align__(128) __half g_wvt[(size_t)DDIM * IDIM];       // fp16 Wv^T
__device__ __align__(128) __half g_M[(size_t)IDIM * IDIM];         // M = Wq Wk^T fp16
__device__ __align__(128) __half g_P[(size_t)NTOK * IDIM];         // P = k M^T fp16
__device__ __align__(128) __half g_vpth[(size_t)DDIM * NTOK];      // vp^T fp16
__device__ __align__(128) float g_logits[(size_t)BDIM * SDIM * SDIM];
__device__ __align__(128) __half g_ah[(size_t)BDIM * SDIM * SDIM]; // attn fp16
__device__ float g_w1[IDIM];
__device__ float g_w2[IDIM];
__device__ float g_c[1];
__device__ float g_u[NTOK];
__device__ float g_v[NTOK];

// ---------------------------------------------------------------------------
// PTX helpers
// ---------------------------------------------------------------------------
__device__ __forceinline__ uint32_t smem_u32(const void* p) {
    uint32_t a;
    asm("{ .reg .u64 t; cvta.to.shared.u64 t, %1; cvt.u32.u64 %0, t; }"
        : "=r"(a) : "l"(p));
    return a;
}

__device__ __forceinline__ void cp16(uint32_t d, const void* g) {
    asm volatile("cp.async.cg.shared.global [%0], [%1], 16;" :: "r"(d), "l"(g) : "memory");
}
#define CP_COMMIT() asm volatile("cp.async.commit_group;" ::: "memory")
#define CP_WAIT1()  asm volatile("cp.async.wait_group 1;" ::: "memory")

__device__ __forceinline__ void ldsm4(uint32_t* r, uint32_t addr) {
    asm volatile("ldmatrix.sync.aligned.m8n8.x4.shared.b16 {%0,%1,%2,%3}, [%4];"
        : "=r"(r[0]), "=r"(r[1]), "=r"(r[2]), "=r"(r[3]) : "r"(addr));
}

__device__ __forceinline__ void mma_bf16(float* d, const uint32_t* a,
                                         uint32_t b0, uint32_t b1) {
    asm volatile(
        "mma.sync.aligned.m16n8k16.row.col.f32.bf16.bf16.f32 "
        "{%0,%1,%2,%3}, {%4,%5,%6,%7}, {%8,%9}, {%0,%1,%2,%3};"
        : "+f"(d[0]), "+f"(d[1]), "+f"(d[2]), "+f"(d[3])
        : "r"(a[0]), "r"(a[1]), "r"(a[2]), "r"(a[3]), "r"(b0), "r"(b1));
}

__device__ __forceinline__ void mma_fp16(float* d, const uint32_t* a,
                                         uint32_t b0, uint32_t b1) {
    asm volatile(
        "mma.sync.aligned.m16n8k16.row.col.f32.f16.f16.f32 "
        "{%0,%1,%2,%3}, {%4,%5,%6,%7}, {%8,%9}, {%0,%1,%2,%3};"
        : "+f"(d[0]), "+f"(d[1]), "+f"(d[2]), "+f"(d[3])
        : "r"(a[0]), "r"(a[1]), "r"(a[2]), "r"(a[3]), "r"(b0), "r"(b1));
}

// SMEM geometry: 128 rows x 144B pitch arrays (128B data = 64 halves), KT=64
#define KT 64
#define ROWB 144
#define ARR_BYTES (128 * ROWB)          // 18432
#define STG4 (4 * ARR_BYTES)            // m_gemm (bf16 3-prod), 1 CTA/SM
#define SMEM4_TOTAL (2 * STG4)          // 147456
#define STG3 (3 * ARR_BYTES)
#define SMEM3_TOTAL (2 * STG3)          // 110592 -> 2 CTAs/SM
#define STG2 (2 * ARR_BYTES)
#define SMEM2_TOTAL (2 * STG2)          // 73728  -> 2 CTAs/SM

#define NTHREADS 256
#define TPITCH 132

__device__ __forceinline__ void load_arr(const void* __restrict__ Gv,
                                         int ldg, int kt, uint32_t dst, int tid) {
    const __half* G = (const __half*)Gv;
#pragma unroll
    for (int i = 0; i < 4; i++) {
        int idx = tid + i * NTHREADS;
        int row = idx >> 3;
        int c = idx & 7;
        cp16(dst + row * ROWB + c * 16, (const void*)(G + (size_t)row * ldg + kt + c * 8));
    }
}

// ---------------------------------------------------------------------------
// fp16 2-product mainloop: D[128,128] += (Ah+Al)[128,K] * B[128,K]^T (NT).
// KT=64, 3 smem arrays/stage, 2 stages.
// ---------------------------------------------------------------------------
__device__ __forceinline__ void gemm2p_mainloop(
    const __half* __restrict__ Ahb, const __half* __restrict__ Alb,
    const __half* __restrict__ Bb,
    int K, int lda, int ldb,
    uint32_t sbase, int tid, int wm, int wn, int lane,
    float d[2][8][4])
{
    const int w8 = lane & 7, j8 = lane >> 3;
    int aoff[2], boff[4];
#pragma unroll
    for (int mf = 0; mf < 2; mf++)
        aoff[mf] = (wm * 32 + mf * 16 + w8 + 8 * (j8 & 1)) * ROWB + (j8 >> 1) * 16;
#pragma unroll
    for (int g = 0; g < 4; g++)
        boff[g] = (wn * 64 + g * 16 + w8 + 8 * (j8 >> 1)) * ROWB + (j8 & 1) * 16;

    const int T = K / KT;

#pragma unroll
    for (int p = 0; p < 2; p++) {
        uint32_t b = sbase + p * STG3;
        load_arr(Ahb, lda, p * KT, b + 0, tid);
        load_arr(Alb, lda, p * KT, b + ARR_BYTES, tid);
        load_arr(Bb,  ldb, p * KT, b + 2 * ARR_BYTES, tid);
        CP_COMMIT();
    }

    for (int t = 0; t < T; t++) {
        CP_WAIT1();
        __syncthreads();

        const uint32_t sb = sbase + (t & 1) * STG3;
        const uint32_t sAh = sb;
        const uint32_t sAl = sb + ARR_BYTES;
        const uint32_t sB  = sb + 2 * ARR_BYTES;

#pragma unroll
        for (int ks = 0; ks < 4; ks++) {
            const int kb = ks * 32;
            uint32_t ah[2][4], al[2][4];
            ldsm4(ah[0], sAh + aoff[0] + kb);
            ldsm4(ah[1], sAh + aoff[1] + kb);
            ldsm4(al[0], sAl + aoff[0] + kb);
            ldsm4(al[1], sAl + aoff[1] + kb);
#pragma unroll
            for (int g = 0; g < 4; g++) {
                uint32_t bh[4];
                ldsm4(bh, sB + boff[g] + kb);
#pragma unroll
                for (int sub = 0; sub < 2; sub++) {
                    const int nf = g * 2 + sub;
                    const uint32_t b0 = bh[sub * 2], b1 = bh[sub * 2 + 1];
                    mma_fp16(d[0][nf], ah[0], b0, b1);
                    mma_fp16(d[1][nf], ah[1], b0, b1);
                    mma_fp16(d[0][nf], al[0], b0, b1);
                    mma_fp16(d[1][nf], al[1], b0, b1);
                }
            }
        }

        __syncthreads();
        if (t + 2 < T) {
            const int kt = (t + 2) * KT;
            load_arr(Ahb, lda, kt, sb + 0, tid);
            load_arr(Alb, lda, kt, sb + ARR_BYTES, tid);
            load_arr(Bb,  ldb, kt, sb + 2 * ARR_BYTES, tid);
        }
        CP_COMMIT();
    }
}

// ---------------------------------------------------------------------------
// m_gemm: M = Wq Wk^T (bf16 3-product) -> fp16. Grid (8, 8).
// ---------------------------------------------------------------------------
__global__ void __launch_bounds__(NTHREADS, 1)
m_gemm(const __nv_bfloat16* __restrict__ Ah, const __nv_bfloat16* __restrict__ Al,
       const __nv_bfloat16* __restrict__ Bh, const __nv_bfloat16* __restrict__ Bl,
       __half* __restrict__ Mo)
{
    extern __shared__ char smem[];
    const uint32_t sbase = smem_u32(smem);
    const int tid = threadIdx.x;
    const int wid = tid >> 5, lane = tid & 31;
    const int wm = wid & 3, wn = wid >> 2;
    const int mBase = blockIdx.y * 128;
    const int nBase = blockIdx.x * 128;

    const __nv_bfloat16* Ahb = Ah + (size_t)mBase * DDIM;
    const __nv_bfloat16* Alb = Al + (size_t)mBase * DDIM;
    const __nv_bfloat16* Bhb = Bh + (size_t)nBase * DDIM;
    const __nv_bfloat16* Blb = Bl + (size_t)nBase * DDIM;

    const int w8 = lane & 7, j8 = lane >> 3;
    int aoff[2], boff[4];
#pragma unroll
    for (int mf = 0; mf < 2; mf++)
        aoff[mf] = (wm * 32 + mf * 16 + w8 + 8 * (j8 & 1)) * ROWB + (j8 >> 1) * 16;
#pragma unroll
    for (int g = 0; g < 4; g++)
        boff[g] = (wn * 64 + g * 16 + w8 + 8 * (j8 >> 1)) * ROWB + (j8 & 1) * 16;

    float d[2][8][4];
#pragma unroll
    for (int i = 0; i < 2; i++)
#pragma unroll
        for (int j = 0; j < 8; j++)
#pragma unroll
            for (int e = 0; e < 4; e++) d[i][j][e] = 0.f;

    const int T = DDIM / KT;

#pragma unroll
    for (int p = 0; p < 2; p++) {
        uint32_t b = sbase + p * STG4;
        load_arr(Ahb, DDIM, p * KT, b + 0, tid);
        load_arr(Alb, DDIM, p * KT, b + ARR_BYTES, tid);
        load_arr(Bhb, DDIM, p * KT, b + 2 * ARR_BYTES, tid);
        load_arr(Blb, DDIM, p * KT, b + 3 * ARR_BYTES, tid);
        CP_COMMIT();
    }

    for (int t = 0; t < T; t++) {
        CP_WAIT1();
        __syncthreads();

        const uint32_t sb = sbase + (t & 1) * STG4;
        const uint32_t sAh = sb, sAl = sb + ARR_BYTES;
        const uint32_t sBh = sb + 2 * ARR_BYTES, sBl = sb + 3 * ARR_BYTES;

#pragma unroll
        for (int ks = 0; ks < 4; ks++) {
            const int kb = ks * 32;
            uint32_t ah[2][4], al[2][4];
            ldsm4(ah[0], sAh + aoff[0] + kb);
            ldsm4(ah[1], sAh + aoff[1] + kb);
            ldsm4(al[0], sAl + aoff[0] + kb);
            ldsm4(al[1], sAl + aoff[1] + kb);
#pragma unroll
            for (int g = 0; g < 4; g++) {
                uint32_t bh[4], bl[4];
                ldsm4(bh, sBh + boff[g] + kb);
                ldsm4(bl, sBl + boff[g] + kb);
#pragma unroll
                for (int sub = 0; sub < 2; sub++) {
                    const int nf = g * 2 + sub;
                    const uint32_t bh0 = bh[sub * 2], bh1 = bh[sub * 2 + 1];
                    const uint32_t bl0 = bl[sub * 2], bl1 = bl[sub * 2 + 1];
                    mma_bf16(d[0][nf], ah[0], bh0, bh1);
                    mma_bf16(d[1][nf], ah[1], bh0, bh1);
                    mma_bf16(d[0][nf], ah[0], bl0, bl1);
                    mma_bf16(d[1][nf], ah[1], bl0, bl1);
                    mma_bf16(d[0][nf], al[0], bh0, bh1);
                    mma_bf16(d[1][nf], al[1], bh0, bh1);
                }
            }
        }

        __syncthreads();
        if (t + 2 < T) {
            const int kt = (t + 2) * KT;
            load_arr(Ahb, DDIM, kt, sb + 0, tid);
            load_arr(Alb, DDIM, kt, sb + ARR_BYTES, tid);
            load_arr(Bhb, DDIM, kt, sb + 2 * ARR_BYTES, tid);
            load_arr(Blb, DDIM, kt, sb + 3 * ARR_BYTES, tid);
        }
        CP_COMMIT();
    }

    const int row0 = mBase + wm * 32 + (lane >> 2);
    const int col0 = nBase + wn * 64 + (lane & 3) * 2;
#pragma unroll
    for (int mf = 0; mf < 2; mf++) {
#pragma unroll
        for (int nf = 0; nf < 8; nf++) {
            const int r = row0 + mf * 16;
            const int c = col0 + nf * 8;
            const float* dd = d[mf][nf];
#pragma unroll
            for (int h = 0; h < 2; h++) {
                size_t o = (size_t)(r + h * 8) * IDIM + c;
                *(__half2*)(Mo + o) = __halves2half2(
                    __float2half_rn(dd[h * 2 + 0]), __float2half_rn(dd[h * 2 + 1]));
            }
        }
    }
}

// ---------------------------------------------------------------------------
// pv_gemm (fp16 2-product). z=0: P = k M^T -> fp16 row-major.
// z=1: vp = v Wv + bv -> fp16 transposed [DDIM, NTOK].
// ---------------------------------------------------------------------------
__global__ void __launch_bounds__(NTHREADS, 2)
pv_gemm(const __half* __restrict__ kh, const __half* __restrict__ kl,
        const __half* __restrict__ M,
        const __half* __restrict__ vh, const __half* __restrict__ vl,
        const __half* __restrict__ wvt,
        const float* __restrict__ bv,
        __half* __restrict__ P, __half* __restrict__ vpth)
{
    extern __shared__ char smem[];
    const uint32_t sbase = smem_u32(smem);
    const int tid = threadIdx.x;
    const int wid = tid >> 5, lane = tid & 31;
    const int wm = wid & 3, wn = wid >> 2;
    const int mBase = blockIdx.y * 128;
    const int nBase = blockIdx.x * 128;
    const int z = blockIdx.z;

    const __half* Ah = z ? vh : kh;
    const __half* Al = z ? vl : kl;
    const __half* B  = z ? wvt : M;

    float d[2][8][4];
#pragma unroll
    for (int i = 0; i < 2; i++)
#pragma unroll
        for (int j = 0; j < 8; j++)
#pragma unroll
            for (int e = 0; e < 4; e++) d[i][j][e] = 0.f;

    gemm2p_mainloop(Ah + (size_t)mBase * IDIM, Al + (size_t)mBase * IDIM,
                    B + (size_t)nBase * IDIM,
                    IDIM, IDIM, IDIM, sbase, tid, wm, wn, lane, d);

    if (z == 0) {
        const int row0 = mBase + wm * 32 + (lane >> 2);
        const int col0 = nBase + wn * 64 + (lane & 3) * 2;
#pragma unroll
        for (int mf = 0; mf < 2; mf++) {
#pragma unroll
            for (int nf = 0; nf < 8; nf++) {
                const int r = row0 + mf * 16;
                const int c = col0 + nf * 8;
                const float* dd = d[mf][nf];
#pragma unroll
                for (int h = 0; h < 2; h++) {
                    size_t o = (size_t)(r + h * 8) * IDIM + c;
                    *(__half2*)(P + o) = __halves2half2(
                        __float2half_rn(dd[h * 2 + 0]), __float2half_rn(dd[h * 2 + 1]));
                }
            }
        }
    } else {
        __syncthreads();
        __half* sh = (__half*)smem;
        const int lr0 = wm * 32 + (lane >> 2);
        const int lc0 = wn * 64 + (lane & 3) * 2;
#pragma unroll
        for (int mf = 0; mf < 2; mf++) {
#pragma unroll
            for (int nf = 0; nf < 8; nf++) {
                const float* dd = d[mf][nf];
                const int c = lc0 + nf * 8;
                const float b0v = bv[nBase + c], b1v = bv[nBase + c + 1];
#pragma unroll
                for (int h = 0; h < 2; h++) {
                    const int r = lr0 + mf * 16 + h * 8;
                    sh[c * TPITCH + r] = __float2half_rn(dd[h * 2 + 0] + b0v);
                    sh[(c + 1) * TPITCH + r] = __float2half_rn(dd[h * 2 + 1] + b1v);
                }
            }
        }
        __syncthreads();
#pragma unroll
        for (int i = 0; i < 16; i++) {
            const int c = wid * 16 + i;
            uint2 vh2 = *(const uint2*)(sh + c * TPITCH + lane * 4);
            size_t o = (size_t)(nBase + c) * NTOK + mBase + lane * 4;
            *(uint2*)(vpth + o) = vh2;
        }
    }
}

// ---------------------------------------------------------------------------
// Logits GEMM (fp16 2-product): x = (qh+ql) P^T * scale + mask + u + v.
// Writes softmax-ready values.
// ---------------------------------------------------------------------------
__global__ void __launch_bounds__(NTHREADS, 2)
logits_gemm(const __half* __restrict__ Ah, const __half* __restrict__ Al,
            const __half* __restrict__ B, float* __restrict__ Cf,
            const float* __restrict__ mask,
            const float* __restrict__ u, const float* __restrict__ vv,
            float scale)
{
    extern __shared__ char smem[];
    const uint32_t sbase = smem_u32(smem);
    const int tid = threadIdx.x;
    const int wid = tid >> 5, lane = tid & 31;
    const int wm = wid & 3, wn = wid >> 2;
    const int mBase = blockIdx.y * 128;
    const int nBase = blockIdx.x * 128;
    const int z = blockIdx.z;

    float d[2][8][4];
#pragma unroll
    for (int i = 0; i < 2; i++)
#pragma unroll
        for (int j = 0; j < 8; j++)
#pragma unroll
            for (int e = 0; e < 4; e++) d[i][j][e] = 0.f;

    gemm2p_mainloop(Ah + ((size_t)z * SDIM + mBase) * IDIM,
                    Al + ((size_t)z * SDIM + mBase) * IDIM,
                    B + ((size_t)z * SDIM + nBase) * IDIM,
                    IDIM, IDIM, IDIM, sbase, tid, wm, wn, lane, d);

    const int row0 = mBase + wm * 32 + (lane >> 2);
    const int col0 = nBase + wn * 64 + (lane & 3) * 2;
    float* Cp = Cf + (size_t)z * SDIM * SDIM;
    const float* ub = u + z * SDIM;
    const float* vb = vv + z * SDIM;

#pragma unroll
    for (int mf = 0; mf < 2; mf++) {
#pragma unroll
        for (int nf = 0; nf < 8; nf++) {
            const int c = col0 + nf * 8;
            const float* dd = d[mf][nf];
            const float v0 = vb[c], v1 = vb[c + 1];
#pragma unroll
            for (int h = 0; h < 2; h++) {
                const int r = row0 + mf * 16 + h * 8;
                const float uv = ub[r];
                const float* mp = mask + (size_t)r * SDIM + c;
                float2 o;
                o.x = fmaf(dd[h * 2 + 0], scale, mp[0] + uv + v0);
                o.y = fmaf(dd[h * 2 + 1], scale, mp[1] + uv + v1);
                *(float2*)(Cp + (size_t)r * SDIM + c) = o;
            }
        }
    }
}

// ---------------------------------------------------------------------------
// AV GEMM: fp16 1-product. D = attn @ vp (NT; B = vp^T K-major). KT=64.
// ---------------------------------------------------------------------------
__global__ void __launch_bounds__(NTHREADS, 2)
av_gemm(const __half* __restrict__ Ag, const __half* __restrict__ Bg,
        float* __restrict__ Cf,
        int K, int lda, int ldb, int ldc,
        size_t sA, size_t sB, size_t sC)
{
    extern __shared__ char smem[];
    const uint32_t sbase = smem_u32(smem);
    const int tid = threadIdx.x;
    const int wid = tid >> 5, lane = tid & 31;
    const int wm = wid & 3, wn = wid >> 2;
    const int mBase = blockIdx.y * 128;
    const int nBase = blockIdx.x * 128;
    const int z = blockIdx.z;

    const __half* Ab = Ag + z * sA + (size_t)mBase * lda;
    const __half* Bb = Bg + z * sB + (size_t)nBase * ldb;

    const int w8 = lane & 7, j8 = lane >> 3;
    int aoff[2], boff[4];
#pragma unroll
    for (int mf = 0; mf < 2; mf++)
        aoff[mf] = (wm * 32 + mf * 16 + w8 + 8 * (j8 & 1)) * ROWB + (j8 >> 1) * 16;
#pragma unroll
    for (int g = 0; g < 4; g++)
        boff[g] = (wn * 64 + g * 16 + w8 + 8 * (j8 >> 1)) * ROWB + (j8 & 1) * 16;

    float d[2][8][4];
#pragma unroll
    for (int i = 0; i < 2; i++)
#pragma unroll
        for (int j = 0; j < 8; j++)
#pragma unroll
            for (int e = 0; e < 4; e++) d[i][j][e] = 0.f;

    const int T = K / KT;

#pragma unroll
    for (int p = 0; p < 2; p++) {
        uint32_t b = sbase + p * STG2;
        load_arr(Ab, lda, p * KT, b + 0, tid);
        load_arr(Bb, ldb, p * KT, b + ARR_BYTES, tid);
        CP_COMMIT();
    }

    for (int t = 0; t < T; t++) {
        CP_WAIT1();
        __syncthreads();

        const uint32_t sb = sbase + (t & 1) * STG2;
        const uint32_t sA_ = sb;
        const uint32_t sB_ = sb + ARR_BYTES;

#pragma unroll
        for (int ks = 0; ks < 4; ks++) {
            const int kb = ks * 32;
            uint32_t a[2][4];
            ldsm4(a[0], sA_ + aoff[0] + kb);
            ldsm4(a[1], sA_ + aoff[1] + kb);
#pragma unroll
            for (int g = 0; g < 4; g++) {
                uint32_t bh[4];
                ldsm4(bh, sB_ + boff[g] + kb);
#pragma unroll
                for (int sub = 0; sub < 2; sub++) {
                    const int nf = g * 2 + sub;
                    const uint32_t b0 = bh[sub * 2], b1 = bh[sub * 2 + 1];
                    mma_fp16(d[0][nf], a[0], b0, b1);
                    mma_fp16(d[1][nf], a[1], b0, b1);
                }
            }
        }

        __syncthreads();
        if (t + 2 < T) {
            const int kt = (t + 2) * KT;
            load_arr(Ab, lda, kt, sb + 0, tid);
            load_arr(Bb, ldb, kt, sb + ARR_BYTES, tid);
        }
        CP_COMMIT();
    }

    const int row0 = mBase + wm * 32 + (lane >> 2);
    const int col0 = nBase + wn * 64 + (lane & 3) * 2;
    float* Cp = Cf + z * sC;

#pragma unroll
    for (int mf = 0; mf < 2; mf++) {
#pragma unroll
        for (int nf = 0; nf < 8; nf++) {
            const int r = row0 + mf * 16;
            const int c = col0 + nf * 8;
            const float* dd = d[mf][nf];
            *(float2*)(Cp + (size_t)r * ldc + c) = make_float2(dd[0], dd[1]);
            *(float2*)(Cp + (size_t)(r + 8) * ldc + c) = make_float2(dd[2], dd[3]);
        }
    }
}

// ---------------------------------------------------------------------------
// 5-way fp32 split: q,k,v -> fp16 hi/lo; Wq,Wk -> bf16 hi/lo
// ---------------------------------------------------------------------------
__global__ void __launch_bounds__(256)
split5(const float4* x0, __half* h0, __half* l0, int n0,
       const float4* x1, __half* h1, __half* l1, int n1,
       const float4* x2, __half* h2, __half* l2, int n2,
       const float4* x3, __nv_bfloat16* h3, __nv_bfloat16* l3, int n3,
       const float4* x4, __nv_bfloat16* h4, __nv_bfloat16* l4, int n4v)
{
    int i = blockIdx.x * 256 + threadIdx.x;
    int s = blockIdx.y;

    if (s < 3) {
        const float4* x = (s == 0) ? x0 : (s == 1) ? x1 : x2;
        __half* hi = (s == 0) ? h0 : (s == 1) ? h1 : h2;
        __half* lo = (s == 0) ? l0 : (s == 1) ? l1 : l2;
        int n = (s == 0) ? n0 : (s == 1) ? n1 : n2;
        if (i >= n) return;
        float4 v = x[i];
        float vv[4] = {v.x, v.y, v.z, v.w};
        __half hh[4], ll[4];
#pragma unroll
        for (int j = 0; j < 4; j++) {
            __half h = __float2half_rn(vv[j]);
            hh[j] = h;
            ll[j] = __float2half_rn(vv[j] - __half2float(h));
        }
        ((uint2*)hi)[i] = *(uint2*)hh;
        ((uint2*)lo)[i] = *(uint2*)ll;
        return;
    }

    const float4* x = (s == 3) ? x3 : x4;
    __nv_bfloat16* hi = (s == 3) ? h3 : h4;
    __nv_bfloat16* lo = (s == 3) ? l3 : l4;
    int n = (s == 3) ? n3 : n4v;
    if (i >= n) return;

    float4 v = x[i];
    float vv[4] = {v.x, v.y, v.z, v.w};
    __nv_bfloat16 hh[4], ll[4];
#pragma unroll
    for (int j = 0; j < 4; j++) {
        __nv_bfloat16 h = __float2bfloat16(vv[j]);
        hh[j] = h;
        ll[j] = __float2bfloat16(vv[j] - __bfloat162float(h));
    }
    ((uint2*)hi)[i] = *(uint2*)hh;
    ((uint2*)lo)[i] = *(uint2*)ll;
}

// W[K,N] fp32 -> WT [N,K] fp16 (round only; Wv)
__global__ void __launch_bounds__(256)
transpose_half(const float* __restrict__ W, __half* __restrict__ T,
               int rows, int cols)
{
    __shared__ float tile[32][33];
    int bx = blockIdx.x * 32;
    int by = blockIdx.y * 32;
    int tx = threadIdx.x & 31;
    int ty = threadIdx.x >> 5;
#pragma unroll
    for (int i = ty; i < 32; i += 8)
        tile[i][tx] = W[(size_t)(by + i) * cols + bx + tx];
    __syncthreads();
#pragma unroll
    for (int i = ty; i < 32; i += 8)
        T[(size_t)(bx + i) * rows + by + tx] = __float2half_rn(tile[tx][i]);
}

// ---------------------------------------------------------------------------
// uv_prep / uv_main (rank-1 bias terms)
// ---------------------------------------------------------------------------
__global__ void __launch_bounds__(256)
uv_prep(const float* __restrict__ wq, const float* __restrict__ wk,
        const float* __restrict__ bq, const float* __restrict__ bk,
        float* __restrict__ w1, float* __restrict__ w2, float* __restrict__ cOut)
{
    int wid = threadIdx.x >> 5, lane = threadIdx.x & 31;
    int s = blockIdx.y;
    int row = blockIdx.x * 8 + wid;
    const float* W = s ? wk : wq;
    const float* b = s ? bq : bk;

    float acc = 0.f;
#pragma unroll
    for (int j = 0; j < 32; j++)
        acc += W[(size_t)row * DDIM + lane + 32 * j] * b[lane + 32 * j];
#pragma unroll
    for (int o = 16; o; o >>= 1) acc += __shfl_xor_sync(0xffffffffu, acc, o);
    if (lane == 0) (s ? w2 : w1)[row] = acc;

    if (blockIdx.x == 0 && s == 0 && wid == 0) {
        float cc = 0.f;
#pragma unroll
        for (int j = 0; j < 32; j++)
            cc += bq[lane + 32 * j] * bk[lane + 32 * j];
#pragma unroll
        for (int o = 16; o; o >>= 1) cc += __shfl_xor_sync(0xffffffffu, cc, o);
        if (lane == 0) cOut[0] = cc;
    }
}

__global__ void __launch_bounds__(256)
uv_main(const float* __restrict__ q, const float* __restrict__ k,
        const float* __restrict__ w1, const float* __restrict__ w2,
        const float* __restrict__ cIn,
        float* __restrict__ u, float* __restrict__ v, float scale)
{
    int wid = threadIdx.x >> 5, lane = threadIdx.x & 31;
    int s = blockIdx.y;
    int row = blockIdx.x * 8 + wid;
    const float* src = s ? k : q;
    const float* w = s ? w2 : w1;

    float acc = 0.f;
#pragma unroll
    for (int j = 0; j < 32; j++)
        acc += src[(size_t)row * IDIM + lane + 32 * j] * w[lane + 32 * j];
#pragma unroll
    for (int o = 16; o; o >>= 1) acc += __shfl_xor_sync(0xffffffffu, acc, o);
    if (lane == 0) {
        if (s == 0) u[row] = (acc + cIn[0]) * scale;
        else        v[row] = acc * scale;
    }
}

// ---------------------------------------------------------------------------
// softmax over pre-biased x -> fp16 attn
// ---------------------------------------------------------------------------
__global__ void __launch_bounds__(256)
softmax_fp16(const float* __restrict__ xin, __half* __restrict__ ah)
{
    __shared__ float red[8];
    __shared__ float bval;

    size_t row = blockIdx.x;
    const float* rp = xin + row * (size_t)SDIM;
    int t = threadIdx.x;

    float4 a = ((const float4*)rp)[t];
    float4 b = ((const float4*)rp)[t + 256];
    float x[8] = {a.x, a.y, a.z, a.w, b.x, b.y, b.z, b.w};

    float mx = x[0];
#pragma unroll
    for (int i = 1; i < 8; i++) mx = fmaxf(mx, x[i]);
#pragma unroll
    for (int o = 16; o; o >>= 1) mx = fmaxf(mx, __shfl_xor_sync(0xffffffffu, mx, o));
    if ((t & 31) == 0) red[t >> 5] = mx;
    __syncthreads();
    if (t == 0) {
        float m = red[0];
#pragma unroll
        for (int i = 1; i < 8; i++) m = fmaxf(m, red[i]);
        bval = m;
    }
    __syncthreads();
    mx = bval;

    float s = 0.f;
#pragma unroll
    for (int i = 0; i < 8; i++) { x[i] = __expf(x[i] - mx); s += x[i]; }
#pragma unroll
    for (int o = 16; o; o >>= 1) s += __shfl_xor_sync(0xffffffffu, s, o);
    if ((t & 31) == 0) red[t >> 5] = s;
    __syncthreads();
    if (t == 0) {
        float ss = 0.f;
#pragma unroll
        for (int i = 0; i < 8; i++) ss += red[i];
        bval = 1.f / ss;
    }
    __syncthreads();
    float inv = bval;

    __half2* ah2 = (__half2*)(ah + row * (size_t)SDIM);
#pragma unroll
    for (int half = 0; half < 2; half++) {
#pragma unroll
        for (int p = 0; p < 2; p++) {
            float p0 = x[half * 4 + p * 2 + 0] * inv;
            float p1 = x[half * 4 + p * 2 + 1] * inv;
            int idx = half * 512 + t * 2 + p;
            ah2[idx] = __halves2half2(__float2half_rn(p0), __float2half_rn(p1));
        }
    }
}

// ---------------------------------------------------------------------------
extern "C" void kernel_launch(void* const* d_in, const int* in_sizes, int n_in,
                              void* d_out, int out_size)
{
    const float* q    = (const float*)d_in[0];
    const float* k    = (const float*)d_in[1];
    const float* v    = (const float*)d_in[2];
    const float* mask = (const float*)d_in[3];
    const float* wq   = (const float*)d_in[4];
    const float* bq   = (const float*)d_in[5];
    const float* wk   = (const float*)d_in[6];
    const float* bk   = (const float*)d_in[7];
    const float* wv   = (const float*)d_in[8];
    const float* bv   = (const float*)d_in[9];
    float* out = (float*)d_out;

#define SYM(p, s) do { void* _t; cudaGetSymbolAddress(&_t, s); p = (decltype(p))_t; } while (0)
    __half *qh, *ql, *kh, *kl, *vh, *vl, *wvt, *M, *P, *vpth, *ah;
    __nv_bfloat16 *wqh, *wql, *wkh, *wkl;
    float *lg, *w1, *w2, *cptr, *u, *vvp;
    SYM(qh, g_qh); SYM(ql, g_ql); SYM(kh, g_kh); SYM(kl, g_kl);
    SYM(vh, g_vh); SYM(vl, g_vl);
    SYM(wqh, g_wqh); SYM(wql, g_wql); SYM(wkh, g_wkh); SYM(wkl, g_wkl);
    SYM(wvt, g_wvt); SYM(M, g_M); SYM(P, g_P);
    SYM(vpth, g_vpth); SYM(ah, g_ah);
    SYM(lg, g_logits);
    SYM(w1, g_w1); SYM(w2, g_w2); SYM(cptr, g_c); SYM(u, g_u); SYM(vvp, g_v);
#undef SYM

    cudaFuncSetAttribute(m_gemm, cudaFuncAttributeMaxDynamicSharedMemorySize, SMEM4_TOTAL);
    cudaFuncSetAttribute(pv_gemm, cudaFuncAttributeMaxDynamicSharedMemorySize, SMEM3_TOTAL);
    cudaFuncSetAttribute(logits_gemm, cudaFuncAttributeMaxDynamicSharedMemorySize, SMEM3_TOTAL);
    cudaFuncSetAttribute(av_gemm, cudaFuncAttributeMaxDynamicSharedMemorySize, SMEM2_TOTAL);

    const int n4_act = NTOK * IDIM / 4;
    const int n4_w = IDIM * DDIM / 4;
    const float scale = 0.03125f;

    // 1: split q,k,v (fp16 hi/lo), Wq,Wk (bf16 hi/lo)
    split5<<<dim3(n4_act / 256, 5), 256>>>(
        (const float4*)q, qh, ql, n4_act,
        (const float4*)k, kh, kl, n4_act,
        (const float4*)v, vh, vl, n4_act,
        (const float4*)wq, wqh, wql, n4_w,
        (const float4*)wk, wkh, wkl, n4_w);

    // 2: transpose Wv -> fp16
    transpose_half<<<dim3(IDIM / 32, IDIM / 32), 256>>>(wv, wvt, IDIM, DDIM);

    // 3: M = Wq Wk^T (bf16 3-prod) -> fp16
    m_gemm<<<dim3(8, 8), NTHREADS, SMEM4_TOTAL>>>(wqh, wql, wkh, wkl, M);

    // 4: P = k M^T (z=0) and vp^T (z=1), fp16 2-prod   <- ncu slot
    pv_gemm<<<dim3(IDIM / 128, NTOK / 128, 2), NTHREADS, SMEM3_TOTAL>>>(
        kh, kl, M, vh, vl, wvt, bv, P, vpth);

    // 5-6: rank-1 bias terms
    uv_prep<<<dim3(IDIM / 8, 2), 256>>>(wq, wk, bq, bk, w1, w2, cptr);
    uv_main<<<dim3(NTOK / 8, 2), 256>>>(q, k, w1, w2, cptr, u, vvp, scale);

    // 7: x = q P^T * scale + mask + u + v  (fused bias epilogue)
    dim3 gl(SDIM / 128, SDIM / 128, BDIM);
    logits_gemm<<<gl, NTHREADS, SMEM3_TOTAL>>>(qh, ql, P, lg, mask, u, vvp, scale);

    // 8: softmax -> fp16 attn
    softmax_fp16<<<BDIM * SDIM, 256>>>(lg, ah);

    // 9: out = attn @ vp (fp16 1-product)
    dim3 ga(DDIM / 128, SDIM / 128, BDIM);
    av_gemm<<<ga, NTHREADS, SMEM2_TOTAL>>>(ah, vpth, out,
                                           SDIM, SDIM, NTOK, DDIM,
                                           (size_t)SDIM * SDIM, (size_t)SDIM,
                                           (size_t)SDIM * DDIM);
}

// round 17
// speedup vs baseline: 1.7931x; 1.0008x over previous
#include <cuda_runtime.h>
#include <cuda_bf16.h>
#include <cuda_fp16.h>
#include <cstdint>

#define BDIM 4
#define SDIM 2048
#define IDIM 1024
#define DDIM 1024
#define NTOK (BDIM * SDIM)   // 8192

// ---------------------------------------------------------------------------
// Device scratch (allocation-free rule)
// ---------------------------------------------------------------------------
__device__ __align__(128) __half g_qh[(size_t)NTOK * IDIM];
__device__ __align__(128) __half g_ql[(size_t)NTOK * IDIM];
__device__ __align__(128) __half g_kh[(size_t)NTOK * IDIM];
__device__ __align__(128) __half g_kl[(size_t)NTOK * IDIM];
__device__ __align__(128) __half g_vh[(size_t)NTOK * IDIM];
__device__ __align__(128) __half g_vl[(size_t)NTOK * IDIM];
__device__ __align__(128) __nv_bfloat16 g_wqh[(size_t)IDIM * DDIM];
__device__ __align__(128) __nv_bfloat16 g_wql[(size_t)IDIM * DDIM];
__device__ __align__(128) __nv_bfloat16 g_wkh[(size_t)IDIM * DDIM];
__device__ __align__(128) __nv_bfloat16 g_wkl[(size_t)IDIM * DDIM];
__device__ __align__(128) __half g_wvt[(size_t)DDIM * IDIM];       // fp16 Wv^T
__device__ __align__(128) __half g_M[(size_t)IDIM * IDIM];         // M = Wq Wk^T fp16
__device__ __align__(128) __half g_P[(size_t)NTOK * IDIM];         // P = k M^T fp16
__device__ __align__(128) __half g_vpth[(size_t)DDIM * NTOK];      // vp^T fp16
__device__ __align__(128) float g_logits[(size_t)BDIM * SDIM * SDIM];
__device__ __align__(128) __half g_ah[(size_t)BDIM * SDIM * SDIM]; // attn fp16
__device__ float g_w1[IDIM];
__device__ float g_w2[IDIM];
__device__ float g_c[1];
__device__ float g_u[NTOK];
__device__ float g_v[NTOK];

// ---------------------------------------------------------------------------
// PTX helpers
// ---------------------------------------------------------------------------
__device__ __forceinline__ uint32_t smem_u32(const void* p) {
    uint32_t a;
    asm("{ .reg .u64 t; cvta.to.shared.u64 t, %1; cvt.u32.u64 %0, t; }"
        : "=r"(a) : "l"(p));
    return a;
}

__device__ __forceinline__ void cp16(uint32_t d, const void* g) {
    asm volatile("cp.async.cg.shared.global [%0], [%1], 16;" :: "r"(d), "l"(g) : "memory");
}
#define CP_COMMIT() asm volatile("cp.async.commit_group;" ::: "memory")
#define CP_WAIT1()  asm volatile("cp.async.wait_group 1;" ::: "memory")

__device__ __forceinline__ void ldsm4(uint32_t* r, uint32_t addr) {
    asm volatile("ldmatrix.sync.aligned.m8n8.x4.shared.b16 {%0,%1,%2,%3}, [%4];"
        : "=r"(r[0]), "=r"(r[1]), "=r"(r[2]), "=r"(r[3]) : "r"(addr));
}

__device__ __forceinline__ void mma_bf16(float* d, const uint32_t* a,
                                         uint32_t b0, uint32_t b1) {
    asm volatile(
        "mma.sync.aligned.m16n8k16.row.col.f32.bf16.bf16.f32 "
        "{%0,%1,%2,%3}, {%4,%5,%6,%7}, {%8,%9}, {%0,%1,%2,%3};"
        : "+f"(d[0]), "+f"(d[1]), "+f"(d[2]), "+f"(d[3])
        : "r"(a[0]), "r"(a[1]), "r"(a[2]), "r"(a[3]), "r"(b0), "r"(b1));
}

__device__ __forceinline__ void mma_fp16(float* d, const uint32_t* a,
                                         uint32_t b0, uint32_t b1) {
    asm volatile(
        "mma.sync.aligned.m16n8k16.row.col.f32.f16.f16.f32 "
        "{%0,%1,%2,%3}, {%4,%5,%6,%7}, {%8,%9}, {%0,%1,%2,%3};"
        : "+f"(d[0]), "+f"(d[1]), "+f"(d[2]), "+f"(d[3])
        : "r"(a[0]), "r"(a[1]), "r"(a[2]), "r"(a[3]), "r"(b0), "r"(b1));
}

// SMEM geometry: 128 rows x 80B pitch arrays (64B data = 32 halves), KT=32
#define KT 32
#define ROWB 80
#define ARR_BYTES (128 * ROWB)          // 10240
#define STG4 (4 * ARR_BYTES)
#define SMEM4_TOTAL (2 * STG4)          // 81920 (m_gemm)
#define STG3 (3 * ARR_BYTES)
#define SMEM3_TOTAL (2 * STG3)          // 61440 (2-prod fp16 GEMMs)
#define STG2 (2 * ARR_BYTES)
#define SMEM2_TOTAL (2 * STG2)          // 40960 (AV 1-prod)

#define NTHREADS 256
#define TPITCH 132

__device__ __forceinline__ void load_arr(const void* __restrict__ Gv,
                                         int ldg, int kt, uint32_t dst, int tid) {
    const __half* G = (const __half*)Gv;
#pragma unroll
    for (int i = 0; i < 2; i++) {
        int idx = tid + i * NTHREADS;
        int row = idx >> 2;
        int c = idx & 3;
        cp16(dst + row * ROWB + c * 16, (const void*)(G + (size_t)row * ldg + kt + c * 8));
    }
}

// ---------------------------------------------------------------------------
// fp16 2-product mainloop: D[128,128] += (Ah+Al)[128,K] * B[128,K]^T (NT).
// KT=32, 3 smem arrays/stage, 2 stages.
// ---------------------------------------------------------------------------
__device__ __forceinline__ void gemm2p_mainloop(
    const __half* __restrict__ Ahb, const __half* __restrict__ Alb,
    const __half* __restrict__ Bb,
    int K, int lda, int ldb,
    uint32_t sbase, int tid, int wm, int wn, int lane,
    float d[2][8][4])
{
    const int w8 = lane & 7, j8 = lane >> 3;
    int aoff[2], boff[4];
#pragma unroll
    for (int mf = 0; mf < 2; mf++)
        aoff[mf] = (wm * 32 + mf * 16 + w8 + 8 * (j8 & 1)) * ROWB + (j8 >> 1) * 16;
#pragma unroll
    for (int g = 0; g < 4; g++)
        boff[g] = (wn * 64 + g * 16 + w8 + 8 * (j8 >> 1)) * ROWB + (j8 & 1) * 16;

    const int T = K / KT;

#pragma unroll
    for (int p = 0; p < 2; p++) {
        uint32_t b = sbase + p * STG3;
        load_arr(Ahb, lda, p * KT, b + 0, tid);
        load_arr(Alb, lda, p * KT, b + ARR_BYTES, tid);
        load_arr(Bb,  ldb, p * KT, b + 2 * ARR_BYTES, tid);
        CP_COMMIT();
    }

    for (int t = 0; t < T; t++) {
        CP_WAIT1();
        __syncthreads();

        const uint32_t sb = sbase + (t & 1) * STG3;
        const uint32_t sAh = sb;
        const uint32_t sAl = sb + ARR_BYTES;
        const uint32_t sB  = sb + 2 * ARR_BYTES;

#pragma unroll
        for (int ks = 0; ks < 2; ks++) {
            const int kb = ks * 32;
            uint32_t ah[2][4], al[2][4];
            ldsm4(ah[0], sAh + aoff[0] + kb);
            ldsm4(ah[1], sAh + aoff[1] + kb);
            ldsm4(al[0], sAl + aoff[0] + kb);
            ldsm4(al[1], sAl + aoff[1] + kb);
#pragma unroll
            for (int g = 0; g < 4; g++) {
                uint32_t bh[4];
                ldsm4(bh, sB + boff[g] + kb);
#pragma unroll
                for (int sub = 0; sub < 2; sub++) {
                    const int nf = g * 2 + sub;
                    const uint32_t b0 = bh[sub * 2], b1 = bh[sub * 2 + 1];
                    mma_fp16(d[0][nf], ah[0], b0, b1);
                    mma_fp16(d[1][nf], ah[1], b0, b1);
                    mma_fp16(d[0][nf], al[0], b0, b1);
                    mma_fp16(d[1][nf], al[1], b0, b1);
                }
            }
        }

        __syncthreads();
        if (t + 2 < T) {
            const int kt = (t + 2) * KT;
            load_arr(Ahb, lda, kt, sb + 0, tid);
            load_arr(Alb, lda, kt, sb + ARR_BYTES, tid);
            load_arr(Bb,  ldb, kt, sb + 2 * ARR_BYTES, tid);
        }
        CP_COMMIT();
    }
}

// ---------------------------------------------------------------------------
// m_gemm: M = Wq Wk^T (bf16 3-product) -> fp16. Grid (8, 8).
// ---------------------------------------------------------------------------
__global__ void __launch_bounds__(NTHREADS, 2)
m_gemm(const __nv_bfloat16* __restrict__ Ah, const __nv_bfloat16* __restrict__ Al,
       const __nv_bfloat16* __restrict__ Bh, const __nv_bfloat16* __restrict__ Bl,
       __half* __restrict__ Mo)
{
    extern __shared__ char smem[];
    const uint32_t sbase = smem_u32(smem);
    const int tid = threadIdx.x;
    const int wid = tid >> 5, lane = tid & 31;
    const int wm = wid & 3, wn = wid >> 2;
    const int mBase = blockIdx.y * 128;
    const int nBase = blockIdx.x * 128;

    const __nv_bfloat16* Ahb = Ah + (size_t)mBase * DDIM;
    const __nv_bfloat16* Alb = Al + (size_t)mBase * DDIM;
    const __nv_bfloat16* Bhb = Bh + (size_t)nBase * DDIM;
    const __nv_bfloat16* Blb = Bl + (size_t)nBase * DDIM;

    const int w8 = lane & 7, j8 = lane >> 3;
    int aoff[2], boff[4];
#pragma unroll
    for (int mf = 0; mf < 2; mf++)
        aoff[mf] = (wm * 32 + mf * 16 + w8 + 8 * (j8 & 1)) * ROWB + (j8 >> 1) * 16;
#pragma unroll
    for (int g = 0; g < 4; g++)
        boff[g] = (wn * 64 + g * 16 + w8 + 8 * (j8 >> 1)) * ROWB + (j8 & 1) * 16;

    float d[2][8][4];
#pragma unroll
    for (int i = 0; i < 2; i++)
#pragma unroll
        for (int j = 0; j < 8; j++)
#pragma unroll
            for (int e = 0; e < 4; e++) d[i][j][e] = 0.f;

    const int T = DDIM / KT;

#pragma unroll
    for (int p = 0; p < 2; p++) {
        uint32_t b = sbase + p * STG4;
        load_arr(Ahb, DDIM, p * KT, b + 0, tid);
        load_arr(Alb, DDIM, p * KT, b + ARR_BYTES, tid);
        load_arr(Bhb, DDIM, p * KT, b + 2 * ARR_BYTES, tid);
        load_arr(Blb, DDIM, p * KT, b + 3 * ARR_BYTES, tid);
        CP_COMMIT();
    }

    for (int t = 0; t < T; t++) {
        CP_WAIT1();
        __syncthreads();

        const uint32_t sb = sbase + (t & 1) * STG4;
        const uint32_t sAh = sb, sAl = sb + ARR_BYTES;
        const uint32_t sBh = sb + 2 * ARR_BYTES, sBl = sb + 3 * ARR_BYTES;

#pragma unroll
        for (int ks = 0; ks < 2; ks++) {
            const int kb = ks * 32;
            uint32_t ah[2][4], al[2][4];
            ldsm4(ah[0], sAh + aoff[0] + kb);
            ldsm4(ah[1], sAh + aoff[1] + kb);
            ldsm4(al[0], sAl + aoff[0] + kb);
            ldsm4(al[1], sAl + aoff[1] + kb);
#pragma unroll
            for (int g = 0; g < 4; g++) {
                uint32_t bh[4], bl[4];
                ldsm4(bh, sBh + boff[g] + kb);
                ldsm4(bl, sBl + boff[g] + kb);
#pragma unroll
                for (int sub = 0; sub < 2; sub++) {
                    const int nf = g * 2 + sub;
                    const uint32_t bh0 = bh[sub * 2], bh1 = bh[sub * 2 + 1];
                    const uint32_t bl0 = bl[sub * 2], bl1 = bl[sub * 2 + 1];
                    mma_bf16(d[0][nf], ah[0], bh0, bh1);
                    mma_bf16(d[1][nf], ah[1], bh0, bh1);
                    mma_bf16(d[0][nf], ah[0], bl0, bl1);
                    mma_bf16(d[1][nf], ah[1], bl0, bl1);
                    mma_bf16(d[0][nf], al[0], bh0, bh1);
                    mma_bf16(d[1][nf], al[1], bh0, bh1);
                }
            }
        }

        __syncthreads();
        if (t + 2 < T) {
            const int kt = (t + 2) * KT;
            load_arr(Ahb, DDIM, kt, sb + 0, tid);
            load_arr(Alb, DDIM, kt, sb + ARR_BYTES, tid);
            load_arr(Bhb, DDIM, kt, sb + 2 * ARR_BYTES, tid);
            load_arr(Blb, DDIM, kt, sb + 3 * ARR_BYTES, tid);
        }
        CP_COMMIT();
    }

    const int row0 = mBase + wm * 32 + (lane >> 2);
    const int col0 = nBase + wn * 64 + (lane & 3) * 2;
#pragma unroll
    for (int mf = 0; mf < 2; mf++) {
#pragma unroll
        for (int nf = 0; nf < 8; nf++) {
            const int r = row0 + mf * 16;
            const int c = col0 + nf * 8;
            const float* dd = d[mf][nf];
#pragma unroll
            for (int h = 0; h < 2; h++) {
                size_t o = (size_t)(r + h * 8) * IDIM + c;
                *(__half2*)(Mo + o) = __halves2half2(
                    __float2half_rn(dd[h * 2 + 0]), __float2half_rn(dd[h * 2 + 1]));
            }
        }
    }
}

// ---------------------------------------------------------------------------
// pv_gemm (fp16 2-product). z=0: P = k M^T -> fp16 row-major.
// z=1: vp = v Wv + bv -> fp16 transposed [DDIM, NTOK].
// ---------------------------------------------------------------------------
__global__ void __launch_bounds__(NTHREADS, 2)
pv_gemm(const __half* __restrict__ kh, const __half* __restrict__ kl,
        const __half* __restrict__ M,
        const __half* __restrict__ vh, const __half* __restrict__ vl,
        const __half* __restrict__ wvt,
        const float* __restrict__ bv,
        __half* __restrict__ P, __half* __restrict__ vpth)
{
    extern __shared__ char smem[];
    const uint32_t sbase = smem_u32(smem);
    const int tid = threadIdx.x;
    const int wid = tid >> 5, lane = tid & 31;
    const int wm = wid & 3, wn = wid >> 2;
    const int mBase = blockIdx.y * 128;
    const int nBase = blockIdx.x * 128;
    const int z = blockIdx.z;

    const __half* Ah = z ? vh : kh;
    const __half* Al = z ? vl : kl;
    const __half* B  = z ? wvt : M;

    float d[2][8][4];
#pragma unroll
    for (int i = 0; i < 2; i++)
#pragma unroll
        for (int j = 0; j < 8; j++)
#pragma unroll
            for (int e = 0; e < 4; e++) d[i][j][e] = 0.f;

    gemm2p_mainloop(Ah + (size_t)mBase * IDIM, Al + (size_t)mBase * IDIM,
                    B + (size_t)nBase * IDIM,
                    IDIM, IDIM, IDIM, sbase, tid, wm, wn, lane, d);

    if (z == 0) {
        const int row0 = mBase + wm * 32 + (lane >> 2);
        const int col0 = nBase + wn * 64 + (lane & 3) * 2;
#pragma unroll
        for (int mf = 0; mf < 2; mf++) {
#pragma unroll
            for (int nf = 0; nf < 8; nf++) {
                const int r = row0 + mf * 16;
                const int c = col0 + nf * 8;
                const float* dd = d[mf][nf];
#pragma unroll
                for (int h = 0; h < 2; h++) {
                    size_t o = (size_t)(r + h * 8) * IDIM + c;
                    *(__half2*)(P + o) = __halves2half2(
                        __float2half_rn(dd[h * 2 + 0]), __float2half_rn(dd[h * 2 + 1]));
                }
            }
        }
    } else {
        __syncthreads();
        __half* sh = (__half*)smem;
        const int lr0 = wm * 32 + (lane >> 2);
        const int lc0 = wn * 64 + (lane & 3) * 2;
#pragma unroll
        for (int mf = 0; mf < 2; mf++) {
#pragma unroll
            for (int nf = 0; nf < 8; nf++) {
                const float* dd = d[mf][nf];
                const int c = lc0 + nf * 8;
                const float b0v = bv[nBase + c], b1v = bv[nBase + c + 1];
#pragma unroll
                for (int h = 0; h < 2; h++) {
                    const int r = lr0 + mf * 16 + h * 8;
                    sh[c * TPITCH + r] = __float2half_rn(dd[h * 2 + 0] + b0v);
                    sh[(c + 1) * TPITCH + r] = __float2half_rn(dd[h * 2 + 1] + b1v);
                }
            }
        }
        __syncthreads();
#pragma unroll
        for (int i = 0; i < 16; i++) {
            const int c = wid * 16 + i;
            uint2 vh2 = *(const uint2*)(sh + c * TPITCH + lane * 4);
            size_t o = (size_t)(nBase + c) * NTOK + mBase + lane * 4;
            *(uint2*)(vpth + o) = vh2;
        }
    }
}

// ---------------------------------------------------------------------------
// Logits GEMM (fp16 2-product): x = (qh+ql) P^T * scale + mask + u + v.
// Writes softmax-ready values.
// ---------------------------------------------------------------------------
__global__ void __launch_bounds__(NTHREADS, 2)
logits_gemm(const __half* __restrict__ Ah, const __half* __restrict__ Al,
            const __half* __restrict__ B, float* __restrict__ Cf,
            const float* __restrict__ mask,
            const float* __restrict__ u, const float* __restrict__ vv,
            float scale)
{
    extern __shared__ char smem[];
    const uint32_t sbase = smem_u32(smem);
    const int tid = threadIdx.x;
    const int wid = tid >> 5, lane = tid & 31;
    const int wm = wid & 3, wn = wid >> 2;
    const int mBase = blockIdx.y * 128;
    const int nBase = blockIdx.x * 128;
    const int z = blockIdx.z;

    float d[2][8][4];
#pragma unroll
    for (int i = 0; i < 2; i++)
#pragma unroll
        for (int j = 0; j < 8; j++)
#pragma unroll
            for (int e = 0; e < 4; e++) d[i][j][e] = 0.f;

    gemm2p_mainloop(Ah + ((size_t)z * SDIM + mBase) * IDIM,
                    Al + ((size_t)z * SDIM + mBase) * IDIM,
                    B + ((size_t)z * SDIM + nBase) * IDIM,
                    IDIM, IDIM, IDIM, sbase, tid, wm, wn, lane, d);

    const int row0 = mBase + wm * 32 + (lane >> 2);
    const int col0 = nBase + wn * 64 + (lane & 3) * 2;
    float* Cp = Cf + (size_t)z * SDIM * SDIM;
    const float* ub = u + z * SDIM;
    const float* vb = vv + z * SDIM;

#pragma unroll
    for (int mf = 0; mf < 2; mf++) {
#pragma unroll
        for (int nf = 0; nf < 8; nf++) {
            const int c = col0 + nf * 8;
            const float* dd = d[mf][nf];
            const float v0 = vb[c], v1 = vb[c + 1];
#pragma unroll
            for (int h = 0; h < 2; h++) {
                const int r = row0 + mf * 16 + h * 8;
                const float uv = ub[r];
                const float* mp = mask + (size_t)r * SDIM + c;
                float2 o;
                o.x = fmaf(dd[h * 2 + 0], scale, mp[0] + uv + v0);
                o.y = fmaf(dd[h * 2 + 1], scale, mp[1] + uv + v1);
                *(float2*)(Cp + (size_t)r * SDIM + c) = o;
            }
        }
    }
}

// ---------------------------------------------------------------------------
// AV GEMM: fp16 1-product. D = attn @ vp (NT; B = vp^T K-major). KT=32.
// ---------------------------------------------------------------------------
__global__ void __launch_bounds__(NTHREADS, 2)
av_gemm(const __half* __restrict__ Ag, const __half* __restrict__ Bg,
        float* __restrict__ Cf,
        int K, int lda, int ldb, int ldc,
        size_t sA, size_t sB, size_t sC)
{
    extern __shared__ char smem[];
    const uint32_t sbase = smem_u32(smem);
    const int tid = threadIdx.x;
    const int wid = tid >> 5, lane = tid & 31;
    const int wm = wid & 3, wn = wid >> 2;
    const int mBase = blockIdx.y * 128;
    const int nBase = blockIdx.x * 128;
    const int z = blockIdx.z;

    const __half* Ab = Ag + z * sA + (size_t)mBase * lda;
    const __half* Bb = Bg + z * sB + (size_t)nBase * ldb;

    const int w8 = lane & 7, j8 = lane >> 3;
    int aoff[2], boff[4];
#pragma unroll
    for (int mf = 0; mf < 2; mf++)
        aoff[mf] = (wm * 32 + mf * 16 + w8 + 8 * (j8 & 1)) * ROWB + (j8 >> 1) * 16;
#pragma unroll
    for (int g = 0; g < 4; g++)
        boff[g] = (wn * 64 + g * 16 + w8 + 8 * (j8 >> 1)) * ROWB + (j8 & 1) * 16;

    float d[2][8][4];
#pragma unroll
    for (int i = 0; i < 2; i++)
#pragma unroll
        for (int j = 0; j < 8; j++)
#pragma unroll
            for (int e = 0; e < 4; e++) d[i][j][e] = 0.f;

    const int T = K / KT;

#pragma unroll
    for (int p = 0; p < 2; p++) {
        uint32_t b = sbase + p * STG2;
        load_arr(Ab, lda, p * KT, b + 0, tid);
        load_arr(Bb, ldb, p * KT, b + ARR_BYTES, tid);
        CP_COMMIT();
    }

    for (int t = 0; t < T; t++) {
        CP_WAIT1();
        __syncthreads();

        const uint32_t sb = sbase + (t & 1) * STG2;
        const uint32_t sA_ = sb;
        const uint32_t sB_ = sb + ARR_BYTES;

#pragma unroll
        for (int ks = 0; ks < 2; ks++) {
            const int kb = ks * 32;
            uint32_t a[2][4];
            ldsm4(a[0], sA_ + aoff[0] + kb);
            ldsm4(a[1], sA_ + aoff[1] + kb);
#pragma unroll
            for (int g = 0; g < 4; g++) {
                uint32_t bh[4];
                ldsm4(bh, sB_ + boff[g] + kb);
#pragma unroll
                for (int sub = 0; sub < 2; sub++) {
                    const int nf = g * 2 + sub;
                    const uint32_t b0 = bh[sub * 2], b1 = bh[sub * 2 + 1];
                    mma_fp16(d[0][nf], a[0], b0, b1);
                    mma_fp16(d[1][nf], a[1], b0, b1);
                }
            }
        }

        __syncthreads();
        if (t + 2 < T) {
            const int kt = (t + 2) * KT;
            load_arr(Ab, lda, kt, sb + 0, tid);
            load_arr(Bb, ldb, kt, sb + ARR_BYTES, tid);
        }
        CP_COMMIT();
    }

    const int row0 = mBase + wm * 32 + (lane >> 2);
    const int col0 = nBase + wn * 64 + (lane & 3) * 2;
    float* Cp = Cf + z * sC;

#pragma unroll
    for (int mf = 0; mf < 2; mf++) {
#pragma unroll
        for (int nf = 0; nf < 8; nf++) {
            const int r = row0 + mf * 16;
            const int c = col0 + nf * 8;
            const float* dd = d[mf][nf];
            *(float2*)(Cp + (size_t)r * ldc + c) = make_float2(dd[0], dd[1]);
            *(float2*)(Cp + (size_t)(r + 8) * ldc + c) = make_float2(dd[2], dd[3]);
        }
    }
}

// ---------------------------------------------------------------------------
// 5-way fp32 split: q,k,v -> fp16 hi/lo; Wq,Wk -> bf16 hi/lo
// ---------------------------------------------------------------------------
__global__ void __launch_bounds__(256)
split5(const float4* x0, __half* h0, __half* l0, int n0,
       const float4* x1, __half* h1, __half* l1, int n1,
       const float4* x2, __half* h2, __half* l2, int n2,
       const float4* x3, __nv_bfloat16* h3, __nv_bfloat16* l3, int n3,
       const float4* x4, __nv_bfloat16* h4, __nv_bfloat16* l4, int n4v)
{
    int i = blockIdx.x * 256 + threadIdx.x;
    int s = blockIdx.y;

    if (s < 3) {
        const float4* x = (s == 0) ? x0 : (s == 1) ? x1 : x2;
        __half* hi = (s == 0) ? h0 : (s == 1) ? h1 : h2;
        __half* lo = (s == 0) ? l0 : (s == 1) ? l1 : l2;
        int n = (s == 0) ? n0 : (s == 1) ? n1 : n2;
        if (i >= n) return;
        float4 v = x[i];
        float vv[4] = {v.x, v.y, v.z, v.w};
        __half hh[4], ll[4];
#pragma unroll
        for (int j = 0; j < 4; j++) {
            __half h = __float2half_rn(vv[j]);
            hh[j] = h;
            ll[j] = __float2half_rn(vv[j] - __half2float(h));
        }
        ((uint2*)hi)[i] = *(uint2*)hh;
        ((uint2*)lo)[i] = *(uint2*)ll;
        return;
    }

    const float4* x = (s == 3) ? x3 : x4;
    __nv_bfloat16* hi = (s == 3) ? h3 : h4;
    __nv_bfloat16* lo = (s == 3) ? l3 : l4;
    int n = (s == 3) ? n3 : n4v;
    if (i >= n) return;

    float4 v = x[i];
    float vv[4] = {v.x, v.y, v.z, v.w};
    __nv_bfloat16 hh[4], ll[4];
#pragma unroll
    for (int j = 0; j < 4; j++) {
        __nv_bfloat16 h = __float2bfloat16(vv[j]);
        hh[j] = h;
        ll[j] = __float2bfloat16(vv[j] - __bfloat162float(h));
    }
    ((uint2*)hi)[i] = *(uint2*)hh;
    ((uint2*)lo)[i] = *(uint2*)ll;
}

// W[K,N] fp32 -> WT [N,K] fp16 (round only; Wv)
__global__ void __launch_bounds__(256)
transpose_half(const float* __restrict__ W, __half* __restrict__ T,
               int rows, int cols)
{
    __shared__ float tile[32][33];
    int bx = blockIdx.x * 32;
    int by = blockIdx.y * 32;
    int tx = threadIdx.x & 31;
    int ty = threadIdx.x >> 5;
#pragma unroll
    for (int i = ty; i < 32; i += 8)
        tile[i][tx] = W[(size_t)(by + i) * cols + bx + tx];
    __syncthreads();
#pragma unroll
    for (int i = ty; i < 32; i += 8)
        T[(size_t)(bx + i) * rows + by + tx] = __float2half_rn(tile[tx][i]);
}

// ---------------------------------------------------------------------------
// uv_prep / uv_main (rank-1 bias terms)
// ---------------------------------------------------------------------------
__global__ void __launch_bounds__(256)
uv_prep(const float* __restrict__ wq, const float* __restrict__ wk,
        const float* __restrict__ bq, const float* __restrict__ bk,
        float* __restrict__ w1, float* __restrict__ w2, float* __restrict__ cOut)
{
    int wid = threadIdx.x >> 5, lane = threadIdx.x & 31;
    int s = blockIdx.y;
    int row = blockIdx.x * 8 + wid;
    const float* W = s ? wk : wq;
    const float* b = s ? bq : bk;

    float acc = 0.f;
#pragma unroll
    for (int j = 0; j < 32; j++)
        acc += W[(size_t)row * DDIM + lane + 32 * j] * b[lane + 32 * j];
#pragma unroll
    for (int o = 16; o; o >>= 1) acc += __shfl_xor_sync(0xffffffffu, acc, o);
    if (lane == 0) (s ? w2 : w1)[row] = acc;

    if (blockIdx.x == 0 && s == 0 && wid == 0) {
        float cc = 0.f;
#pragma unroll
        for (int j = 0; j < 32; j++)
            cc += bq[lane + 32 * j] * bk[lane + 32 * j];
#pragma unroll
        for (int o = 16; o; o >>= 1) cc += __shfl_xor_sync(0xffffffffu, cc, o);
        if (lane == 0) cOut[0] = cc;
    }
}

__global__ void __launch_bounds__(256)
uv_main(const float* __restrict__ q, const float* __restrict__ k,
        const float* __restrict__ w1, const float* __restrict__ w2,
        const float* __restrict__ cIn,
        float* __restrict__ u, float* __restrict__ v, float scale)
{
    int wid = threadIdx.x >> 5, lane = threadIdx.x & 31;
    int s = blockIdx.y;
    int row = blockIdx.x * 8 + wid;
    const float* src = s ? k : q;
    const float* w = s ? w2 : w1;

    float acc = 0.f;
#pragma unroll
    for (int j = 0; j < 32; j++)
        acc += src[(size_t)row * IDIM + lane + 32 * j] * w[lane + 32 * j];
#pragma unroll
    for (int o = 16; o; o >>= 1) acc += __shfl_xor_sync(0xffffffffu, acc, o);
    if (lane == 0) {
        if (s == 0) u[row] = (acc + cIn[0]) * scale;
        else        v[row] = acc * scale;
    }
}

// ---------------------------------------------------------------------------
// softmax over pre-biased x -> fp16 attn
// ---------------------------------------------------------------------------
__global__ void __launch_bounds__(256)
softmax_fp16(const float* __restrict__ xin, __half* __restrict__ ah)
{
    __shared__ float red[8];
    __shared__ float bval;

    size_t row = blockIdx.x;
    const float* rp = xin + row * (size_t)SDIM;
    int t = threadIdx.x;

    float4 a = ((const float4*)rp)[t];
    float4 b = ((const float4*)rp)[t + 256];
    float x[8] = {a.x, a.y, a.z, a.w, b.x, b.y, b.z, b.w};

    float mx = x[0];
#pragma unroll
    for (int i = 1; i < 8; i++) mx = fmaxf(mx, x[i]);
#pragma unroll
    for (int o = 16; o; o >>= 1) mx = fmaxf(mx, __shfl_xor_sync(0xffffffffu, mx, o));
    if ((t & 31) == 0) red[t >> 5] = mx;
    __syncthreads();
    if (t == 0) {
        float m = red[0];
#pragma unroll
        for (int i = 1; i < 8; i++) m = fmaxf(m, red[i]);
        bval = m;
    }
    __syncthreads();
    mx = bval;

    float s = 0.f;
#pragma unroll
    for (int i = 0; i < 8; i++) { x[i] = __expf(x[i] - mx); s += x[i]; }
#pragma unroll
    for (int o = 16; o; o >>= 1) s += __shfl_xor_sync(0xffffffffu, s, o);
    if ((t & 31) == 0) red[t >> 5] = s;
    __syncthreads();
    if (t == 0) {
        float ss = 0.f;
#pragma unroll
        for (int i = 0; i < 8; i++) ss += red[i];
        bval = 1.f / ss;
    }
    __syncthreads();
    float inv = bval;

    __half2* ah2 = (__half2*)(ah + row * (size_t)SDIM);
#pragma unroll
    for (int half = 0; half < 2; half++) {
#pragma unroll
        for (int p = 0; p < 2; p++) {
            float p0 = x[half * 4 + p * 2 + 0] * inv;
            float p1 = x[half * 4 + p * 2 + 1] * inv;
            int idx = half * 512 + t * 2 + p;
            ah2[idx] = __halves2half2(__float2half_rn(p0), __float2half_rn(p1));
        }
    }
}

// ---------------------------------------------------------------------------
extern "C" void kernel_launch(void* const* d_in, const int* in_sizes, int n_in,
                              void* d_out, int out_size)
{
    const float* q    = (const float*)d_in[0];
    const float* k    = (const float*)d_in[1];
    const float* v    = (const float*)d_in[2];
    const float* mask = (const float*)d_in[3];
    const float* wq   = (const float*)d_in[4];
    const float* bq   = (const float*)d_in[5];
    const float* wk   = (const float*)d_in[6];
    const float* bk   = (const float*)d_in[7];
    const float* wv   = (const float*)d_in[8];
    const float* bv   = (const float*)d_in[9];
    float* out = (float*)d_out;

#define SYM(p, s) do { void* _t; cudaGetSymbolAddress(&_t, s); p = (decltype(p))_t; } while (0)
    __half *qh, *ql, *kh, *kl, *vh, *vl, *wvt, *M, *P, *vpth, *ah;
    __nv_bfloat16 *wqh, *wql, *wkh, *wkl;
    float *lg, *w1, *w2, *cptr, *u, *vvp;
    SYM(qh, g_qh); SYM(ql, g_ql); SYM(kh, g_kh); SYM(kl, g_kl);
    SYM(vh, g_vh); SYM(vl, g_vl);
    SYM(wqh, g_wqh); SYM(wql, g_wql); SYM(wkh, g_wkh); SYM(wkl, g_wkl);
    SYM(wvt, g_wvt); SYM(M, g_M); SYM(P, g_P);
    SYM(vpth, g_vpth); SYM(ah, g_ah);
    SYM(lg, g_logits);
    SYM(w1, g_w1); SYM(w2, g_w2); SYM(cptr, g_c); SYM(u, g_u); SYM(vvp, g_v);
#undef SYM

    cudaFuncSetAttribute(m_gemm, cudaFuncAttributeMaxDynamicSharedMemorySize, SMEM4_TOTAL);
    cudaFuncSetAttribute(pv_gemm, cudaFuncAttributeMaxDynamicSharedMemorySize, SMEM3_TOTAL);
    cudaFuncSetAttribute(logits_gemm, cudaFuncAttributeMaxDynamicSharedMemorySize, SMEM3_TOTAL);
    cudaFuncSetAttribute(av_gemm, cudaFuncAttributeMaxDynamicSharedMemorySize, SMEM2_TOTAL);

    const int n4_act = NTOK * IDIM / 4;
    const int n4_w = IDIM * DDIM / 4;
    const float scale = 0.03125f;

    // 1: split q,k,v (fp16 hi/lo), Wq,Wk (bf16 hi/lo)
    split5<<<dim3(n4_act / 256, 5), 256>>>(
        (const float4*)q, qh, ql, n4_act,
        (const float4*)k, kh, kl, n4_act,
        (const float4*)v, vh, vl, n4_act,
        (const float4*)wq, wqh, wql, n4_w,
        (const float4*)wk, wkh, wkl, n4_w);

    // 2: transpose Wv -> fp16
    transpose_half<<<dim3(IDIM / 32, IDIM / 32), 256>>>(wv, wvt, IDIM, DDIM);

    // 3: M = Wq Wk^T (bf16 3-prod) -> fp16
    m_gemm<<<dim3(8, 8), NTHREADS, SMEM4_TOTAL>>>(wqh, wql, wkh, wkl, M);

    // 4: P = k M^T (z=0) and vp^T (z=1), fp16 2-prod   <- ncu slot
    pv_gemm<<<dim3(IDIM / 128, NTOK / 128, 2), NTHREADS, SMEM3_TOTAL>>>(
        kh, kl, M, vh, vl, wvt, bv, P, vpth);

    // 5-6: rank-1 bias terms
    uv_prep<<<dim3(IDIM / 8, 2), 256>>>(wq, wk, bq, bk, w1, w2, cptr);
    uv_main<<<dim3(NTOK / 8, 2), 256>>>(q, k, w1, w2, cptr, u, vvp, scale);

    // 7: x = q P^T * scale + mask + u + v  (fused bias epilogue)
    dim3 gl(SDIM / 128, SDIM / 128, BDIM);
    logits_gemm<<<gl, NTHREADS, SMEM3_TOTAL>>>(qh, ql, P, lg, mask, u, vvp, scale);

    // 8: softmax -> fp16 attn
    softmax_fp16<<<BDIM * SDIM, 256>>>(lg, ah);

    // 9: out = attn @ vp (fp16 1-product)
    dim3 ga(DDIM / 128, SDIM / 128, BDIM);
    av_gemm<<<ga, NTHREADS, SMEM2_TOTAL>>>(ah, vpth, out,
                                           SDIM, SDIM, NTOK, DDIM,
                                           (size_t)SDIM * SDIM, (size_t)SDIM,
                                           (size_t)SDIM * DDIM);
}